// round 7
// baseline (speedup 1.0000x reference)
#include <cuda_runtime.h>
#include <cuda_bf16.h>
#include <math.h>

// ---------------- constants ----------------
#define B_ 16
#define N_ 4096
#define C_ 256
#define H_ 4
#define D_ 64
#define M_ (B_ * N_)              // 65536
#define OUT_MAIN (M_ * C_)        // 16777216
#define OUT_S (B_ * H_ * D_ * D_) // 262144

typedef unsigned int u32;

// ---------------- device scratch ----------------
__device__ __nv_bfloat16 g_wph[B_ * C_ * C_], g_wpl[B_ * C_ * C_]; // W' = Sd@Wq per batch (split)
__device__ __nv_bfloat16 g_wsh[2][C_ * C_], g_wsl[2][C_ * C_];     // Wk, Wo (split)
__device__ float g_y[M_ * C_];
__device__ float g_beta[B_ * H_ * N_];
__device__ float g_invrms[M_];
__device__ float g_mkp[1024 * 256], g_mbkp[1024 * 256];  // per-64row-tile k partials
__device__ float g_xbp[1024 * H_ * C_];                   // per-64row beta*x partials
__device__ float g_werr[64 * 64], g_wkey[64 * 64];

// ---------------- helpers ----------------
__device__ __forceinline__ u32 smem_u32(const void* p) {
    u32 a;
    asm("{ .reg .u64 t; cvta.to.shared.u64 t, %1; cvt.u32.u64 %0, t; }" : "=r"(a) : "l"(p));
    return a;
}
__device__ __forceinline__ void ldmx4(u32* r, u32 addr) {
    asm volatile("ldmatrix.sync.aligned.m8n8.x4.shared.b16 {%0,%1,%2,%3}, [%4];"
                 : "=r"(r[0]), "=r"(r[1]), "=r"(r[2]), "=r"(r[3]) : "r"(addr));
}
__device__ __forceinline__ void mma_bf16(float* d, const u32* a, u32 b0, u32 b1) {
    asm volatile("mma.sync.aligned.m16n8k16.row.col.f32.bf16.bf16.f32 "
                 "{%0,%1,%2,%3}, {%4,%5,%6,%7}, {%8,%9}, {%0,%1,%2,%3};"
                 : "+f"(d[0]), "+f"(d[1]), "+f"(d[2]), "+f"(d[3])
                 : "r"(a[0]), "r"(a[1]), "r"(a[2]), "r"(a[3]), "r"(b0), "r"(b1));
}
__device__ __forceinline__ u32 prmt16(u32 a, u32 b) {
    u32 r;
    asm("prmt.b32 %0, %1, %2, 0x7632;" : "=r"(r) : "r"(a), "r"(b));
    return r;
}
// truncation split: h = top16(f), l = top16(f - as_float(top16(f)))
__device__ __forceinline__ void split2(float f0, float f1, u32& h01, u32& l01) {
    u32 b0 = __float_as_uint(f0), b1 = __float_as_uint(f1);
    h01 = prmt16(b0, b1);
    float lo0 = f0 - __uint_as_float(b0 & 0xFFFF0000u);
    float lo1 = f1 - __uint_as_float(b1 & 0xFFFF0000u);
    l01 = prmt16(__float_as_uint(lo0), __float_as_uint(lo1));
}
__device__ __forceinline__ u32 pack2(float a, float b, float& ra, float& rb) {
    __nv_bfloat16 h0 = __float2bfloat16(a), h1 = __float2bfloat16(b);
    ra = a - __bfloat162float(h0);
    rb = b - __bfloat162float(h1);
    return (u32)__bfloat16_as_ushort(h0) | ((u32)__bfloat16_as_ushort(h1) << 16);
}
__device__ __forceinline__ float eluf(float v) {
    return (v > 0.f) ? (v + 1.f) : expf(v);
}

// ---------------- K0: Wk, Wo -> split bf16 ----------------
__global__ void __launch_bounds__(256) convw_kernel(
    const float* __restrict__ Wk, const float* __restrict__ Wo)
{
    int gid = blockIdx.x * 256 + threadIdx.x;   // < 131072
    int sel = gid >> 16, idx = gid & 65535;
    const float* W = sel ? Wo : Wk;
    float v = W[idx];
    __nv_bfloat16 h = __float2bfloat16(v);
    g_wsh[sel][idx] = h;
    g_wsl[sel][idx] = __float2bfloat16(v - __bfloat162float(h));
}

// ---------------- K1: W'[b] = (0.95*S[b,h]) @ Wq_h, split bf16 ----------------
__global__ void __launch_bounds__(256)
wprime_kernel(const float* __restrict__ S, const float* __restrict__ Wq)
{
    extern __shared__ float sm[];        // sSdT[4096] + sWq[64*256] = 80KB
    float* sSdT = sm;
    float* sWq = sm + 4096;
    int bh = blockIdx.x, b = bh >> 2, h = bh & 3, tid = threadIdx.x;
    for (int t = tid; t < 4096; t += 256) {
        int i = t >> 6, j = t & 63;
        sSdT[j * 64 + i] = S[(size_t)bh * 4096 + t] * 0.95f;
    }
    for (int t = tid; t < 64 * 256; t += 256)
        sWq[t] = Wq[(size_t)(h * 64 + (t >> 8)) * 256 + (t & 255)];
    __syncthreads();
    int i = tid & 63, stripe = tid >> 6;
#pragma unroll 1
    for (int cc = 0; cc < 64; cc++) {
        int c = stripe * 64 + cc;
        float acc = 0.f;
#pragma unroll
        for (int j = 0; j < 64; j++)
            acc += sSdT[j * 64 + i] * sWq[j * 256 + c];
        __nv_bfloat16 hh = __float2bfloat16(acc);
        size_t o = (size_t)b * 65536 + (size_t)(h * 64 + i) * 256 + c;
        g_wph[o] = hh;
        g_wpl[o] = __float2bfloat16(acc - __bfloat162float(hh));
    }
}

// ---------------- K2/K6: projection GEMM, M-tile 64 x N-tile 256, K=256 ----------------
// task 0: y = x @ W'[b]^T + fused beta + fused invrms   (grid 1024)
// task 1: out = (y*invrms*grms) @ Wo^T -> fout          (grid 1024)
__global__ void __launch_bounds__(256, 2)
gemm_proj_kernel(int task, const float* __restrict__ Xfp,
                 const float* __restrict__ Wb, const float* __restrict__ grms,
                 float* __restrict__ fout)
{
    extern __shared__ char smem[];
    __shared__ float s_g[1024];
    __shared__ float sm_red[64][4];
    const u32 sb = smem_u32(smem);
    const int tid = threadIdx.x, wid = tid >> 5, lane = tid & 31;
    const int m0 = blockIdx.x * 64;

    const float* Afp = (task == 0) ? Xfp : g_y;
    const __nv_bfloat16 *Bh, *Bl;
    if (task == 0) {
        int b = m0 >> 12;
        Bh = g_wph + (size_t)b * 65536;
        Bl = g_wpl + (size_t)b * 65536;
        for (int i = tid; i < 1024; i += 256) s_g[i] = Wb[i];
    } else {
        Bh = g_wsh[1]; Bl = g_wsl[1];
        s_g[tid] = grms[tid];
    }
    __syncthreads();

    const u32 OAH = 0, OAL = 8192, OBH = 16384, OBL = 49152;
    const int wm = wid & 1, wn = wid >> 1;
    const int rA = (lane & 7) + ((lane >> 3) & 1) * 8, cAx = (lane >> 4) & 1;
    const int rB = (lane & 7) + ((lane >> 4) & 1) * 8, cBx = (lane >> 3) & 1;

    float acc[2][8][4];
#pragma unroll
    for (int i = 0; i < 2; i++)
#pragma unroll
        for (int j = 0; j < 8; j++)
#pragma unroll
            for (int t = 0; t < 4; t++) acc[i][j][t] = 0.f;

    const int lr = tid >> 2, ql = tid & 3;          // staging: row, 16-col quad
    const size_t arow = (size_t)(m0 + lr) * C_ + ql * 16;
    float irm = (task == 1) ? g_invrms[m0 + lr] : 1.f;
    float ba[4] = {0.f, 0.f, 0.f, 0.f};

    for (int c = 0; c < 4; c++) {
        // ---- stage A (fp32 -> truncation split) ----
        const float* xr = Afp + arow + c * 64;
        float f[16];
        *(float4*)(f)      = *(const float4*)(xr);
        *(float4*)(f + 4)  = *(const float4*)(xr + 4);
        *(float4*)(f + 8)  = *(const float4*)(xr + 8);
        *(float4*)(f + 12) = *(const float4*)(xr + 12);
        int colb = c * 64 + ql * 16;
        if (task == 1) {
#pragma unroll
            for (int t = 0; t < 16; t++) f[t] *= irm * s_g[colb + t];
        } else {
#pragma unroll
            for (int h = 0; h < 4; h++) {
                const float* w = s_g + h * 256 + colb;
                float a = 0.f;
#pragma unroll
                for (int t = 0; t < 16; t++) a += f[t] * w[t];
                ba[h] += a;
            }
        }
        u32 hv[8], lv[8];
#pragma unroll
        for (int t = 0; t < 8; t++) split2(f[2 * t], f[2 * t + 1], hv[t], lv[t]);
#pragma unroll
        for (int j2 = 0; j2 < 2; j2++) {
            int cg = ql * 2 + j2;
            u32 off = (u32)lr * 128 + (u32)((cg ^ (lr & 7)) << 4);
            *(uint4*)(smem + OAH + off) = make_uint4(hv[j2*4], hv[j2*4+1], hv[j2*4+2], hv[j2*4+3]);
            *(uint4*)(smem + OAL + off) = make_uint4(lv[j2*4], lv[j2*4+1], lv[j2*4+2], lv[j2*4+3]);
        }
        // ---- stage B (256 rows x 64 cols, already split) ----
        {
            const uint4* pbh = (const uint4*)(Bh + (size_t)tid * 256 + c * 64);
            const uint4* pbl = (const uint4*)(Bl + (size_t)tid * 256 + c * 64);
            u32 rb8 = (u32)tid * 128;
#pragma unroll
            for (int j = 0; j < 8; j++) {
                u32 off = rb8 + (u32)((j ^ (tid & 7)) << 4);
                *(uint4*)(smem + OBH + off) = pbh[j];
                *(uint4*)(smem + OBL + off) = pbl[j];
            }
        }
        __syncthreads();
        // ---- mma ----
#pragma unroll
        for (int ks = 0; ks < 4; ks++) {
            u32 ah[2][4], al[2][4];
#pragma unroll
            for (int ms = 0; ms < 2; ms++) {
                int r = wm * 32 + ms * 16 + rA;
                u32 byt = (u32)r * 128 + (u32)((((2 * ks + cAx) ^ (r & 7)) << 4));
                ldmx4(ah[ms], sb + OAH + byt);
                ldmx4(al[ms], sb + OAL + byt);
            }
#pragma unroll
            for (int nh = 0; nh < 4; nh++) {
                int n = wn * 64 + nh * 16 + rB;
                u32 bytB = (u32)n * 128 + (u32)((((2 * ks + cBx) ^ (n & 7)) << 4));
                u32 bhf[4], blf[4];
                ldmx4(bhf, sb + OBH + bytB);
                ldmx4(blf, sb + OBL + bytB);
#pragma unroll
                for (int ms = 0; ms < 2; ms++) {
                    mma_bf16(acc[ms][nh * 2],     ah[ms], bhf[0], bhf[1]);
                    mma_bf16(acc[ms][nh * 2 + 1], ah[ms], bhf[2], bhf[3]);
                    mma_bf16(acc[ms][nh * 2],     al[ms], bhf[0], bhf[1]);
                    mma_bf16(acc[ms][nh * 2 + 1], al[ms], bhf[2], bhf[3]);
                    mma_bf16(acc[ms][nh * 2],     ah[ms], blf[0], blf[1]);
                    mma_bf16(acc[ms][nh * 2 + 1], ah[ms], blf[2], blf[3]);
                }
            }
        }
        __syncthreads();
    }

    const int qrow = lane >> 2, qcol = (lane & 3) * 2;
    if (task == 0) {
        // beta
#pragma unroll
        for (int h = 0; h < 4; h++) {
            ba[h] += __shfl_xor_sync(0xffffffffu, ba[h], 1);
            ba[h] += __shfl_xor_sync(0xffffffffu, ba[h], 2);
        }
        if (ql == 0) {
            int m = m0 + lr, bb = m >> 12, n = m & (N_ - 1);
#pragma unroll
            for (int h = 0; h < 4; h++)
                g_beta[(bb * H_ + h) * N_ + n] = 1.f / (1.f + expf(-ba[h]));
        }
        // y + per-row ss
#pragma unroll
        for (int ms = 0; ms < 2; ms++) {
            int rr = wm * 32 + ms * 16 + qrow;
            size_t r_lo = (size_t)(m0 + rr);
            float ssl = 0.f, ssh = 0.f;
#pragma unroll
            for (int nf = 0; nf < 8; nf++) {
                int cof = wn * 64 + nf * 8 + qcol;
                *(float2*)(g_y + r_lo * C_ + cof)       = make_float2(acc[ms][nf][0], acc[ms][nf][1]);
                *(float2*)(g_y + (r_lo + 8) * C_ + cof) = make_float2(acc[ms][nf][2], acc[ms][nf][3]);
                ssl += acc[ms][nf][0] * acc[ms][nf][0] + acc[ms][nf][1] * acc[ms][nf][1];
                ssh += acc[ms][nf][2] * acc[ms][nf][2] + acc[ms][nf][3] * acc[ms][nf][3];
            }
            ssl += __shfl_xor_sync(0xffffffffu, ssl, 1);
            ssl += __shfl_xor_sync(0xffffffffu, ssl, 2);
            ssh += __shfl_xor_sync(0xffffffffu, ssh, 1);
            ssh += __shfl_xor_sync(0xffffffffu, ssh, 2);
            if ((lane & 3) == 0) {
                sm_red[rr][wn]     = ssl;
                sm_red[rr + 8][wn] = ssh;
            }
        }
        __syncthreads();
        if (tid < 64) {
            float s = sm_red[tid][0] + sm_red[tid][1] + sm_red[tid][2] + sm_red[tid][3];
            g_invrms[m0 + tid] = rsqrtf(s * (1.f / (float)C_) + 1e-6f);
        }
    } else {
#pragma unroll
        for (int ms = 0; ms < 2; ms++) {
            size_t r_lo = (size_t)(m0 + wm * 32 + ms * 16 + qrow);
#pragma unroll
            for (int nf = 0; nf < 8; nf++) {
                int cof = wn * 64 + nf * 8 + qcol;
                *(float2*)(fout + r_lo * C_ + cof)       = make_float2(acc[ms][nf][0], acc[ms][nf][1]);
                *(float2*)(fout + (r_lo + 8) * C_ + cof) = make_float2(acc[ms][nf][2], acc[ms][nf][3]);
            }
        }
    }
}

// ---------------- K4: k GEMM (M64 x N256) + fused elu/L2norm + mk/mbk ----------------
__global__ void __launch_bounds__(256, 2)
gemm_k_kernel(const float* __restrict__ Xfp)
{
    extern __shared__ char smem[];
    const u32 sb = smem_u32(smem);
    const int tid = threadIdx.x, wid = tid >> 5, lane = tid & 31;
    const int m0 = blockIdx.x * 64;
    const __nv_bfloat16* Bh = g_wsh[0];
    const __nv_bfloat16* Bl = g_wsl[0];

    const u32 OAH = 0, OAL = 8192, OBH = 16384, OBL = 49152;
    const int wm = wid & 1, wn = wid >> 1;
    const int rA = (lane & 7) + ((lane >> 3) & 1) * 8, cAx = (lane >> 4) & 1;
    const int rB = (lane & 7) + ((lane >> 4) & 1) * 8, cBx = (lane >> 3) & 1;

    float acc[2][8][4];
#pragma unroll
    for (int i = 0; i < 2; i++)
#pragma unroll
        for (int j = 0; j < 8; j++)
#pragma unroll
            for (int t = 0; t < 4; t++) acc[i][j][t] = 0.f;

    const int lr = tid >> 2, ql = tid & 3;
    const size_t arow = (size_t)(m0 + lr) * C_ + ql * 16;

    for (int c = 0; c < 4; c++) {
        const float* xr = Xfp + arow + c * 64;
        float f[16];
        *(float4*)(f)      = *(const float4*)(xr);
        *(float4*)(f + 4)  = *(const float4*)(xr + 4);
        *(float4*)(f + 8)  = *(const float4*)(xr + 8);
        *(float4*)(f + 12) = *(const float4*)(xr + 12);
        u32 hv[8], lv[8];
#pragma unroll
        for (int t = 0; t < 8; t++) split2(f[2 * t], f[2 * t + 1], hv[t], lv[t]);
#pragma unroll
        for (int j2 = 0; j2 < 2; j2++) {
            int cg = ql * 2 + j2;
            u32 off = (u32)lr * 128 + (u32)((cg ^ (lr & 7)) << 4);
            *(uint4*)(smem + OAH + off) = make_uint4(hv[j2*4], hv[j2*4+1], hv[j2*4+2], hv[j2*4+3]);
            *(uint4*)(smem + OAL + off) = make_uint4(lv[j2*4], lv[j2*4+1], lv[j2*4+2], lv[j2*4+3]);
        }
        {
            const uint4* pbh = (const uint4*)(Bh + (size_t)tid * 256 + c * 64);
            const uint4* pbl = (const uint4*)(Bl + (size_t)tid * 256 + c * 64);
            u32 rb8 = (u32)tid * 128;
#pragma unroll
            for (int j = 0; j < 8; j++) {
                u32 off = rb8 + (u32)((j ^ (tid & 7)) << 4);
                *(uint4*)(smem + OBH + off) = pbh[j];
                *(uint4*)(smem + OBL + off) = pbl[j];
            }
        }
        __syncthreads();
#pragma unroll
        for (int ks = 0; ks < 4; ks++) {
            u32 ah[2][4], al[2][4];
#pragma unroll
            for (int ms = 0; ms < 2; ms++) {
                int r = wm * 32 + ms * 16 + rA;
                u32 byt = (u32)r * 128 + (u32)((((2 * ks + cAx) ^ (r & 7)) << 4));
                ldmx4(ah[ms], sb + OAH + byt);
                ldmx4(al[ms], sb + OAL + byt);
            }
#pragma unroll
            for (int nh = 0; nh < 4; nh++) {
                int n = wn * 64 + nh * 16 + rB;
                u32 bytB = (u32)n * 128 + (u32)((((2 * ks + cBx) ^ (n & 7)) << 4));
                u32 bhf[4], blf[4];
                ldmx4(bhf, sb + OBH + bytB);
                ldmx4(blf, sb + OBL + bytB);
#pragma unroll
                for (int ms = 0; ms < 2; ms++) {
                    mma_bf16(acc[ms][nh * 2],     ah[ms], bhf[0], bhf[1]);
                    mma_bf16(acc[ms][nh * 2 + 1], ah[ms], bhf[2], bhf[3]);
                    mma_bf16(acc[ms][nh * 2],     al[ms], bhf[0], bhf[1]);
                    mma_bf16(acc[ms][nh * 2 + 1], al[ms], bhf[2], bhf[3]);
                    mma_bf16(acc[ms][nh * 2],     ah[ms], blf[0], blf[1]);
                    mma_bf16(acc[ms][nh * 2 + 1], ah[ms], blf[2], blf[3]);
                }
            }
        }
        __syncthreads();
    }

    // ---- epilogue: elu+1, per-head L2 norm (head = wn), reduce mk / beta*mk ----
    const int qrow = lane >> 2, qcol = (lane & 3) * 2;
    const int bhh = (m0 >> 12) * H_ + wn;
    float mk0[8], mk1[8], mbk0[8], mbk1[8];
#pragma unroll
    for (int nf = 0; nf < 8; nf++) { mk0[nf] = mk1[nf] = mbk0[nf] = mbk1[nf] = 0.f; }

#pragma unroll
    for (int ms = 0; ms < 2; ms++) {
        float ssl = 0.f, ssh = 0.f;
#pragma unroll
        for (int nf = 0; nf < 8; nf++) {
            float e0 = eluf(acc[ms][nf][0]); acc[ms][nf][0] = e0; ssl += e0 * e0;
            float e1 = eluf(acc[ms][nf][1]); acc[ms][nf][1] = e1; ssl += e1 * e1;
            float e2 = eluf(acc[ms][nf][2]); acc[ms][nf][2] = e2; ssh += e2 * e2;
            float e3 = eluf(acc[ms][nf][3]); acc[ms][nf][3] = e3; ssh += e3 * e3;
        }
        ssl += __shfl_xor_sync(0xffffffffu, ssl, 1);
        ssl += __shfl_xor_sync(0xffffffffu, ssl, 2);
        ssh += __shfl_xor_sync(0xffffffffu, ssh, 1);
        ssh += __shfl_xor_sync(0xffffffffu, ssh, 2);
        float invl = 1.f / (sqrtf(ssl) + 1e-6f);
        float invh = 1.f / (sqrtf(ssh) + 1e-6f);
        int nrow = (m0 & (N_ - 1)) + wm * 32 + ms * 16 + qrow;
        float b_lo = g_beta[bhh * N_ + nrow];
        float b_hi = g_beta[bhh * N_ + nrow + 8];
#pragma unroll
        for (int nf = 0; nf < 8; nf++) {
            float v0 = acc[ms][nf][0] * invl, v1 = acc[ms][nf][1] * invl;
            float v2 = acc[ms][nf][2] * invh, v3 = acc[ms][nf][3] * invh;
            mk0[nf]  += v0 + v2;
            mk1[nf]  += v1 + v3;
            mbk0[nf] += b_lo * v0 + b_hi * v2;
            mbk1[nf] += b_lo * v1 + b_hi * v3;
        }
    }
#pragma unroll
    for (int o = 4; o <= 16; o <<= 1) {
#pragma unroll
        for (int nf = 0; nf < 8; nf++) {
            mk0[nf]  += __shfl_xor_sync(0xffffffffu, mk0[nf], o);
            mk1[nf]  += __shfl_xor_sync(0xffffffffu, mk1[nf], o);
            mbk0[nf] += __shfl_xor_sync(0xffffffffu, mbk0[nf], o);
            mbk1[nf] += __shfl_xor_sync(0xffffffffu, mbk1[nf], o);
        }
    }
    float* red = (float*)smem;   // reuse staging smem
    if (lane < 4) {
#pragma unroll
        for (int nf = 0; nf < 8; nf++) {
            red[wid * 64 + nf * 8 + lane * 2]           = mk0[nf];
            red[wid * 64 + nf * 8 + lane * 2 + 1]       = mk1[nf];
            red[512 + wid * 64 + nf * 8 + lane * 2]     = mbk0[nf];
            red[512 + wid * 64 + nf * 8 + lane * 2 + 1] = mbk1[nf];
        }
    }
    __syncthreads();
    {
        int h = tid >> 6, col = tid & 63;
        // warps sharing head h: wid = h*2 and h*2+1
        float s  = red[(h * 2) * 64 + col] + red[(h * 2 + 1) * 64 + col];
        float s2 = red[512 + (h * 2) * 64 + col] + red[512 + (h * 2 + 1) * 64 + col];
        g_mkp[(size_t)blockIdx.x * 256 + tid]  = s;
        g_mbkp[(size_t)blockIdx.x * 256 + tid] = s2;
    }
}

// ---------------- K3: xbar partials = sum_n beta*x over 64-row chunks ----------------
__global__ void __launch_bounds__(256)
xbar_kernel(const float* __restrict__ x)
{
    __shared__ float sbeta[64][4];
    int blk = blockIdx.x, m0 = blk * 64, tid = threadIdx.x;
    {
        int r = tid >> 2, h = tid & 3;
        int m = m0 + r, b = m >> 12, n = m & (N_ - 1);
        sbeta[r][h] = g_beta[(b * H_ + h) * N_ + n];
    }
    __syncthreads();
    float a0 = 0.f, a1 = 0.f, a2 = 0.f, a3 = 0.f;
    for (int r = 0; r < 64; r++) {
        float xv = x[(size_t)(m0 + r) * C_ + tid];
        a0 += xv * sbeta[r][0];
        a1 += xv * sbeta[r][1];
        a2 += xv * sbeta[r][2];
        a3 += xv * sbeta[r][3];
    }
    g_xbp[((size_t)blk * 4 + 0) * 256 + tid] = a0;
    g_xbp[((size_t)blk * 4 + 1) * 256 + tid] = a1;
    g_xbp[((size_t)blk * 4 + 2) * 256 + tid] = a2;
    g_xbp[((size_t)blk * 4 + 3) * 256 + tid] = a3;
}

// ---------------- K5b: finalize werr/wkey ----------------
__global__ void __launch_bounds__(256)
final_kernel(const float* __restrict__ S, const float* __restrict__ Wv)
{
    __shared__ float s_mk[64], s_mbk[64], s_xbar[256];
    int bh = blockIdx.x, b = bh >> 2, h = bh & 3, tid = threadIdx.x;
    {
        float a = 0.f;
        for (int t = 0; t < 64; t++)
            a += g_xbp[((size_t)(b * 64 + t) * 4 + h) * 256 + tid];
        s_xbar[tid] = a * (1.f / (float)N_);
    }
    if (tid < 64) {
        float s = 0.f;
        for (int t = 0; t < 64; t++)
            s += g_mkp[(size_t)(b * 64 + t) * 256 + h * 64 + tid];
        s_mk[tid] = s * (1.f / (float)N_);
    } else if (tid < 128) {
        int c = tid - 64;
        float s = 0.f;
        for (int t = 0; t < 64; t++)
            s += g_mbkp[(size_t)(b * 64 + t) * 256 + h * 64 + c];
        s_mbk[c] = s * (1.f / (float)N_);
    }
    __syncthreads();
    if (tid < 64) {
        int i = tid;
        const float* wv = Wv + (size_t)(h * 64 + i) * 256;
        float mbv = 0.f;
        for (int c = 0; c < 256; c++) mbv += wv[c] * s_xbar[c];
        const float* sd = S + (size_t)bh * 4096 + (size_t)i * 64;
        float sp = 0.f;
        for (int j = 0; j < 64; j++) sp += 0.95f * sd[j] * s_mbk[j];
        g_werr[bh * 64 + i] = mbv - sp;
        g_wkey[bh * 64 + i] = s_mk[i];
    }
}

// ---------------- K5c: S_new ----------------
__global__ void __launch_bounds__(256)
snew_kernel(const float* __restrict__ S, float* __restrict__ out_s)
{
    int idx = blockIdx.x * 256 + threadIdx.x;
    int bh = idx >> 12;
    int i = (idx >> 6) & 63;
    int j = idx & 63;
    float val = S[idx] * 0.95f + g_werr[bh * 64 + i] * g_wkey[bh * 64 + j];
    out_s[idx] = fminf(fmaxf(val, -10.f), 10.f);
}

// ---------------- launcher ----------------
extern "C" void kernel_launch(void* const* d_in, const int* in_sizes, int n_in,
                              void* d_out, int out_size)
{
    const float* x    = (const float*)d_in[0];
    const float* S    = (const float*)d_in[1];
    const float* Wq   = (const float*)d_in[2];
    const float* Wk   = (const float*)d_in[3];
    const float* Wv   = (const float*)d_in[4];
    const float* Wb   = (const float*)d_in[5];
    const float* Wo   = (const float*)d_in[6];
    const float* grms = (const float*)d_in[7];
    float* out = (float*)d_out;

    static int init = 0;
    if (!init) {
        cudaFuncSetAttribute(gemm_proj_kernel, cudaFuncAttributeMaxDynamicSharedMemorySize, 81920);
        cudaFuncSetAttribute(gemm_k_kernel, cudaFuncAttributeMaxDynamicSharedMemorySize, 81920);
        cudaFuncSetAttribute(wprime_kernel, cudaFuncAttributeMaxDynamicSharedMemorySize, 81920);
        init = 1;
    }

    // weight prep
    convw_kernel<<<512, 256>>>(Wk, Wo);
    wprime_kernel<<<64, 256, 81920>>>(S, Wq);

    // y = x @ W'^T (+ beta + invrms)
    gemm_proj_kernel<<<1024, 256, 81920>>>(0, x, Wb, grms, nullptr);

    // xbar partials (needs beta)
    xbar_kernel<<<1024, 256>>>(x);

    // k GEMM + fused reductions (needs beta)
    gemm_k_kernel<<<1024, 256, 81920>>>(x);

    // werr/wkey, S_new
    final_kernel<<<64, 256>>>(S, Wv);
    if (out_size >= OUT_MAIN + OUT_S) {
        snew_kernel<<<OUT_S / 256, 256>>>(S, out + OUT_MAIN);
    }

    // out = (y * invrms * grms) @ Wo^T
    gemm_proj_kernel<<<1024, 256, 81920>>>(1, x, Wb, grms, out);
}

// round 8
// speedup vs baseline: 1.1955x; 1.1955x over previous
#include <cuda_runtime.h>
#include <cuda_bf16.h>
#include <math.h>

// ---------------- constants ----------------
#define B_ 16
#define N_ 4096
#define C_ 256
#define H_ 4
#define D_ 64
#define M_ (B_ * N_)              // 65536
#define OUT_MAIN (M_ * C_)        // 16777216
#define OUT_S (B_ * H_ * D_ * D_) // 262144

typedef unsigned int u32;

// ---------------- device scratch ----------------
__device__ __nv_bfloat16 g_wph[B_ * C_ * C_], g_wpl[B_ * C_ * C_]; // W' = Sd@Wq per batch (split)
__device__ __nv_bfloat16 g_wsh[2][C_ * C_], g_wsl[2][C_ * C_];     // Wk, Wo*g (split)
__device__ float g_y[M_ * C_];
__device__ float g_beta[B_ * H_ * N_];
__device__ float g_ssp[M_ * 2];
__device__ float g_invrms[M_];
__device__ float g_mkp[512 * 256], g_mbkp[512 * 256];   // per-mtile k partials
__device__ float g_xbp[1024 * H_ * C_];                  // per-64row beta*x partials
__device__ float g_werr[64 * 64], g_wkey[64 * 64];

// ---------------- helpers ----------------
__device__ __forceinline__ u32 smem_u32(const void* p) {
    u32 a;
    asm("{ .reg .u64 t; cvta.to.shared.u64 t, %1; cvt.u32.u64 %0, t; }" : "=r"(a) : "l"(p));
    return a;
}
__device__ __forceinline__ void ldmx4(u32* r, u32 addr) {
    asm volatile("ldmatrix.sync.aligned.m8n8.x4.shared.b16 {%0,%1,%2,%3}, [%4];"
                 : "=r"(r[0]), "=r"(r[1]), "=r"(r[2]), "=r"(r[3]) : "r"(addr));
}
__device__ __forceinline__ void mma_bf16(float* d, const u32* a, u32 b0, u32 b1) {
    asm volatile("mma.sync.aligned.m16n8k16.row.col.f32.bf16.bf16.f32 "
                 "{%0,%1,%2,%3}, {%4,%5,%6,%7}, {%8,%9}, {%0,%1,%2,%3};"
                 : "+f"(d[0]), "+f"(d[1]), "+f"(d[2]), "+f"(d[3])
                 : "r"(a[0]), "r"(a[1]), "r"(a[2]), "r"(a[3]), "r"(b0), "r"(b1));
}
__device__ __forceinline__ u32 prmt16(u32 a, u32 b) {
    u32 r;
    asm("prmt.b32 %0, %1, %2, 0x7632;" : "=r"(r) : "r"(a), "r"(b));
    return r;
}
// truncation split: h = top16(f), l = top16(f - as_float(top16(f)))
__device__ __forceinline__ void split2(float f0, float f1, u32& h01, u32& l01) {
    u32 b0 = __float_as_uint(f0), b1 = __float_as_uint(f1);
    h01 = prmt16(b0, b1);
    float lo0 = f0 - __uint_as_float(b0 & 0xFFFF0000u);
    float lo1 = f1 - __uint_as_float(b1 & 0xFFFF0000u);
    l01 = prmt16(__float_as_uint(lo0), __float_as_uint(lo1));
}
__device__ __forceinline__ float eluf(float v) {
    return (v > 0.f) ? (v + 1.f) : expf(v);
}

// ---------------- K0: Wk, Wo*grms -> split bf16 ----------------
__global__ void __launch_bounds__(256) convw_kernel(
    const float* __restrict__ Wk, const float* __restrict__ Wo,
    const float* __restrict__ grms)
{
    int gid = blockIdx.x * 256 + threadIdx.x;   // < 131072
    int sel = gid >> 16, idx = gid & 65535;
    float v = sel ? (Wo[idx] * grms[idx & 255]) : Wk[idx];
    __nv_bfloat16 h = __float2bfloat16(v);
    g_wsh[sel][idx] = h;
    g_wsl[sel][idx] = __float2bfloat16(v - __bfloat162float(h));
}

// ---------------- K1: W'[b] = (0.95*S[b,h]) @ Wq_h, split bf16 ----------------
__global__ void __launch_bounds__(256)
wprime_kernel(const float* __restrict__ S, const float* __restrict__ Wq)
{
    extern __shared__ float sm[];        // sSdT[4096] + sWq[64*256] = 80KB
    float* sSdT = sm;
    float* sWq = sm + 4096;
    int bh = blockIdx.x, b = bh >> 2, h = bh & 3, tid = threadIdx.x;
    for (int t = tid; t < 4096; t += 256) {
        int i = t >> 6, j = t & 63;
        sSdT[j * 64 + i] = S[(size_t)bh * 4096 + t] * 0.95f;
    }
    for (int t = tid; t < 64 * 256; t += 256)
        sWq[t] = Wq[(size_t)(h * 64 + (t >> 8)) * 256 + (t & 255)];
    __syncthreads();
    int i = tid & 63, stripe = tid >> 6;
#pragma unroll 1
    for (int cc = 0; cc < 64; cc++) {
        int c = stripe * 64 + cc;
        float acc = 0.f;
#pragma unroll
        for (int j = 0; j < 64; j++)
            acc += sSdT[j * 64 + i] * sWq[j * 256 + c];
        __nv_bfloat16 hh = __float2bfloat16(acc);
        size_t o = (size_t)b * 65536 + (size_t)(h * 64 + i) * 256 + c;
        g_wph[o] = hh;
        g_wpl[o] = __float2bfloat16(acc - __bfloat162float(hh));
    }
}

// ---------------- K2/K6: projection GEMM (split-bf16 from fp32 A), 128x128 tiles ----------------
// task 0: y = x @ W'[b]^T (grid 2 x 512), fused beta (bx==0) + per-row ss partials
// task 1: out = irm * (y @ Wog^T) (grid 2 x 512) -> fout
__global__ void __launch_bounds__(256, 2)
gemm_proj_kernel(int task, const float* __restrict__ Xfp,
                 const float* __restrict__ Wb, float* __restrict__ fout)
{
    extern __shared__ char smem[];
    __shared__ float s_g[1024];
    __shared__ float sm_ss[128][2];
    const u32 sb = smem_u32(smem);
    const int tid = threadIdx.x, wid = tid >> 5, lane = tid & 31;
    const int m0 = blockIdx.y * 128;
    const int n0 = (int)blockIdx.x * 128;

    const float* Afp = (task == 0) ? Xfp : g_y;
    const __nv_bfloat16 *Bh, *Bl;
    bool doBeta = false;
    if (task == 0) {
        int b = m0 >> 12;
        Bh = g_wph + (size_t)b * 65536;
        Bl = g_wpl + (size_t)b * 65536;
        doBeta = (blockIdx.x == 0);
        if (doBeta) for (int i = tid; i < 1024; i += 256) s_g[i] = Wb[i];
    } else {
        Bh = g_wsh[1]; Bl = g_wsl[1];
    }
    __syncthreads();

    const u32 OAH = 0, OAL = 16384, OBH = 32768, OBL = 49152;
    const int wm = wid & 3, wn = wid >> 2;
    const int rA = (lane & 7) + ((lane >> 3) & 1) * 8, cAx = (lane >> 4) & 1;
    const int rB = (lane & 7) + ((lane >> 4) & 1) * 8, cBx = (lane >> 3) & 1;

    float acc[2][8][4];
#pragma unroll
    for (int i = 0; i < 2; i++)
#pragma unroll
        for (int j = 0; j < 8; j++)
#pragma unroll
            for (int t = 0; t < 4; t++) acc[i][j][t] = 0.f;

    const int lr = tid >> 1, lh = tid & 1;
    const size_t arow = (size_t)(m0 + lr) * C_ + lh * 32;
    const size_t brow = (size_t)(n0 + lr) * C_ + lh * 32;
    float ba0 = 0.f, ba1 = 0.f, ba2 = 0.f, ba3 = 0.f;

    for (int c = 0; c < 4; c++) {
        const float* xrow = Afp + arow + c * 64;
        const uint4* pb  = (const uint4*)(Bh + brow + c * 64);
        const uint4* pbl = (const uint4*)(Bl + brow + c * 64);
        u32 sbase = (u32)lr * 128;
#pragma unroll
        for (int j = 0; j < 4; j++) {
            float4 f0 = *(const float4*)(xrow + j * 8);
            float4 f1 = *(const float4*)(xrow + j * 8 + 4);
            if (doBeta) {
                int colb = c * 64 + lh * 32 + j * 8;
                const float* w0 = s_g + colb;
                ba0 += f0.x*w0[0]+f0.y*w0[1]+f0.z*w0[2]+f0.w*w0[3]+f1.x*w0[4]+f1.y*w0[5]+f1.z*w0[6]+f1.w*w0[7];
                const float* w1 = s_g + 256 + colb;
                ba1 += f0.x*w1[0]+f0.y*w1[1]+f0.z*w1[2]+f0.w*w1[3]+f1.x*w1[4]+f1.y*w1[5]+f1.z*w1[6]+f1.w*w1[7];
                const float* w2 = s_g + 512 + colb;
                ba2 += f0.x*w2[0]+f0.y*w2[1]+f0.z*w2[2]+f0.w*w2[3]+f1.x*w2[4]+f1.y*w2[5]+f1.z*w2[6]+f1.w*w2[7];
                const float* w3 = s_g + 768 + colb;
                ba3 += f0.x*w3[0]+f0.y*w3[1]+f0.z*w3[2]+f0.w*w3[3]+f1.x*w3[4]+f1.y*w3[5]+f1.z*w3[6]+f1.w*w3[7];
            }
            u32 h0, l0, h1, l1, h2, l2, h3, l3;
            split2(f0.x, f0.y, h0, l0);
            split2(f0.z, f0.w, h1, l1);
            split2(f1.x, f1.y, h2, l2);
            split2(f1.z, f1.w, h3, l3);
            u32 off = sbase + (u32)(((lh * 4 + j) ^ (lr & 7)) << 4);
            *(uint4*)(smem + OAH + off) = make_uint4(h0, h1, h2, h3);
            *(uint4*)(smem + OAL + off) = make_uint4(l0, l1, l2, l3);
            *(uint4*)(smem + OBH + off) = pb[j];
            *(uint4*)(smem + OBL + off) = pbl[j];
        }
        __syncthreads();
#pragma unroll
        for (int ks = 0; ks < 4; ks++) {
            u32 ah[2][4], al[2][4];
#pragma unroll
            for (int mm = 0; mm < 2; mm++) {
                int r = wm * 32 + mm * 16 + rA;
                u32 byt = (u32)r * 128 + (u32)((((2 * ks + cAx) ^ (r & 7)) << 4));
                ldmx4(ah[mm], sb + OAH + byt);
                ldmx4(al[mm], sb + OAL + byt);
            }
#pragma unroll
            for (int nh = 0; nh < 4; nh++) {
                int n = wn * 64 + nh * 16 + rB;
                u32 bytB = (u32)n * 128 + (u32)((((2 * ks + cBx) ^ (n & 7)) << 4));
                u32 bhf[4], blf[4];
                ldmx4(bhf, sb + OBH + bytB);
                ldmx4(blf, sb + OBL + bytB);
#pragma unroll
                for (int mm = 0; mm < 2; mm++) {
                    mma_bf16(acc[mm][nh * 2],     ah[mm], bhf[0], bhf[1]);
                    mma_bf16(acc[mm][nh * 2 + 1], ah[mm], bhf[2], bhf[3]);
                    mma_bf16(acc[mm][nh * 2],     al[mm], bhf[0], bhf[1]);
                    mma_bf16(acc[mm][nh * 2 + 1], al[mm], bhf[2], bhf[3]);
                    mma_bf16(acc[mm][nh * 2],     ah[mm], blf[0], blf[1]);
                    mma_bf16(acc[mm][nh * 2 + 1], ah[mm], blf[2], blf[3]);
                }
            }
        }
        __syncthreads();
    }

    if (doBeta) {
        ba0 += __shfl_xor_sync(0xffffffffu, ba0, 1);
        ba1 += __shfl_xor_sync(0xffffffffu, ba1, 1);
        ba2 += __shfl_xor_sync(0xffffffffu, ba2, 1);
        ba3 += __shfl_xor_sync(0xffffffffu, ba3, 1);
        if (lh == 0) {
            int m = m0 + lr, bb = m >> 12, n = m & (N_ - 1);
            g_beta[(bb * H_ + 0) * N_ + n] = 1.f / (1.f + expf(-ba0));
            g_beta[(bb * H_ + 1) * N_ + n] = 1.f / (1.f + expf(-ba1));
            g_beta[(bb * H_ + 2) * N_ + n] = 1.f / (1.f + expf(-ba2));
            g_beta[(bb * H_ + 3) * N_ + n] = 1.f / (1.f + expf(-ba3));
        }
    }

    // ---- epilogue ----
    const int qrow = lane >> 2, qcol = (lane & 3) * 2;
    if (task == 0) {
#pragma unroll
        for (int mm = 0; mm < 2; mm++) {
            size_t r_lo = (size_t)(m0 + wm * 32 + mm * 16 + qrow);
            size_t r_hi = r_lo + 8;
            float ssl = 0.f, ssh = 0.f;
#pragma unroll
            for (int nf = 0; nf < 8; nf++) {
                int cof = n0 + wn * 64 + nf * 8 + qcol;
                *(float2*)(g_y + r_lo * C_ + cof) = make_float2(acc[mm][nf][0], acc[mm][nf][1]);
                *(float2*)(g_y + r_hi * C_ + cof) = make_float2(acc[mm][nf][2], acc[mm][nf][3]);
                ssl += acc[mm][nf][0] * acc[mm][nf][0] + acc[mm][nf][1] * acc[mm][nf][1];
                ssh += acc[mm][nf][2] * acc[mm][nf][2] + acc[mm][nf][3] * acc[mm][nf][3];
            }
            ssl += __shfl_xor_sync(0xffffffffu, ssl, 1);
            ssl += __shfl_xor_sync(0xffffffffu, ssl, 2);
            ssh += __shfl_xor_sync(0xffffffffu, ssh, 1);
            ssh += __shfl_xor_sync(0xffffffffu, ssh, 2);
            if ((lane & 3) == 0) {
                sm_ss[wm * 32 + mm * 16 + qrow][wn]     = ssl;
                sm_ss[wm * 32 + mm * 16 + qrow + 8][wn] = ssh;
            }
        }
        __syncthreads();
        if (tid < 128)
            g_ssp[(size_t)(m0 + tid) * 2 + (n0 >> 7)] = sm_ss[tid][0] + sm_ss[tid][1];
    } else {
#pragma unroll
        for (int mm = 0; mm < 2; mm++) {
            size_t r_lo = (size_t)(m0 + wm * 32 + mm * 16 + qrow);
            size_t r_hi = r_lo + 8;
            float irm_lo = g_invrms[r_lo];
            float irm_hi = g_invrms[r_hi];
#pragma unroll
            for (int nf = 0; nf < 8; nf++) {
                int cof = n0 + wn * 64 + nf * 8 + qcol;
                *(float2*)(fout + r_lo * C_ + cof) =
                    make_float2(acc[mm][nf][0] * irm_lo, acc[mm][nf][1] * irm_lo);
                *(float2*)(fout + r_hi * C_ + cof) =
                    make_float2(acc[mm][nf][2] * irm_hi, acc[mm][nf][3] * irm_hi);
            }
        }
    }
}

// ---------------- K4: k GEMM + fused elu/L2norm + mk/mbk reductions ----------------
// grid (2, 512). k never stored; only per-mtile partial sums emitted.
__global__ void __launch_bounds__(256, 2)
gemm_k_kernel(const float* __restrict__ Xfp)
{
    extern __shared__ char smem[];
    const u32 sb = smem_u32(smem);
    const int tid = threadIdx.x, wid = tid >> 5, lane = tid & 31;
    const int m0 = blockIdx.y * 128;
    const int n0 = (int)blockIdx.x * 128;
    const __nv_bfloat16* Bh = g_wsh[0];
    const __nv_bfloat16* Bl = g_wsl[0];

    const u32 OAH = 0, OAL = 16384, OBH = 32768, OBL = 49152;
    const int wm = wid & 3, wn = wid >> 2;
    const int rA = (lane & 7) + ((lane >> 3) & 1) * 8, cAx = (lane >> 4) & 1;
    const int rB = (lane & 7) + ((lane >> 4) & 1) * 8, cBx = (lane >> 3) & 1;

    float acc[2][8][4];
#pragma unroll
    for (int i = 0; i < 2; i++)
#pragma unroll
        for (int j = 0; j < 8; j++)
#pragma unroll
            for (int t = 0; t < 4; t++) acc[i][j][t] = 0.f;

    const int lr = tid >> 1, lh = tid & 1;
    const size_t arow = (size_t)(m0 + lr) * C_ + lh * 32;
    const size_t brow = (size_t)(n0 + lr) * C_ + lh * 32;

    for (int c = 0; c < 4; c++) {
        const float* xrow = Xfp + arow + c * 64;
        const uint4* pb  = (const uint4*)(Bh + brow + c * 64);
        const uint4* pbl = (const uint4*)(Bl + brow + c * 64);
        u32 sbase = (u32)lr * 128;
#pragma unroll
        for (int j = 0; j < 4; j++) {
            float4 f0 = *(const float4*)(xrow + j * 8);
            float4 f1 = *(const float4*)(xrow + j * 8 + 4);
            u32 h0, l0, h1, l1, h2, l2, h3, l3;
            split2(f0.x, f0.y, h0, l0);
            split2(f0.z, f0.w, h1, l1);
            split2(f1.x, f1.y, h2, l2);
            split2(f1.z, f1.w, h3, l3);
            u32 off = sbase + (u32)(((lh * 4 + j) ^ (lr & 7)) << 4);
            *(uint4*)(smem + OAH + off) = make_uint4(h0, h1, h2, h3);
            *(uint4*)(smem + OAL + off) = make_uint4(l0, l1, l2, l3);
            *(uint4*)(smem + OBH + off) = pb[j];
            *(uint4*)(smem + OBL + off) = pbl[j];
        }
        __syncthreads();
#pragma unroll
        for (int ks = 0; ks < 4; ks++) {
            u32 ah[2][4], al[2][4];
#pragma unroll
            for (int mm = 0; mm < 2; mm++) {
                int r = wm * 32 + mm * 16 + rA;
                u32 byt = (u32)r * 128 + (u32)((((2 * ks + cAx) ^ (r & 7)) << 4));
                ldmx4(ah[mm], sb + OAH + byt);
                ldmx4(al[mm], sb + OAL + byt);
            }
#pragma unroll
            for (int nh = 0; nh < 4; nh++) {
                int n = wn * 64 + nh * 16 + rB;
                u32 bytB = (u32)n * 128 + (u32)((((2 * ks + cBx) ^ (n & 7)) << 4));
                u32 bhf[4], blf[4];
                ldmx4(bhf, sb + OBH + bytB);
                ldmx4(blf, sb + OBL + bytB);
#pragma unroll
                for (int mm = 0; mm < 2; mm++) {
                    mma_bf16(acc[mm][nh * 2],     ah[mm], bhf[0], bhf[1]);
                    mma_bf16(acc[mm][nh * 2 + 1], ah[mm], bhf[2], bhf[3]);
                    mma_bf16(acc[mm][nh * 2],     al[mm], bhf[0], bhf[1]);
                    mma_bf16(acc[mm][nh * 2 + 1], al[mm], bhf[2], bhf[3]);
                    mma_bf16(acc[mm][nh * 2],     ah[mm], blf[0], blf[1]);
                    mma_bf16(acc[mm][nh * 2 + 1], ah[mm], blf[2], blf[3]);
                }
            }
        }
        __syncthreads();
    }

    // ---- epilogue: elu+1, per-head L2 norm, reduce mk & beta-weighted mbk over rows ----
    const int qrow = lane >> 2, qcol = (lane & 3) * 2;
    const int head = (n0 >> 6) + wn;
    const int bhh = (m0 >> 12) * H_ + head;
    float mk0[8], mk1[8], mbk0[8], mbk1[8];
#pragma unroll
    for (int nf = 0; nf < 8; nf++) { mk0[nf] = mk1[nf] = mbk0[nf] = mbk1[nf] = 0.f; }

#pragma unroll
    for (int mm = 0; mm < 2; mm++) {
        float ssl = 0.f, ssh = 0.f;
#pragma unroll
        for (int nf = 0; nf < 8; nf++) {
            float e0 = eluf(acc[mm][nf][0]); acc[mm][nf][0] = e0; ssl += e0 * e0;
            float e1 = eluf(acc[mm][nf][1]); acc[mm][nf][1] = e1; ssl += e1 * e1;
            float e2 = eluf(acc[mm][nf][2]); acc[mm][nf][2] = e2; ssh += e2 * e2;
            float e3 = eluf(acc[mm][nf][3]); acc[mm][nf][3] = e3; ssh += e3 * e3;
        }
        ssl += __shfl_xor_sync(0xffffffffu, ssl, 1);
        ssl += __shfl_xor_sync(0xffffffffu, ssl, 2);
        ssh += __shfl_xor_sync(0xffffffffu, ssh, 1);
        ssh += __shfl_xor_sync(0xffffffffu, ssh, 2);
        float invl = 1.f / (sqrtf(ssl) + 1e-6f);
        float invh = 1.f / (sqrtf(ssh) + 1e-6f);
        int nrow = (m0 & (N_ - 1)) + wm * 32 + mm * 16 + qrow;
        float b_lo = g_beta[bhh * N_ + nrow];
        float b_hi = g_beta[bhh * N_ + nrow + 8];
#pragma unroll
        for (int nf = 0; nf < 8; nf++) {
            float v0 = acc[mm][nf][0] * invl, v1 = acc[mm][nf][1] * invl;
            float v2 = acc[mm][nf][2] * invh, v3 = acc[mm][nf][3] * invh;
            mk0[nf]  += v0 + v2;
            mk1[nf]  += v1 + v3;
            mbk0[nf] += b_lo * v0 + b_hi * v2;
            mbk1[nf] += b_lo * v1 + b_hi * v3;
        }
    }
#pragma unroll
    for (int o = 4; o <= 16; o <<= 1) {
#pragma unroll
        for (int nf = 0; nf < 8; nf++) {
            mk0[nf]  += __shfl_xor_sync(0xffffffffu, mk0[nf], o);
            mk1[nf]  += __shfl_xor_sync(0xffffffffu, mk1[nf], o);
            mbk0[nf] += __shfl_xor_sync(0xffffffffu, mbk0[nf], o);
            mbk1[nf] += __shfl_xor_sync(0xffffffffu, mbk1[nf], o);
        }
    }
    float* red = (float*)smem;   // reuse staging smem: [0,512) mk, [512,1024) mbk
    if (lane < 4) {
#pragma unroll
        for (int nf = 0; nf < 8; nf++) {
            red[wid * 64 + nf * 8 + lane * 2]           = mk0[nf];
            red[wid * 64 + nf * 8 + lane * 2 + 1]       = mk1[nf];
            red[512 + wid * 64 + nf * 8 + lane * 2]     = mbk0[nf];
            red[512 + wid * 64 + nf * 8 + lane * 2 + 1] = mbk1[nf];
        }
    }
    __syncthreads();
    if (tid < 128) {
        int hh = tid >> 6, col = tid & 63;
        float s = red[(hh * 4 + 0) * 64 + col] + red[(hh * 4 + 1) * 64 + col]
                + red[(hh * 4 + 2) * 64 + col] + red[(hh * 4 + 3) * 64 + col];
        g_mkp[(size_t)blockIdx.y * 256 + n0 + hh * 64 + col] = s;
    } else {
        int t2 = tid - 128, hh = t2 >> 6, col = t2 & 63;
        float s = red[512 + (hh * 4 + 0) * 64 + col] + red[512 + (hh * 4 + 1) * 64 + col]
                + red[512 + (hh * 4 + 2) * 64 + col] + red[512 + (hh * 4 + 3) * 64 + col];
        g_mbkp[(size_t)blockIdx.y * 256 + n0 + hh * 64 + col] = s;
    }
}

// ---------------- K3: xbar partials = sum_n beta*x over 64-row chunks ----------------
__global__ void __launch_bounds__(256)
xbar_kernel(const float* __restrict__ x)
{
    __shared__ float sbeta[64][4];
    int blk = blockIdx.x, m0 = blk * 64, tid = threadIdx.x;
    {
        int r = tid >> 2, h = tid & 3;
        int m = m0 + r, b = m >> 12, n = m & (N_ - 1);
        sbeta[r][h] = g_beta[(b * H_ + h) * N_ + n];
    }
    __syncthreads();
    float a0 = 0.f, a1 = 0.f, a2 = 0.f, a3 = 0.f;
    for (int r = 0; r < 64; r++) {
        float xv = x[(size_t)(m0 + r) * C_ + tid];
        a0 += xv * sbeta[r][0];
        a1 += xv * sbeta[r][1];
        a2 += xv * sbeta[r][2];
        a3 += xv * sbeta[r][3];
    }
    g_xbp[((size_t)blk * 4 + 0) * 256 + tid] = a0;
    g_xbp[((size_t)blk * 4 + 1) * 256 + tid] = a1;
    g_xbp[((size_t)blk * 4 + 2) * 256 + tid] = a2;
    g_xbp[((size_t)blk * 4 + 3) * 256 + tid] = a3;
}

// ---------------- K5a: invrms ----------------
__global__ void __launch_bounds__(256)
invrms_kernel()
{
    int m = blockIdx.x * 256 + threadIdx.x;
    float s = g_ssp[(size_t)m * 2] + g_ssp[(size_t)m * 2 + 1];
    g_invrms[m] = rsqrtf(s * (1.f / (float)C_) + 1e-6f);
}

// ---------------- K5b: finalize werr/wkey ----------------
__global__ void __launch_bounds__(256)
final_kernel(const float* __restrict__ S, const float* __restrict__ Wv)
{
    __shared__ float s_mk[64], s_mbk[64], s_xbar[256];
    int bh = blockIdx.x, b = bh >> 2, h = bh & 3, tid = threadIdx.x;
    {
        float a = 0.f;
        for (int t = 0; t < 64; t++)
            a += g_xbp[((size_t)(b * 64 + t) * 4 + h) * 256 + tid];
        s_xbar[tid] = a * (1.f / (float)N_);
    }
    if (tid < 64) {
        float s = 0.f;
        for (int t = 0; t < 32; t++)
            s += g_mkp[(size_t)(b * 32 + t) * 256 + h * 64 + tid];
        s_mk[tid] = s * (1.f / (float)N_);
    } else if (tid < 128) {
        int c = tid - 64;
        float s = 0.f;
        for (int t = 0; t < 32; t++)
            s += g_mbkp[(size_t)(b * 32 + t) * 256 + h * 64 + c];
        s_mbk[c] = s * (1.f / (float)N_);
    }
    __syncthreads();
    if (tid < 64) {
        int i = tid;
        const float* wv = Wv + (size_t)(h * 64 + i) * 256;
        float mbv = 0.f;
        for (int c = 0; c < 256; c++) mbv += wv[c] * s_xbar[c];
        const float* sd = S + (size_t)bh * 4096 + (size_t)i * 64;
        float sp = 0.f;
        for (int j = 0; j < 64; j++) sp += 0.95f * sd[j] * s_mbk[j];
        g_werr[bh * 64 + i] = mbv - sp;
        g_wkey[bh * 64 + i] = s_mk[i];
    }
}

// ---------------- K5c: S_new ----------------
__global__ void __launch_bounds__(256)
snew_kernel(const float* __restrict__ S, float* __restrict__ out_s)
{
    int idx = blockIdx.x * 256 + threadIdx.x;
    int bh = idx >> 12;
    int i = (idx >> 6) & 63;
    int j = idx & 63;
    float val = S[idx] * 0.95f + g_werr[bh * 64 + i] * g_wkey[bh * 64 + j];
    out_s[idx] = fminf(fmaxf(val, -10.f), 10.f);
}

// ---------------- launcher ----------------
extern "C" void kernel_launch(void* const* d_in, const int* in_sizes, int n_in,
                              void* d_out, int out_size)
{
    const float* x    = (const float*)d_in[0];
    const float* S    = (const float*)d_in[1];
    const float* Wq   = (const float*)d_in[2];
    const float* Wk   = (const float*)d_in[3];
    const float* Wv   = (const float*)d_in[4];
    const float* Wb   = (const float*)d_in[5];
    const float* Wo   = (const float*)d_in[6];
    const float* grms = (const float*)d_in[7];
    float* out = (float*)d_out;

    static int init = 0;
    if (!init) {
        cudaFuncSetAttribute(gemm_proj_kernel, cudaFuncAttributeMaxDynamicSharedMemorySize, 65536);
        cudaFuncSetAttribute(gemm_k_kernel, cudaFuncAttributeMaxDynamicSharedMemorySize, 65536);
        cudaFuncSetAttribute(wprime_kernel, cudaFuncAttributeMaxDynamicSharedMemorySize, 81920);
        init = 1;
    }

    // weight prep: Wk split, Wo*grms split; W' = Sd@Wq per batch
    convw_kernel<<<512, 256>>>(Wk, Wo, grms);
    wprime_kernel<<<64, 256, 81920>>>(S, Wq);

    // y = x @ W'^T (+ beta + ss partials)
    gemm_proj_kernel<<<dim3(2, 512), 256, 65536>>>(0, x, Wb, nullptr);

    // xbar partials (needs beta)
    xbar_kernel<<<1024, 256>>>(x);

    // k GEMM + fused reductions (needs beta)
    gemm_k_kernel<<<dim3(2, 512), 256, 65536>>>(x);

    // invrms, werr/wkey, S_new
    invrms_kernel<<<M_ / 256, 256>>>();
    final_kernel<<<64, 256>>>(S, Wv);
    if (out_size >= OUT_MAIN + OUT_S) {
        snew_kernel<<<OUT_S / 256, 256>>>(S, out + OUT_MAIN);
    }

    // out = irm * (y @ Wog^T)
    gemm_proj_kernel<<<dim3(2, 512), 256, 65536>>>(1, x, Wb, out);
}

// round 9
// speedup vs baseline: 1.4931x; 1.2489x over previous
#include <cuda_runtime.h>
#include <cuda_bf16.h>
#include <math.h>

// ---------------- constants ----------------
#define B_ 16
#define N_ 4096
#define C_ 256
#define H_ 4
#define D_ 64
#define M_ (B_ * N_)              // 65536
#define OUT_MAIN (M_ * C_)        // 16777216
#define OUT_S (B_ * H_ * D_ * D_) // 262144

typedef unsigned int u32;

// ---------------- device scratch ----------------
__device__ __nv_bfloat16 g_wph[B_ * C_ * C_], g_wpl[B_ * C_ * C_]; // W' = Sd@Wq per batch (split)
__device__ __nv_bfloat16 g_wsh[2][C_ * C_], g_wsl[2][C_ * C_];     // Wk, Wo*g (split)
__device__ float g_y[M_ * C_];
__device__ float g_beta[B_ * H_ * N_];
__device__ float g_ssp[M_ * 2];
__device__ float g_invrms[M_];
__device__ float g_mkp[512 * 256], g_mbkp[512 * 256];   // per-mtile k partials
__device__ float g_xbp[1024 * H_ * C_];                  // per-64row beta*x partials
__device__ float g_werr[64 * 64], g_wkey[64 * 64];

// ---------------- helpers ----------------
__device__ __forceinline__ u32 smem_u32(const void* p) {
    u32 a;
    asm("{ .reg .u64 t; cvta.to.shared.u64 t, %1; cvt.u32.u64 %0, t; }" : "=r"(a) : "l"(p));
    return a;
}
__device__ __forceinline__ void ldmx4(u32* r, u32 addr) {
    asm volatile("ldmatrix.sync.aligned.m8n8.x4.shared.b16 {%0,%1,%2,%3}, [%4];"
                 : "=r"(r[0]), "=r"(r[1]), "=r"(r[2]), "=r"(r[3]) : "r"(addr));
}
__device__ __forceinline__ void mma_bf16(float* d, const u32* a, u32 b0, u32 b1) {
    asm volatile("mma.sync.aligned.m16n8k16.row.col.f32.bf16.bf16.f32 "
                 "{%0,%1,%2,%3}, {%4,%5,%6,%7}, {%8,%9}, {%0,%1,%2,%3};"
                 : "+f"(d[0]), "+f"(d[1]), "+f"(d[2]), "+f"(d[3])
                 : "r"(a[0]), "r"(a[1]), "r"(a[2]), "r"(a[3]), "r"(b0), "r"(b1));
}
__device__ __forceinline__ u32 prmt16(u32 a, u32 b) {
    u32 r;
    asm("prmt.b32 %0, %1, %2, 0x7632;" : "=r"(r) : "r"(a), "r"(b));
    return r;
}
// truncation split: h = top16(f), l = top16(f - as_float(top16(f)))
__device__ __forceinline__ void split2(float f0, float f1, u32& h01, u32& l01) {
    u32 b0 = __float_as_uint(f0), b1 = __float_as_uint(f1);
    h01 = prmt16(b0, b1);
    float lo0 = f0 - __uint_as_float(b0 & 0xFFFF0000u);
    float lo1 = f1 - __uint_as_float(b1 & 0xFFFF0000u);
    l01 = prmt16(__float_as_uint(lo0), __float_as_uint(lo1));
}
__device__ __forceinline__ float eluf(float v) {
    return (v > 0.f) ? (v + 1.f) : expf(v);
}
#define CP_ASYNC16(dst, src) \
    asm volatile("cp.async.cg.shared.global [%0], [%1], 16;" :: "r"(dst), "l"(src))
#define CP_COMMIT() asm volatile("cp.async.commit_group;")
#define CP_WAIT0()  asm volatile("cp.async.wait_group 0;" ::: "memory")

// ---------------- K0: Wk, Wo*grms -> split bf16 ----------------
__global__ void __launch_bounds__(256) convw_kernel(
    const float* __restrict__ Wk, const float* __restrict__ Wo,
    const float* __restrict__ grms)
{
    int gid = blockIdx.x * 256 + threadIdx.x;   // < 131072
    int sel = gid >> 16, idx = gid & 65535;
    float v = sel ? (Wo[idx] * grms[idx & 255]) : Wk[idx];
    __nv_bfloat16 h = __float2bfloat16(v);
    g_wsh[sel][idx] = h;
    g_wsl[sel][idx] = __float2bfloat16(v - __bfloat162float(h));
}

// ---------------- K1: W'[b] = (0.95*S[b,h]) @ Wq_h, split bf16 ----------------
__global__ void __launch_bounds__(256)
wprime_kernel(const float* __restrict__ S, const float* __restrict__ Wq)
{
    extern __shared__ float sm[];        // sSdT[4096] + sWq[64*256] = 80KB
    float* sSdT = sm;
    float* sWq = sm + 4096;
    int bh = blockIdx.x, b = bh >> 2, h = bh & 3, tid = threadIdx.x;
    for (int t = tid; t < 4096; t += 256) {
        int i = t >> 6, j = t & 63;
        sSdT[j * 64 + i] = S[(size_t)bh * 4096 + t] * 0.95f;
    }
    for (int t = tid; t < 64 * 256; t += 256)
        sWq[t] = Wq[(size_t)(h * 64 + (t >> 8)) * 256 + (t & 255)];
    __syncthreads();
    int i = tid & 63, stripe = tid >> 6;
#pragma unroll 1
    for (int cc = 0; cc < 64; cc++) {
        int c = stripe * 64 + cc;
        float acc = 0.f;
#pragma unroll
        for (int j = 0; j < 64; j++)
            acc += sSdT[j * 64 + i] * sWq[j * 256 + c];
        __nv_bfloat16 hh = __float2bfloat16(acc);
        size_t o = (size_t)b * 65536 + (size_t)(h * 64 + i) * 256 + c;
        g_wph[o] = hh;
        g_wpl[o] = __float2bfloat16(acc - __bfloat162float(hh));
    }
}

// ============ pipelined GEMM body pieces (K=32 chunks, double buffered) ============
// smem layout per stage s (s in {0,1}): A at s*32768 (16KB), B at s*32768+16384 (16KB)
// A/B smem rows: 128 bytes = [h cols 0..31 | l cols 0..31] with XOR-8 swizzle on 16B groups.

// ---------------- K2/K6: projection GEMM, 128x128 tiles, pipelined ----------------
// task 0: y = x @ W'[b]^T (grid 2 x 512), fused beta (bx==0) + per-row ss partials
// task 1: out = irm * (y @ Wog^T) (grid 2 x 512) -> fout
__global__ void __launch_bounds__(256, 2)
gemm_proj_kernel(int task, const float* __restrict__ Xfp,
                 const float* __restrict__ Wb, float* __restrict__ fout)
{
    extern __shared__ char smem[];
    __shared__ float s_g[1024];
    __shared__ float sm_ss[128][2];
    const u32 sb = smem_u32(smem);
    const int tid = threadIdx.x, wid = tid >> 5, lane = tid & 31;
    const int m0 = blockIdx.y * 128;
    const int n0 = (int)blockIdx.x * 128;

    const float* Afp = (task == 0) ? Xfp : g_y;
    const __nv_bfloat16 *Bh, *Bl;
    bool doBeta = false;
    if (task == 0) {
        int b = m0 >> 12;
        Bh = g_wph + (size_t)b * 65536;
        Bl = g_wpl + (size_t)b * 65536;
        doBeta = (blockIdx.x == 0);
        if (doBeta) for (int i = tid; i < 1024; i += 256) s_g[i] = Wb[i];
    } else {
        Bh = g_wsh[1]; Bl = g_wsl[1];
    }
    __syncthreads();

    const int wm = wid & 3, wn = wid >> 2;
    const int rA = (lane & 7) + ((lane >> 3) & 1) * 8, cAx = (lane >> 4) & 1;
    const int rB = (lane & 7) + ((lane >> 4) & 1) * 8, cBx = (lane >> 3) & 1;

    float acc[2][8][4];
#pragma unroll
    for (int i = 0; i < 2; i++)
#pragma unroll
        for (int j = 0; j < 8; j++)
#pragma unroll
            for (int t = 0; t < 4; t++) acc[i][j][t] = 0.f;

    const int lr = tid >> 1, q = tid & 1;
    const size_t arow = (size_t)(m0 + lr) * C_ + q * 16;
    const size_t brow = (size_t)(n0 + lr) * C_;
    float ba0 = 0.f, ba1 = 0.f, ba2 = 0.f, ba3 = 0.f;
    float fr[16];

#define LD_A(c) do { \
    const float4* _p = (const float4*)(Afp + arow + (c) * 32); \
    *(float4*)(fr)      = _p[0]; *(float4*)(fr + 4)  = _p[1]; \
    *(float4*)(fr + 8)  = _p[2]; *(float4*)(fr + 12) = _p[3]; \
} while (0)

#define LD_B(c, ob) do { \
    _Pragma("unroll") \
    for (int _i = 0; _i < 2; _i++) { \
        int _cg = q * 2 + _i; \
        u32 _row = (ob) + (u32)lr * 128; \
        CP_ASYNC16(sb + _row + (u32)((_cg ^ (lr & 7)) << 4), \
                   (const void*)(Bh + brow + (c) * 32 + _cg * 8)); \
        CP_ASYNC16(sb + _row + (u32)(((_cg + 4) ^ (lr & 7)) << 4), \
                   (const void*)(Bl + brow + (c) * 32 + _cg * 8)); \
    } \
    CP_COMMIT(); \
} while (0)

#define ST_A(c, oa) do { \
    if (doBeta) { \
        int _colb = (c) * 32 + q * 16; \
        _Pragma("unroll") \
        for (int _h = 0; _h < 4; _h++) { \
            const float* _w = s_g + _h * 256 + _colb; \
            float _a = 0.f; \
            _Pragma("unroll") \
            for (int _t = 0; _t < 16; _t++) _a += fr[_t] * _w[_t]; \
            if (_h == 0) ba0 += _a; else if (_h == 1) ba1 += _a; \
            else if (_h == 2) ba2 += _a; else ba3 += _a; \
        } \
    } \
    u32 _hv[8], _lv[8]; \
    _Pragma("unroll") \
    for (int _t = 0; _t < 8; _t++) split2(fr[2 * _t], fr[2 * _t + 1], _hv[_t], _lv[_t]); \
    u32 _base = (oa) + (u32)lr * 128; \
    int _c0 = q * 2, _c1 = q * 2 + 1; \
    *(uint4*)(smem + _base + ((_c0 ^ (lr & 7)) << 4))       = make_uint4(_hv[0], _hv[1], _hv[2], _hv[3]); \
    *(uint4*)(smem + _base + ((_c1 ^ (lr & 7)) << 4))       = make_uint4(_hv[4], _hv[5], _hv[6], _hv[7]); \
    *(uint4*)(smem + _base + (((_c0 + 4) ^ (lr & 7)) << 4)) = make_uint4(_lv[0], _lv[1], _lv[2], _lv[3]); \
    *(uint4*)(smem + _base + (((_c1 + 4) ^ (lr & 7)) << 4)) = make_uint4(_lv[4], _lv[5], _lv[6], _lv[7]); \
} while (0)

#define MMA_CHUNK(s) do { \
    u32 _oa = (u32)(s) * 32768, _obm = _oa + 16384; \
    _Pragma("unroll") \
    for (int ks = 0; ks < 2; ks++) { \
        u32 ah[2][4], al[2][4]; \
        _Pragma("unroll") \
        for (int ms = 0; ms < 2; ms++) { \
            int r = wm * 32 + ms * 16 + rA; \
            u32 rowb = _oa + (u32)r * 128; \
            ldmx4(ah[ms], sb + rowb + (u32)((((2 * ks + cAx)) ^ (r & 7)) << 4)); \
            ldmx4(al[ms], sb + rowb + (u32)((((2 * ks + cAx) + 4) ^ (r & 7)) << 4)); \
        } \
        _Pragma("unroll") \
        for (int nh = 0; nh < 4; nh++) { \
            int n = wn * 64 + nh * 16 + rB; \
            u32 rowbB = _obm + (u32)n * 128; \
            u32 bhf[4], blf[4]; \
            ldmx4(bhf, sb + rowbB + (u32)((((2 * ks + cBx)) ^ (n & 7)) << 4)); \
            ldmx4(blf, sb + rowbB + (u32)((((2 * ks + cBx) + 4) ^ (n & 7)) << 4)); \
            _Pragma("unroll") \
            for (int ms = 0; ms < 2; ms++) { \
                mma_bf16(acc[ms][nh * 2],     ah[ms], bhf[0], bhf[1]); \
                mma_bf16(acc[ms][nh * 2 + 1], ah[ms], bhf[2], bhf[3]); \
                mma_bf16(acc[ms][nh * 2],     al[ms], bhf[0], bhf[1]); \
                mma_bf16(acc[ms][nh * 2 + 1], al[ms], bhf[2], bhf[3]); \
                mma_bf16(acc[ms][nh * 2],     ah[ms], blf[0], blf[1]); \
                mma_bf16(acc[ms][nh * 2 + 1], ah[ms], blf[2], blf[3]); \
            } \
        } \
    } \
} while (0)

    // prologue: stage chunk 0 into buffer 0
    LD_A(0);
    LD_B(0, 16384u);
    ST_A(0, 0u);
    CP_WAIT0();
    __syncthreads();

#pragma unroll
    for (int c = 0; c < 8; c++) {
        if (c < 7) { LD_A(c + 1); LD_B(c + 1, (u32)(((c + 1) & 1) * 32768 + 16384)); }
        MMA_CHUNK(c & 1);
        if (c < 7) {
            ST_A(c + 1, (u32)(((c + 1) & 1) * 32768));
            CP_WAIT0();
            __syncthreads();
        }
    }

    if (doBeta) {
        ba0 += __shfl_xor_sync(0xffffffffu, ba0, 1);
        ba1 += __shfl_xor_sync(0xffffffffu, ba1, 1);
        ba2 += __shfl_xor_sync(0xffffffffu, ba2, 1);
        ba3 += __shfl_xor_sync(0xffffffffu, ba3, 1);
        if (q == 0) {
            int m = m0 + lr, bb = m >> 12, n = m & (N_ - 1);
            g_beta[(bb * H_ + 0) * N_ + n] = 1.f / (1.f + expf(-ba0));
            g_beta[(bb * H_ + 1) * N_ + n] = 1.f / (1.f + expf(-ba1));
            g_beta[(bb * H_ + 2) * N_ + n] = 1.f / (1.f + expf(-ba2));
            g_beta[(bb * H_ + 3) * N_ + n] = 1.f / (1.f + expf(-ba3));
        }
    }

    // ---- epilogue ----
    const int qrow = lane >> 2, qcol = (lane & 3) * 2;
    if (task == 0) {
#pragma unroll
        for (int mm = 0; mm < 2; mm++) {
            size_t r_lo = (size_t)(m0 + wm * 32 + mm * 16 + qrow);
            size_t r_hi = r_lo + 8;
            float ssl = 0.f, ssh = 0.f;
#pragma unroll
            for (int nf = 0; nf < 8; nf++) {
                int cof = n0 + wn * 64 + nf * 8 + qcol;
                *(float2*)(g_y + r_lo * C_ + cof) = make_float2(acc[mm][nf][0], acc[mm][nf][1]);
                *(float2*)(g_y + r_hi * C_ + cof) = make_float2(acc[mm][nf][2], acc[mm][nf][3]);
                ssl += acc[mm][nf][0] * acc[mm][nf][0] + acc[mm][nf][1] * acc[mm][nf][1];
                ssh += acc[mm][nf][2] * acc[mm][nf][2] + acc[mm][nf][3] * acc[mm][nf][3];
            }
            ssl += __shfl_xor_sync(0xffffffffu, ssl, 1);
            ssl += __shfl_xor_sync(0xffffffffu, ssl, 2);
            ssh += __shfl_xor_sync(0xffffffffu, ssh, 1);
            ssh += __shfl_xor_sync(0xffffffffu, ssh, 2);
            if ((lane & 3) == 0) {
                sm_ss[wm * 32 + mm * 16 + qrow][wn]     = ssl;
                sm_ss[wm * 32 + mm * 16 + qrow + 8][wn] = ssh;
            }
        }
        __syncthreads();
        if (tid < 128)
            g_ssp[(size_t)(m0 + tid) * 2 + (n0 >> 7)] = sm_ss[tid][0] + sm_ss[tid][1];
    } else {
#pragma unroll
        for (int mm = 0; mm < 2; mm++) {
            size_t r_lo = (size_t)(m0 + wm * 32 + mm * 16 + qrow);
            size_t r_hi = r_lo + 8;
            float irm_lo = g_invrms[r_lo];
            float irm_hi = g_invrms[r_hi];
#pragma unroll
            for (int nf = 0; nf < 8; nf++) {
                int cof = n0 + wn * 64 + nf * 8 + qcol;
                *(float2*)(fout + r_lo * C_ + cof) =
                    make_float2(acc[mm][nf][0] * irm_lo, acc[mm][nf][1] * irm_lo);
                *(float2*)(fout + r_hi * C_ + cof) =
                    make_float2(acc[mm][nf][2] * irm_hi, acc[mm][nf][3] * irm_hi);
            }
        }
    }
#undef LD_A
#undef LD_B
#undef ST_A
#undef MMA_CHUNK
}

// ---------------- K4: k GEMM + fused elu/L2norm + mk/mbk reductions, pipelined ----------------
__global__ void __launch_bounds__(256, 2)
gemm_k_kernel(const float* __restrict__ Xfp)
{
    extern __shared__ char smem[];
    const u32 sb = smem_u32(smem);
    const int tid = threadIdx.x, wid = tid >> 5, lane = tid & 31;
    const int m0 = blockIdx.y * 128;
    const int n0 = (int)blockIdx.x * 128;
    const __nv_bfloat16* Bh = g_wsh[0];
    const __nv_bfloat16* Bl = g_wsl[0];

    const int wm = wid & 3, wn = wid >> 2;
    const int rA = (lane & 7) + ((lane >> 3) & 1) * 8, cAx = (lane >> 4) & 1;
    const int rB = (lane & 7) + ((lane >> 4) & 1) * 8, cBx = (lane >> 3) & 1;

    float acc[2][8][4];
#pragma unroll
    for (int i = 0; i < 2; i++)
#pragma unroll
        for (int j = 0; j < 8; j++)
#pragma unroll
            for (int t = 0; t < 4; t++) acc[i][j][t] = 0.f;

    const int lr = tid >> 1, q = tid & 1;
    const size_t arow = (size_t)(m0 + lr) * C_ + q * 16;
    const size_t brow = (size_t)(n0 + lr) * C_;
    float fr[16];

#define LD_A(c) do { \
    const float4* _p = (const float4*)(Xfp + arow + (c) * 32); \
    *(float4*)(fr)      = _p[0]; *(float4*)(fr + 4)  = _p[1]; \
    *(float4*)(fr + 8)  = _p[2]; *(float4*)(fr + 12) = _p[3]; \
} while (0)

#define LD_B(c, ob) do { \
    _Pragma("unroll") \
    for (int _i = 0; _i < 2; _i++) { \
        int _cg = q * 2 + _i; \
        u32 _row = (ob) + (u32)lr * 128; \
        CP_ASYNC16(sb + _row + (u32)((_cg ^ (lr & 7)) << 4), \
                   (const void*)(Bh + brow + (c) * 32 + _cg * 8)); \
        CP_ASYNC16(sb + _row + (u32)(((_cg + 4) ^ (lr & 7)) << 4), \
                   (const void*)(Bl + brow + (c) * 32 + _cg * 8)); \
    } \
    CP_COMMIT(); \
} while (0)

#define ST_A(c, oa) do { \
    u32 _hv[8], _lv[8]; \
    _Pragma("unroll") \
    for (int _t = 0; _t < 8; _t++) split2(fr[2 * _t], fr[2 * _t + 1], _hv[_t], _lv[_t]); \
    u32 _base = (oa) + (u32)lr * 128; \
    int _c0 = q * 2, _c1 = q * 2 + 1; \
    *(uint4*)(smem + _base + ((_c0 ^ (lr & 7)) << 4))       = make_uint4(_hv[0], _hv[1], _hv[2], _hv[3]); \
    *(uint4*)(smem + _base + ((_c1 ^ (lr & 7)) << 4))       = make_uint4(_hv[4], _hv[5], _hv[6], _hv[7]); \
    *(uint4*)(smem + _base + (((_c0 + 4) ^ (lr & 7)) << 4)) = make_uint4(_lv[0], _lv[1], _lv[2], _lv[3]); \
    *(uint4*)(smem + _base + (((_c1 + 4) ^ (lr & 7)) << 4)) = make_uint4(_lv[4], _lv[5], _lv[6], _lv[7]); \
} while (0)

#define MMA_CHUNK(s) do { \
    u32 _oa = (u32)(s) * 32768, _obm = _oa + 16384; \
    _Pragma("unroll") \
    for (int ks = 0; ks < 2; ks++) { \
        u32 ah[2][4], al[2][4]; \
        _Pragma("unroll") \
        for (int ms = 0; ms < 2; ms++) { \
            int r = wm * 32 + ms * 16 + rA; \
            u32 rowb = _oa + (u32)r * 128; \
            ldmx4(ah[ms], sb + rowb + (u32)((((2 * ks + cAx)) ^ (r & 7)) << 4)); \
            ldmx4(al[ms], sb + rowb + (u32)((((2 * ks + cAx) + 4) ^ (r & 7)) << 4)); \
        } \
        _Pragma("unroll") \
        for (int nh = 0; nh < 4; nh++) { \
            int n = wn * 64 + nh * 16 + rB; \
            u32 rowbB = _obm + (u32)n * 128; \
            u32 bhf[4], blf[4]; \
            ldmx4(bhf, sb + rowbB + (u32)((((2 * ks + cBx)) ^ (n & 7)) << 4)); \
            ldmx4(blf, sb + rowbB + (u32)((((2 * ks + cBx) + 4) ^ (n & 7)) << 4)); \
            _Pragma("unroll") \
            for (int ms = 0; ms < 2; ms++) { \
                mma_bf16(acc[ms][nh * 2],     ah[ms], bhf[0], bhf[1]); \
                mma_bf16(acc[ms][nh * 2 + 1], ah[ms], bhf[2], bhf[3]); \
                mma_bf16(acc[ms][nh * 2],     al[ms], bhf[0], bhf[1]); \
                mma_bf16(acc[ms][nh * 2 + 1], al[ms], bhf[2], bhf[3]); \
                mma_bf16(acc[ms][nh * 2],     ah[ms], blf[0], blf[1]); \
                mma_bf16(acc[ms][nh * 2 + 1], ah[ms], blf[2], blf[3]); \
            } \
        } \
    } \
} while (0)

    LD_A(0);
    LD_B(0, 16384u);
    ST_A(0, 0u);
    CP_WAIT0();
    __syncthreads();

#pragma unroll
    for (int c = 0; c < 8; c++) {
        if (c < 7) { LD_A(c + 1); LD_B(c + 1, (u32)(((c + 1) & 1) * 32768 + 16384)); }
        MMA_CHUNK(c & 1);
        if (c < 7) {
            ST_A(c + 1, (u32)(((c + 1) & 1) * 32768));
            CP_WAIT0();
            __syncthreads();
        }
    }

    // ---- epilogue: elu+1, per-head L2 norm, reduce mk & beta-weighted mbk over rows ----
    const int qrow = lane >> 2, qcol = (lane & 3) * 2;
    const int head = (n0 >> 6) + wn;
    const int bhh = (m0 >> 12) * H_ + head;
    float mk0[8], mk1[8], mbk0[8], mbk1[8];
#pragma unroll
    for (int nf = 0; nf < 8; nf++) { mk0[nf] = mk1[nf] = mbk0[nf] = mbk1[nf] = 0.f; }

#pragma unroll
    for (int mm = 0; mm < 2; mm++) {
        float ssl = 0.f, ssh = 0.f;
#pragma unroll
        for (int nf = 0; nf < 8; nf++) {
            float e0 = eluf(acc[mm][nf][0]); acc[mm][nf][0] = e0; ssl += e0 * e0;
            float e1 = eluf(acc[mm][nf][1]); acc[mm][nf][1] = e1; ssl += e1 * e1;
            float e2 = eluf(acc[mm][nf][2]); acc[mm][nf][2] = e2; ssh += e2 * e2;
            float e3 = eluf(acc[mm][nf][3]); acc[mm][nf][3] = e3; ssh += e3 * e3;
        }
        ssl += __shfl_xor_sync(0xffffffffu, ssl, 1);
        ssl += __shfl_xor_sync(0xffffffffu, ssl, 2);
        ssh += __shfl_xor_sync(0xffffffffu, ssh, 1);
        ssh += __shfl_xor_sync(0xffffffffu, ssh, 2);
        float invl = 1.f / (sqrtf(ssl) + 1e-6f);
        float invh = 1.f / (sqrtf(ssh) + 1e-6f);
        int nrow = (m0 & (N_ - 1)) + wm * 32 + mm * 16 + qrow;
        float b_lo = g_beta[bhh * N_ + nrow];
        float b_hi = g_beta[bhh * N_ + nrow + 8];
#pragma unroll
        for (int nf = 0; nf < 8; nf++) {
            float v0 = acc[mm][nf][0] * invl, v1 = acc[mm][nf][1] * invl;
            float v2 = acc[mm][nf][2] * invh, v3 = acc[mm][nf][3] * invh;
            mk0[nf]  += v0 + v2;
            mk1[nf]  += v1 + v3;
            mbk0[nf] += b_lo * v0 + b_hi * v2;
            mbk1[nf] += b_lo * v1 + b_hi * v3;
        }
    }
#pragma unroll
    for (int o = 4; o <= 16; o <<= 1) {
#pragma unroll
        for (int nf = 0; nf < 8; nf++) {
            mk0[nf]  += __shfl_xor_sync(0xffffffffu, mk0[nf], o);
            mk1[nf]  += __shfl_xor_sync(0xffffffffu, mk1[nf], o);
            mbk0[nf] += __shfl_xor_sync(0xffffffffu, mbk0[nf], o);
            mbk1[nf] += __shfl_xor_sync(0xffffffffu, mbk1[nf], o);
        }
    }
    __syncthreads();
    float* red = (float*)smem;   // reuse staging smem: [0,512) mk, [512,1024) mbk
    if (lane < 4) {
#pragma unroll
        for (int nf = 0; nf < 8; nf++) {
            red[wid * 64 + nf * 8 + lane * 2]           = mk0[nf];
            red[wid * 64 + nf * 8 + lane * 2 + 1]       = mk1[nf];
            red[512 + wid * 64 + nf * 8 + lane * 2]     = mbk0[nf];
            red[512 + wid * 64 + nf * 8 + lane * 2 + 1] = mbk1[nf];
        }
    }
    __syncthreads();
    if (tid < 128) {
        int hh = tid >> 6, col = tid & 63;
        float s = red[(hh * 4 + 0) * 64 + col] + red[(hh * 4 + 1) * 64 + col]
                + red[(hh * 4 + 2) * 64 + col] + red[(hh * 4 + 3) * 64 + col];
        g_mkp[(size_t)blockIdx.y * 256 + n0 + hh * 64 + col] = s;
    } else {
        int t2 = tid - 128, hh = t2 >> 6, col = t2 & 63;
        float s = red[512 + (hh * 4 + 0) * 64 + col] + red[512 + (hh * 4 + 1) * 64 + col]
                + red[512 + (hh * 4 + 2) * 64 + col] + red[512 + (hh * 4 + 3) * 64 + col];
        g_mbkp[(size_t)blockIdx.y * 256 + n0 + hh * 64 + col] = s;
    }
#undef LD_A
#undef LD_B
#undef ST_A
#undef MMA_CHUNK
}

// ---------------- K3: xbar partials = sum_n beta*x over 64-row chunks ----------------
__global__ void __launch_bounds__(256)
xbar_kernel(const float* __restrict__ x)
{
    __shared__ float sbeta[64][4];
    int blk = blockIdx.x, m0 = blk * 64, tid = threadIdx.x;
    {
        int r = tid >> 2, h = tid & 3;
        int m = m0 + r, b = m >> 12, n = m & (N_ - 1);
        sbeta[r][h] = g_beta[(b * H_ + h) * N_ + n];
    }
    __syncthreads();
    float a0 = 0.f, a1 = 0.f, a2 = 0.f, a3 = 0.f;
    for (int r = 0; r < 64; r++) {
        float xv = x[(size_t)(m0 + r) * C_ + tid];
        a0 += xv * sbeta[r][0];
        a1 += xv * sbeta[r][1];
        a2 += xv * sbeta[r][2];
        a3 += xv * sbeta[r][3];
    }
    g_xbp[((size_t)blk * 4 + 0) * 256 + tid] = a0;
    g_xbp[((size_t)blk * 4 + 1) * 256 + tid] = a1;
    g_xbp[((size_t)blk * 4 + 2) * 256 + tid] = a2;
    g_xbp[((size_t)blk * 4 + 3) * 256 + tid] = a3;
}

// ---------------- K5a: invrms ----------------
__global__ void __launch_bounds__(256)
invrms_kernel()
{
    int m = blockIdx.x * 256 + threadIdx.x;
    float s = g_ssp[(size_t)m * 2] + g_ssp[(size_t)m * 2 + 1];
    g_invrms[m] = rsqrtf(s * (1.f / (float)C_) + 1e-6f);
}

// ---------------- K5b: finalize werr/wkey ----------------
__global__ void __launch_bounds__(256)
final_kernel(const float* __restrict__ S, const float* __restrict__ Wv)
{
    __shared__ float s_mk[64], s_mbk[64], s_xbar[256];
    int bh = blockIdx.x, b = bh >> 2, h = bh & 3, tid = threadIdx.x;
    {
        float a = 0.f;
        for (int t = 0; t < 64; t++)
            a += g_xbp[((size_t)(b * 64 + t) * 4 + h) * 256 + tid];
        s_xbar[tid] = a * (1.f / (float)N_);
    }
    if (tid < 64) {
        float s = 0.f;
        for (int t = 0; t < 32; t++)
            s += g_mkp[(size_t)(b * 32 + t) * 256 + h * 64 + tid];
        s_mk[tid] = s * (1.f / (float)N_);
    } else if (tid < 128) {
        int c = tid - 64;
        float s = 0.f;
        for (int t = 0; t < 32; t++)
            s += g_mbkp[(size_t)(b * 32 + t) * 256 + h * 64 + c];
        s_mbk[c] = s * (1.f / (float)N_);
    }
    __syncthreads();
    if (tid < 64) {
        int i = tid;
        const float* wv = Wv + (size_t)(h * 64 + i) * 256;
        float mbv = 0.f;
        for (int c = 0; c < 256; c++) mbv += wv[c] * s_xbar[c];
        const float* sd = S + (size_t)bh * 4096 + (size_t)i * 64;
        float sp = 0.f;
        for (int j = 0; j < 64; j++) sp += 0.95f * sd[j] * s_mbk[j];
        g_werr[bh * 64 + i] = mbv - sp;
        g_wkey[bh * 64 + i] = s_mk[i];
    }
}

// ---------------- K5c: S_new ----------------
__global__ void __launch_bounds__(256)
snew_kernel(const float* __restrict__ S, float* __restrict__ out_s)
{
    int idx = blockIdx.x * 256 + threadIdx.x;
    int bh = idx >> 12;
    int i = (idx >> 6) & 63;
    int j = idx & 63;
    float val = S[idx] * 0.95f + g_werr[bh * 64 + i] * g_wkey[bh * 64 + j];
    out_s[idx] = fminf(fmaxf(val, -10.f), 10.f);
}

// ---------------- launcher ----------------
extern "C" void kernel_launch(void* const* d_in, const int* in_sizes, int n_in,
                              void* d_out, int out_size)
{
    const float* x    = (const float*)d_in[0];
    const float* S    = (const float*)d_in[1];
    const float* Wq   = (const float*)d_in[2];
    const float* Wk   = (const float*)d_in[3];
    const float* Wv   = (const float*)d_in[4];
    const float* Wb   = (const float*)d_in[5];
    const float* Wo   = (const float*)d_in[6];
    const float* grms = (const float*)d_in[7];
    float* out = (float*)d_out;

    static int init = 0;
    if (!init) {
        cudaFuncSetAttribute(gemm_proj_kernel, cudaFuncAttributeMaxDynamicSharedMemorySize, 65536);
        cudaFuncSetAttribute(gemm_k_kernel, cudaFuncAttributeMaxDynamicSharedMemorySize, 65536);
        cudaFuncSetAttribute(wprime_kernel, cudaFuncAttributeMaxDynamicSharedMemorySize, 81920);
        init = 1;
    }

    // weight prep: Wk split, Wo*grms split; W' = Sd@Wq per batch
    convw_kernel<<<512, 256>>>(Wk, Wo, grms);
    wprime_kernel<<<64, 256, 81920>>>(S, Wq);

    // y = x @ W'^T (+ beta + ss partials)  [pipelined]
    gemm_proj_kernel<<<dim3(2, 512), 256, 65536>>>(0, x, Wb, nullptr);

    // xbar partials (needs beta)
    xbar_kernel<<<1024, 256>>>(x);

    // k GEMM + fused reductions (needs beta)  [pipelined]
    gemm_k_kernel<<<dim3(2, 512), 256, 65536>>>(x);

    // invrms, werr/wkey, S_new
    invrms_kernel<<<M_ / 256, 256>>>();
    final_kernel<<<64, 256>>>(S, Wv);
    if (out_size >= OUT_MAIN + OUT_S) {
        snew_kernel<<<OUT_S / 256, 256>>>(S, out + OUT_MAIN);
    }

    // out = irm * (y @ Wog^T)  [pipelined]
    gemm_proj_kernel<<<dim3(2, 512), 256, 65536>>>(1, x, Wb, out);
}

// round 10
// speedup vs baseline: 1.5385x; 1.0304x over previous
#include <cuda_runtime.h>
#include <cuda_bf16.h>
#include <math.h>

// ---------------- constants ----------------
#define B_ 16
#define N_ 4096
#define C_ 256
#define H_ 4
#define D_ 64
#define M_ (B_ * N_)              // 65536
#define OUT_MAIN (M_ * C_)        // 16777216
#define OUT_S (B_ * H_ * D_ * D_) // 262144

typedef unsigned int u32;

// ---------------- device scratch ----------------
__device__ __nv_bfloat16 g_wph[B_ * C_ * C_], g_wpl[B_ * C_ * C_]; // W' = Sd@Wq per batch (split)
__device__ __nv_bfloat16 g_wsh[2][C_ * C_], g_wsl[2][C_ * C_];     // Wk, Wo*g (split)
__device__ float g_y[M_ * C_];
__device__ float g_beta[B_ * H_ * N_];
__device__ float g_ssp[M_ * 2];
__device__ float g_invrms[M_];
__device__ float g_mkp[512 * 256], g_mbkp[512 * 256];   // per-mtile k partials
__device__ float g_xbp[1024 * H_ * C_];                  // per-64row beta*x partials
__device__ float g_werr[64 * 64], g_wkey[64 * 64];

// ---------------- helpers ----------------
__device__ __forceinline__ u32 smem_u32(const void* p) {
    u32 a;
    asm("{ .reg .u64 t; cvta.to.shared.u64 t, %1; cvt.u32.u64 %0, t; }" : "=r"(a) : "l"(p));
    return a;
}
__device__ __forceinline__ void ldmx4(u32* r, u32 addr) {
    asm volatile("ldmatrix.sync.aligned.m8n8.x4.shared.b16 {%0,%1,%2,%3}, [%4];"
                 : "=r"(r[0]), "=r"(r[1]), "=r"(r[2]), "=r"(r[3]) : "r"(addr));
}
__device__ __forceinline__ void mma_bf16(float* d, const u32* a, u32 b0, u32 b1) {
    asm volatile("mma.sync.aligned.m16n8k16.row.col.f32.bf16.bf16.f32 "
                 "{%0,%1,%2,%3}, {%4,%5,%6,%7}, {%8,%9}, {%0,%1,%2,%3};"
                 : "+f"(d[0]), "+f"(d[1]), "+f"(d[2]), "+f"(d[3])
                 : "r"(a[0]), "r"(a[1]), "r"(a[2]), "r"(a[3]), "r"(b0), "r"(b1));
}
__device__ __forceinline__ u32 prmt16(u32 a, u32 b) {
    u32 r;
    asm("prmt.b32 %0, %1, %2, 0x7632;" : "=r"(r) : "r"(a), "r"(b));
    return r;
}
// truncation split: h = top16(f), l = top16(f - as_float(top16(f)))
__device__ __forceinline__ void split2(float f0, float f1, u32& h01, u32& l01) {
    u32 b0 = __float_as_uint(f0), b1 = __float_as_uint(f1);
    h01 = prmt16(b0, b1);
    float lo0 = f0 - __uint_as_float(b0 & 0xFFFF0000u);
    float lo1 = f1 - __uint_as_float(b1 & 0xFFFF0000u);
    l01 = prmt16(__float_as_uint(lo0), __float_as_uint(lo1));
}
__device__ __forceinline__ float eluf(float v) {
    return (v > 0.f) ? (v + 1.f) : expf(v);
}
#define CP_ASYNC16(dst, src) \
    asm volatile("cp.async.cg.shared.global [%0], [%1], 16;" :: "r"(dst), "l"(src))
#define CP_COMMIT() asm volatile("cp.async.commit_group;")
#define CP_WAIT0()  asm volatile("cp.async.wait_group 0;" ::: "memory")

// ---------------- K0: Wk, Wo*grms -> split bf16 ----------------
__global__ void __launch_bounds__(256) convw_kernel(
    const float* __restrict__ Wk, const float* __restrict__ Wo,
    const float* __restrict__ grms)
{
    int gid = blockIdx.x * 256 + threadIdx.x;   // < 131072
    int sel = gid >> 16, idx = gid & 65535;
    float v = sel ? (Wo[idx] * grms[idx & 255]) : Wk[idx];
    __nv_bfloat16 h = __float2bfloat16(v);
    g_wsh[sel][idx] = h;
    g_wsl[sel][idx] = __float2bfloat16(v - __bfloat162float(h));
}

// ---------------- K1: W'[b] = (0.95*S[b,h]) @ Wq_h, split bf16 ----------------
__global__ void __launch_bounds__(256)
wprime_kernel(const float* __restrict__ S, const float* __restrict__ Wq)
{
    extern __shared__ float sm[];        // sSdT[4096] + sWq[64*256] = 80KB
    float* sSdT = sm;
    float* sWq = sm + 4096;
    int bh = blockIdx.x, b = bh >> 2, h = bh & 3, tid = threadIdx.x;
    for (int t = tid; t < 4096; t += 256) {
        int i = t >> 6, j = t & 63;
        sSdT[j * 64 + i] = S[(size_t)bh * 4096 + t] * 0.95f;
    }
    for (int t = tid; t < 64 * 256; t += 256)
        sWq[t] = Wq[(size_t)(h * 64 + (t >> 8)) * 256 + (t & 255)];
    __syncthreads();
    int i = tid & 63, stripe = tid >> 6;
#pragma unroll 1
    for (int cc = 0; cc < 64; cc++) {
        int c = stripe * 64 + cc;
        float acc = 0.f;
#pragma unroll
        for (int j = 0; j < 64; j++)
            acc += sSdT[j * 64 + i] * sWq[j * 256 + c];
        __nv_bfloat16 hh = __float2bfloat16(acc);
        size_t o = (size_t)b * 65536 + (size_t)(h * 64 + i) * 256 + c;
        g_wph[o] = hh;
        g_wpl[o] = __float2bfloat16(acc - __bfloat162float(hh));
    }
}

// ============ pipelined GEMM body pieces (K=32 chunks, double buffered) ============
// smem layout per stage s (s in {0,1}): A at s*32768 (16KB), B at s*32768+16384 (16KB)
// A/B smem rows: 128 bytes = [h cols 0..31 | l cols 0..31] with XOR-8 swizzle on 16B groups.

// ---------------- K2/K6: projection GEMM, 128x128 tiles, pipelined ----------------
// task 0: y = x @ W'[b]^T (grid 2 x 512), fused beta (bx==0) + per-row ss partials
// task 1: out = irm * (y @ Wog^T) (grid 2 x 512) -> fout
__global__ void __launch_bounds__(256, 2)
gemm_proj_kernel(int task, const float* __restrict__ Xfp,
                 const float* __restrict__ Wb, float* __restrict__ fout)
{
    extern __shared__ char smem[];
    __shared__ float s_g[1024];
    __shared__ float sm_ss[128][2];
    const u32 sb = smem_u32(smem);
    const int tid = threadIdx.x, wid = tid >> 5, lane = tid & 31;
    const int m0 = blockIdx.y * 128;
    const int n0 = (int)blockIdx.x * 128;

    const float* Afp = (task == 0) ? Xfp : g_y;
    const __nv_bfloat16 *Bh, *Bl;
    bool doBeta = false;
    if (task == 0) {
        int b = m0 >> 12;
        Bh = g_wph + (size_t)b * 65536;
        Bl = g_wpl + (size_t)b * 65536;
        doBeta = (blockIdx.x == 0);
        if (doBeta) for (int i = tid; i < 1024; i += 256) s_g[i] = Wb[i];
    } else {
        Bh = g_wsh[1]; Bl = g_wsl[1];
    }
    __syncthreads();

    const int wm = wid & 3, wn = wid >> 2;
    const int rA = (lane & 7) + ((lane >> 3) & 1) * 8, cAx = (lane >> 4) & 1;
    const int rB = (lane & 7) + ((lane >> 4) & 1) * 8, cBx = (lane >> 3) & 1;

    float acc[2][8][4];
#pragma unroll
    for (int i = 0; i < 2; i++)
#pragma unroll
        for (int j = 0; j < 8; j++)
#pragma unroll
            for (int t = 0; t < 4; t++) acc[i][j][t] = 0.f;

    const int lr = tid >> 1, q = tid & 1;
    const size_t arow = (size_t)(m0 + lr) * C_ + q * 16;
    const size_t brow = (size_t)(n0 + lr) * C_;
    float ba0 = 0.f, ba1 = 0.f, ba2 = 0.f, ba3 = 0.f;
    float fr[16];

#define LD_A(c) do { \
    const float4* _p = (const float4*)(Afp + arow + (c) * 32); \
    *(float4*)(fr)      = _p[0]; *(float4*)(fr + 4)  = _p[1]; \
    *(float4*)(fr + 8)  = _p[2]; *(float4*)(fr + 12) = _p[3]; \
} while (0)

#define LD_B(c, ob) do { \
    _Pragma("unroll") \
    for (int _i = 0; _i < 2; _i++) { \
        int _cg = q * 2 + _i; \
        u32 _row = (ob) + (u32)lr * 128; \
        CP_ASYNC16(sb + _row + (u32)((_cg ^ (lr & 7)) << 4), \
                   (const void*)(Bh + brow + (c) * 32 + _cg * 8)); \
        CP_ASYNC16(sb + _row + (u32)(((_cg + 4) ^ (lr & 7)) << 4), \
                   (const void*)(Bl + brow + (c) * 32 + _cg * 8)); \
    } \
    CP_COMMIT(); \
} while (0)

#define ST_A(c, oa) do { \
    if (doBeta) { \
        int _colb = (c) * 32 + q * 16; \
        _Pragma("unroll") \
        for (int _h = 0; _h < 4; _h++) { \
            const float* _w = s_g + _h * 256 + _colb; \
            float _a = 0.f; \
            _Pragma("unroll") \
            for (int _t = 0; _t < 16; _t++) _a += fr[_t] * _w[_t]; \
            if (_h == 0) ba0 += _a; else if (_h == 1) ba1 += _a; \
            else if (_h == 2) ba2 += _a; else ba3 += _a; \
        } \
    } \
    u32 _hv[8], _lv[8]; \
    _Pragma("unroll") \
    for (int _t = 0; _t < 8; _t++) split2(fr[2 * _t], fr[2 * _t + 1], _hv[_t], _lv[_t]); \
    u32 _base = (oa) + (u32)lr * 128; \
    int _c0 = q * 2, _c1 = q * 2 + 1; \
    *(uint4*)(smem + _base + ((_c0 ^ (lr & 7)) << 4))       = make_uint4(_hv[0], _hv[1], _hv[2], _hv[3]); \
    *(uint4*)(smem + _base + ((_c1 ^ (lr & 7)) << 4))       = make_uint4(_hv[4], _hv[5], _hv[6], _hv[7]); \
    *(uint4*)(smem + _base + (((_c0 + 4) ^ (lr & 7)) << 4)) = make_uint4(_lv[0], _lv[1], _lv[2], _lv[3]); \
    *(uint4*)(smem + _base + (((_c1 + 4) ^ (lr & 7)) << 4)) = make_uint4(_lv[4], _lv[5], _lv[6], _lv[7]); \
} while (0)

#define MMA_CHUNK(s) do { \
    u32 _oa = (u32)(s) * 32768, _obm = _oa + 16384; \
    _Pragma("unroll") \
    for (int ks = 0; ks < 2; ks++) { \
        u32 ah[2][4], al[2][4]; \
        _Pragma("unroll") \
        for (int ms = 0; ms < 2; ms++) { \
            int r = wm * 32 + ms * 16 + rA; \
            u32 rowb = _oa + (u32)r * 128; \
            ldmx4(ah[ms], sb + rowb + (u32)((((2 * ks + cAx)) ^ (r & 7)) << 4)); \
            ldmx4(al[ms], sb + rowb + (u32)((((2 * ks + cAx) + 4) ^ (r & 7)) << 4)); \
        } \
        _Pragma("unroll") \
        for (int nh = 0; nh < 4; nh++) { \
            int n = wn * 64 + nh * 16 + rB; \
            u32 rowbB = _obm + (u32)n * 128; \
            u32 bhf[4], blf[4]; \
            ldmx4(bhf, sb + rowbB + (u32)((((2 * ks + cBx)) ^ (n & 7)) << 4)); \
            ldmx4(blf, sb + rowbB + (u32)((((2 * ks + cBx) + 4) ^ (n & 7)) << 4)); \
            _Pragma("unroll") \
            for (int ms = 0; ms < 2; ms++) { \
                mma_bf16(acc[ms][nh * 2],     ah[ms], bhf[0], bhf[1]); \
                mma_bf16(acc[ms][nh * 2 + 1], ah[ms], bhf[2], bhf[3]); \
                mma_bf16(acc[ms][nh * 2],     al[ms], bhf[0], bhf[1]); \
                mma_bf16(acc[ms][nh * 2 + 1], al[ms], bhf[2], bhf[3]); \
                mma_bf16(acc[ms][nh * 2],     ah[ms], blf[0], blf[1]); \
                mma_bf16(acc[ms][nh * 2 + 1], ah[ms], blf[2], blf[3]); \
            } \
        } \
    } \
} while (0)

    // prologue: stage chunk 0 into buffer 0
    LD_A(0);
    LD_B(0, 16384u);
    ST_A(0, 0u);
    CP_WAIT0();
    __syncthreads();

#pragma unroll
    for (int c = 0; c < 8; c++) {
        if (c < 7) { LD_A(c + 1); LD_B(c + 1, (u32)(((c + 1) & 1) * 32768 + 16384)); }
        MMA_CHUNK(c & 1);
        if (c < 7) {
            ST_A(c + 1, (u32)(((c + 1) & 1) * 32768));
            CP_WAIT0();
            __syncthreads();
        }
    }

    if (doBeta) {
        ba0 += __shfl_xor_sync(0xffffffffu, ba0, 1);
        ba1 += __shfl_xor_sync(0xffffffffu, ba1, 1);
        ba2 += __shfl_xor_sync(0xffffffffu, ba2, 1);
        ba3 += __shfl_xor_sync(0xffffffffu, ba3, 1);
        if (q == 0) {
            int m = m0 + lr, bb = m >> 12, n = m & (N_ - 1);
            g_beta[(bb * H_ + 0) * N_ + n] = 1.f / (1.f + expf(-ba0));
            g_beta[(bb * H_ + 1) * N_ + n] = 1.f / (1.f + expf(-ba1));
            g_beta[(bb * H_ + 2) * N_ + n] = 1.f / (1.f + expf(-ba2));
            g_beta[(bb * H_ + 3) * N_ + n] = 1.f / (1.f + expf(-ba3));
        }
    }

    // ---- epilogue ----
    const int qrow = lane >> 2, qcol = (lane & 3) * 2;
    if (task == 0) {
#pragma unroll
        for (int mm = 0; mm < 2; mm++) {
            size_t r_lo = (size_t)(m0 + wm * 32 + mm * 16 + qrow);
            size_t r_hi = r_lo + 8;
            float ssl = 0.f, ssh = 0.f;
#pragma unroll
            for (int nf = 0; nf < 8; nf++) {
                int cof = n0 + wn * 64 + nf * 8 + qcol;
                *(float2*)(g_y + r_lo * C_ + cof) = make_float2(acc[mm][nf][0], acc[mm][nf][1]);
                *(float2*)(g_y + r_hi * C_ + cof) = make_float2(acc[mm][nf][2], acc[mm][nf][3]);
                ssl += acc[mm][nf][0] * acc[mm][nf][0] + acc[mm][nf][1] * acc[mm][nf][1];
                ssh += acc[mm][nf][2] * acc[mm][nf][2] + acc[mm][nf][3] * acc[mm][nf][3];
            }
            ssl += __shfl_xor_sync(0xffffffffu, ssl, 1);
            ssl += __shfl_xor_sync(0xffffffffu, ssl, 2);
            ssh += __shfl_xor_sync(0xffffffffu, ssh, 1);
            ssh += __shfl_xor_sync(0xffffffffu, ssh, 2);
            if ((lane & 3) == 0) {
                sm_ss[wm * 32 + mm * 16 + qrow][wn]     = ssl;
                sm_ss[wm * 32 + mm * 16 + qrow + 8][wn] = ssh;
            }
        }
        __syncthreads();
        if (tid < 128)
            g_ssp[(size_t)(m0 + tid) * 2 + (n0 >> 7)] = sm_ss[tid][0] + sm_ss[tid][1];
    } else {
#pragma unroll
        for (int mm = 0; mm < 2; mm++) {
            size_t r_lo = (size_t)(m0 + wm * 32 + mm * 16 + qrow);
            size_t r_hi = r_lo + 8;
            float irm_lo = g_invrms[r_lo];
            float irm_hi = g_invrms[r_hi];
#pragma unroll
            for (int nf = 0; nf < 8; nf++) {
                int cof = n0 + wn * 64 + nf * 8 + qcol;
                *(float2*)(fout + r_lo * C_ + cof) =
                    make_float2(acc[mm][nf][0] * irm_lo, acc[mm][nf][1] * irm_lo);
                *(float2*)(fout + r_hi * C_ + cof) =
                    make_float2(acc[mm][nf][2] * irm_hi, acc[mm][nf][3] * irm_hi);
            }
        }
    }
#undef LD_A
#undef LD_B
#undef ST_A
#undef MMA_CHUNK
}

// ---------------- K4: k GEMM + fused elu/L2norm + mk/mbk reductions, pipelined ----------------
__global__ void __launch_bounds__(256, 2)
gemm_k_kernel(const float* __restrict__ Xfp)
{
    extern __shared__ char smem[];
    const u32 sb = smem_u32(smem);
    const int tid = threadIdx.x, wid = tid >> 5, lane = tid & 31;
    const int m0 = blockIdx.y * 128;
    const int n0 = (int)blockIdx.x * 128;
    const __nv_bfloat16* Bh = g_wsh[0];
    const __nv_bfloat16* Bl = g_wsl[0];

    const int wm = wid & 3, wn = wid >> 2;
    const int rA = (lane & 7) + ((lane >> 3) & 1) * 8, cAx = (lane >> 4) & 1;
    const int rB = (lane & 7) + ((lane >> 4) & 1) * 8, cBx = (lane >> 3) & 1;

    float acc[2][8][4];
#pragma unroll
    for (int i = 0; i < 2; i++)
#pragma unroll
        for (int j = 0; j < 8; j++)
#pragma unroll
            for (int t = 0; t < 4; t++) acc[i][j][t] = 0.f;

    const int lr = tid >> 1, q = tid & 1;
    const size_t arow = (size_t)(m0 + lr) * C_ + q * 16;
    const size_t brow = (size_t)(n0 + lr) * C_;
    float fr[16];

#define LD_A(c) do { \
    const float4* _p = (const float4*)(Xfp + arow + (c) * 32); \
    *(float4*)(fr)      = _p[0]; *(float4*)(fr + 4)  = _p[1]; \
    *(float4*)(fr + 8)  = _p[2]; *(float4*)(fr + 12) = _p[3]; \
} while (0)

#define LD_B(c, ob) do { \
    _Pragma("unroll") \
    for (int _i = 0; _i < 2; _i++) { \
        int _cg = q * 2 + _i; \
        u32 _row = (ob) + (u32)lr * 128; \
        CP_ASYNC16(sb + _row + (u32)((_cg ^ (lr & 7)) << 4), \
                   (const void*)(Bh + brow + (c) * 32 + _cg * 8)); \
        CP_ASYNC16(sb + _row + (u32)(((_cg + 4) ^ (lr & 7)) << 4), \
                   (const void*)(Bl + brow + (c) * 32 + _cg * 8)); \
    } \
    CP_COMMIT(); \
} while (0)

#define ST_A(c, oa) do { \
    u32 _hv[8], _lv[8]; \
    _Pragma("unroll") \
    for (int _t = 0; _t < 8; _t++) split2(fr[2 * _t], fr[2 * _t + 1], _hv[_t], _lv[_t]); \
    u32 _base = (oa) + (u32)lr * 128; \
    int _c0 = q * 2, _c1 = q * 2 + 1; \
    *(uint4*)(smem + _base + ((_c0 ^ (lr & 7)) << 4))       = make_uint4(_hv[0], _hv[1], _hv[2], _hv[3]); \
    *(uint4*)(smem + _base + ((_c1 ^ (lr & 7)) << 4))       = make_uint4(_hv[4], _hv[5], _hv[6], _hv[7]); \
    *(uint4*)(smem + _base + (((_c0 + 4) ^ (lr & 7)) << 4)) = make_uint4(_lv[0], _lv[1], _lv[2], _lv[3]); \
    *(uint4*)(smem + _base + (((_c1 + 4) ^ (lr & 7)) << 4)) = make_uint4(_lv[4], _lv[5], _lv[6], _lv[7]); \
} while (0)

#define MMA_CHUNK(s) do { \
    u32 _oa = (u32)(s) * 32768, _obm = _oa + 16384; \
    _Pragma("unroll") \
    for (int ks = 0; ks < 2; ks++) { \
        u32 ah[2][4], al[2][4]; \
        _Pragma("unroll") \
        for (int ms = 0; ms < 2; ms++) { \
            int r = wm * 32 + ms * 16 + rA; \
            u32 rowb = _oa + (u32)r * 128; \
            ldmx4(ah[ms], sb + rowb + (u32)((((2 * ks + cAx)) ^ (r & 7)) << 4)); \
            ldmx4(al[ms], sb + rowb + (u32)((((2 * ks + cAx) + 4) ^ (r & 7)) << 4)); \
        } \
        _Pragma("unroll") \
        for (int nh = 0; nh < 4; nh++) { \
            int n = wn * 64 + nh * 16 + rB; \
            u32 rowbB = _obm + (u32)n * 128; \
            u32 bhf[4], blf[4]; \
            ldmx4(bhf, sb + rowbB + (u32)((((2 * ks + cBx)) ^ (n & 7)) << 4)); \
            ldmx4(blf, sb + rowbB + (u32)((((2 * ks + cBx) + 4) ^ (n & 7)) << 4)); \
            _Pragma("unroll") \
            for (int ms = 0; ms < 2; ms++) { \
                mma_bf16(acc[ms][nh * 2],     ah[ms], bhf[0], bhf[1]); \
                mma_bf16(acc[ms][nh * 2 + 1], ah[ms], bhf[2], bhf[3]); \
                mma_bf16(acc[ms][nh * 2],     al[ms], bhf[0], bhf[1]); \
                mma_bf16(acc[ms][nh * 2 + 1], al[ms], bhf[2], bhf[3]); \
                mma_bf16(acc[ms][nh * 2],     ah[ms], blf[0], blf[1]); \
                mma_bf16(acc[ms][nh * 2 + 1], ah[ms], blf[2], blf[3]); \
            } \
        } \
    } \
} while (0)

    LD_A(0);
    LD_B(0, 16384u);
    ST_A(0, 0u);
    CP_WAIT0();
    __syncthreads();

#pragma unroll
    for (int c = 0; c < 8; c++) {
        if (c < 7) { LD_A(c + 1); LD_B(c + 1, (u32)(((c + 1) & 1) * 32768 + 16384)); }
        MMA_CHUNK(c & 1);
        if (c < 7) {
            ST_A(c + 1, (u32)(((c + 1) & 1) * 32768));
            CP_WAIT0();
            __syncthreads();
        }
    }

    // ---- epilogue: elu+1, per-head L2 norm, reduce mk & beta-weighted mbk over rows ----
    const int qrow = lane >> 2, qcol = (lane & 3) * 2;
    const int head = (n0 >> 6) + wn;
    const int bhh = (m0 >> 12) * H_ + head;
    float mk0[8], mk1[8], mbk0[8], mbk1[8];
#pragma unroll
    for (int nf = 0; nf < 8; nf++) { mk0[nf] = mk1[nf] = mbk0[nf] = mbk1[nf] = 0.f; }

#pragma unroll
    for (int mm = 0; mm < 2; mm++) {
        float ssl = 0.f, ssh = 0.f;
#pragma unroll
        for (int nf = 0; nf < 8; nf++) {
            float e0 = eluf(acc[mm][nf][0]); acc[mm][nf][0] = e0; ssl += e0 * e0;
            float e1 = eluf(acc[mm][nf][1]); acc[mm][nf][1] = e1; ssl += e1 * e1;
            float e2 = eluf(acc[mm][nf][2]); acc[mm][nf][2] = e2; ssh += e2 * e2;
            float e3 = eluf(acc[mm][nf][3]); acc[mm][nf][3] = e3; ssh += e3 * e3;
        }
        ssl += __shfl_xor_sync(0xffffffffu, ssl, 1);
        ssl += __shfl_xor_sync(0xffffffffu, ssl, 2);
        ssh += __shfl_xor_sync(0xffffffffu, ssh, 1);
        ssh += __shfl_xor_sync(0xffffffffu, ssh, 2);
        float invl = 1.f / (sqrtf(ssl) + 1e-6f);
        float invh = 1.f / (sqrtf(ssh) + 1e-6f);
        int nrow = (m0 & (N_ - 1)) + wm * 32 + mm * 16 + qrow;
        float b_lo = g_beta[bhh * N_ + nrow];
        float b_hi = g_beta[bhh * N_ + nrow + 8];
#pragma unroll
        for (int nf = 0; nf < 8; nf++) {
            float v0 = acc[mm][nf][0] * invl, v1 = acc[mm][nf][1] * invl;
            float v2 = acc[mm][nf][2] * invh, v3 = acc[mm][nf][3] * invh;
            mk0[nf]  += v0 + v2;
            mk1[nf]  += v1 + v3;
            mbk0[nf] += b_lo * v0 + b_hi * v2;
            mbk1[nf] += b_lo * v1 + b_hi * v3;
        }
    }
#pragma unroll
    for (int o = 4; o <= 16; o <<= 1) {
#pragma unroll
        for (int nf = 0; nf < 8; nf++) {
            mk0[nf]  += __shfl_xor_sync(0xffffffffu, mk0[nf], o);
            mk1[nf]  += __shfl_xor_sync(0xffffffffu, mk1[nf], o);
            mbk0[nf] += __shfl_xor_sync(0xffffffffu, mbk0[nf], o);
            mbk1[nf] += __shfl_xor_sync(0xffffffffu, mbk1[nf], o);
        }
    }
    __syncthreads();
    float* red = (float*)smem;   // reuse staging smem: [0,512) mk, [512,1024) mbk
    if (lane < 4) {
#pragma unroll
        for (int nf = 0; nf < 8; nf++) {
            red[wid * 64 + nf * 8 + lane * 2]           = mk0[nf];
            red[wid * 64 + nf * 8 + lane * 2 + 1]       = mk1[nf];
            red[512 + wid * 64 + nf * 8 + lane * 2]     = mbk0[nf];
            red[512 + wid * 64 + nf * 8 + lane * 2 + 1] = mbk1[nf];
        }
    }
    __syncthreads();
    if (tid < 128) {
        int hh = tid >> 6, col = tid & 63;
        float s = red[(hh * 4 + 0) * 64 + col] + red[(hh * 4 + 1) * 64 + col]
                + red[(hh * 4 + 2) * 64 + col] + red[(hh * 4 + 3) * 64 + col];
        g_mkp[(size_t)blockIdx.y * 256 + n0 + hh * 64 + col] = s;
    } else {
        int t2 = tid - 128, hh = t2 >> 6, col = t2 & 63;
        float s = red[512 + (hh * 4 + 0) * 64 + col] + red[512 + (hh * 4 + 1) * 64 + col]
                + red[512 + (hh * 4 + 2) * 64 + col] + red[512 + (hh * 4 + 3) * 64 + col];
        g_mbkp[(size_t)blockIdx.y * 256 + n0 + hh * 64 + col] = s;
    }
#undef LD_A
#undef LD_B
#undef ST_A
#undef MMA_CHUNK
}

// ---------------- K3: xbar partials = sum_n beta*x over 64-row chunks ----------------
__global__ void __launch_bounds__(256)
xbar_kernel(const float* __restrict__ x)
{
    __shared__ float sbeta[64][4];
    int blk = blockIdx.x, m0 = blk * 64, tid = threadIdx.x;
    {
        int r = tid >> 2, h = tid & 3;
        int m = m0 + r, b = m >> 12, n = m & (N_ - 1);
        sbeta[r][h] = g_beta[(b * H_ + h) * N_ + n];
    }
    __syncthreads();
    float a0 = 0.f, a1 = 0.f, a2 = 0.f, a3 = 0.f;
    for (int r = 0; r < 64; r++) {
        float xv = x[(size_t)(m0 + r) * C_ + tid];
        a0 += xv * sbeta[r][0];
        a1 += xv * sbeta[r][1];
        a2 += xv * sbeta[r][2];
        a3 += xv * sbeta[r][3];
    }
    g_xbp[((size_t)blk * 4 + 0) * 256 + tid] = a0;
    g_xbp[((size_t)blk * 4 + 1) * 256 + tid] = a1;
    g_xbp[((size_t)blk * 4 + 2) * 256 + tid] = a2;
    g_xbp[((size_t)blk * 4 + 3) * 256 + tid] = a3;
}

// ---------------- K5a: invrms ----------------
__global__ void __launch_bounds__(256)
invrms_kernel()
{
    int m = blockIdx.x * 256 + threadIdx.x;
    float s = g_ssp[(size_t)m * 2] + g_ssp[(size_t)m * 2 + 1];
    g_invrms[m] = rsqrtf(s * (1.f / (float)C_) + 1e-6f);
}

// ---------------- K5b: finalize werr/wkey ----------------
__global__ void __launch_bounds__(256)
final_kernel(const float* __restrict__ S, const float* __restrict__ Wv)
{
    __shared__ float s_mk[64], s_mbk[64], s_xbar[256];
    int bh = blockIdx.x, b = bh >> 2, h = bh & 3, tid = threadIdx.x;
    {
        float a = 0.f;
        for (int t = 0; t < 64; t++)
            a += g_xbp[((size_t)(b * 64 + t) * 4 + h) * 256 + tid];
        s_xbar[tid] = a * (1.f / (float)N_);
    }
    if (tid < 64) {
        float s = 0.f;
        for (int t = 0; t < 32; t++)
            s += g_mkp[(size_t)(b * 32 + t) * 256 + h * 64 + tid];
        s_mk[tid] = s * (1.f / (float)N_);
    } else if (tid < 128) {
        int c = tid - 64;
        float s = 0.f;
        for (int t = 0; t < 32; t++)
            s += g_mbkp[(size_t)(b * 32 + t) * 256 + h * 64 + c];
        s_mbk[c] = s * (1.f / (float)N_);
    }
    __syncthreads();
    if (tid < 64) {
        int i = tid;
        const float* wv = Wv + (size_t)(h * 64 + i) * 256;
        float mbv = 0.f;
        for (int c = 0; c < 256; c++) mbv += wv[c] * s_xbar[c];
        const float* sd = S + (size_t)bh * 4096 + (size_t)i * 64;
        float sp = 0.f;
        for (int j = 0; j < 64; j++) sp += 0.95f * sd[j] * s_mbk[j];
        g_werr[bh * 64 + i] = mbv - sp;
        g_wkey[bh * 64 + i] = s_mk[i];
    }
}

// ---------------- K5c: S_new ----------------
__global__ void __launch_bounds__(256)
snew_kernel(const float* __restrict__ S, float* __restrict__ out_s)
{
    int idx = blockIdx.x * 256 + threadIdx.x;
    int bh = idx >> 12;
    int i = (idx >> 6) & 63;
    int j = idx & 63;
    float val = S[idx] * 0.95f + g_werr[bh * 64 + i] * g_wkey[bh * 64 + j];
    out_s[idx] = fminf(fmaxf(val, -10.f), 10.f);
}

// ---------------- launcher ----------------
extern "C" void kernel_launch(void* const* d_in, const int* in_sizes, int n_in,
                              void* d_out, int out_size)
{
    const float* x    = (const float*)d_in[0];
    const float* S    = (const float*)d_in[1];
    const float* Wq   = (const float*)d_in[2];
    const float* Wk   = (const float*)d_in[3];
    const float* Wv   = (const float*)d_in[4];
    const float* Wb   = (const float*)d_in[5];
    const float* Wo   = (const float*)d_in[6];
    const float* grms = (const float*)d_in[7];
    float* out = (float*)d_out;

    static int init = 0;
    static cudaStream_t s2;
    static cudaEvent_t eA, eB;
    if (!init) {
        cudaFuncSetAttribute(gemm_proj_kernel, cudaFuncAttributeMaxDynamicSharedMemorySize, 65536);
        cudaFuncSetAttribute(gemm_k_kernel, cudaFuncAttributeMaxDynamicSharedMemorySize, 65536);
        cudaFuncSetAttribute(wprime_kernel, cudaFuncAttributeMaxDynamicSharedMemorySize, 81920);
        cudaStreamCreateWithFlags(&s2, cudaStreamNonBlocking);
        cudaEventCreateWithFlags(&eA, cudaEventDisableTiming);
        cudaEventCreateWithFlags(&eB, cudaEventDisableTiming);
        init = 1;
    }

    // --- main stream: weight prep + y-projection ---
    convw_kernel<<<512, 256>>>(Wk, Wo, grms);                       // launch 1
    wprime_kernel<<<64, 256, 81920>>>(S, Wq);                       // launch 2
    gemm_proj_kernel<<<dim3(2, 512), 256, 65536>>>(0, x, Wb, nullptr); // launch 3

    // --- fork: delta-rule branch (needs beta only) on s2 ---
    cudaEventRecord(eA, 0);
    cudaStreamWaitEvent(s2, eA, 0);
    gemm_k_kernel<<<dim3(2, 512), 256, 65536, s2>>>(x);             // launch 4 (profiled)
    xbar_kernel<<<1024, 256, 0, s2>>>(x);                           // launch 5
    final_kernel<<<64, 256, 0, s2>>>(S, Wv);                        // launch 6
    if (out_size >= OUT_MAIN + OUT_S) {
        snew_kernel<<<OUT_S / 256, 256, 0, s2>>>(S, out + OUT_MAIN);
    }
    cudaEventRecord(eB, s2);

    // --- main stream: rmsnorm branch (needs ssp only) runs concurrently with s2 ---
    invrms_kernel<<<M_ / 256, 256>>>();
    gemm_proj_kernel<<<dim3(2, 512), 256, 65536>>>(1, x, Wb, out);

    // --- join ---
    cudaStreamWaitEvent(0, eB, 0);
}

// round 11
// speedup vs baseline: 1.9127x; 1.2432x over previous
#include <cuda_runtime.h>
#include <cuda_bf16.h>
#include <math.h>

// ---------------- constants ----------------
#define B_ 16
#define N_ 4096
#define C_ 256
#define H_ 4
#define D_ 64
#define M_ (B_ * N_)              // 65536
#define OUT_MAIN (M_ * C_)        // 16777216
#define OUT_S (B_ * H_ * D_ * D_) // 262144

typedef unsigned int u32;

// ---------------- device scratch ----------------
__device__ __nv_bfloat16 g_wph[B_ * C_ * C_], g_wpl[B_ * C_ * C_]; // W' = Sd@Wq per batch (split)
__device__ __nv_bfloat16 g_wsh[2][C_ * C_], g_wsl[2][C_ * C_];     // Wk, Wo*g (split)
__device__ float g_y[M_ * C_];
__device__ float g_beta[B_ * H_ * N_];
__device__ float g_ssp[M_ * 2];
__device__ float g_invrms[M_];
__device__ float g_mkp[512 * 256], g_mbkp[512 * 256];   // per-mtile k partials
__device__ float g_xbp[1024 * H_ * C_];                  // per-64row beta*x partials
__device__ float g_werr[64 * 64], g_wkey[64 * 64];

// ---------------- helpers ----------------
__device__ __forceinline__ u32 smem_u32(const void* p) {
    u32 a;
    asm("{ .reg .u64 t; cvta.to.shared.u64 t, %1; cvt.u32.u64 %0, t; }" : "=r"(a) : "l"(p));
    return a;
}
__device__ __forceinline__ void ldmx4(u32* r, u32 addr) {
    asm volatile("ldmatrix.sync.aligned.m8n8.x4.shared.b16 {%0,%1,%2,%3}, [%4];"
                 : "=r"(r[0]), "=r"(r[1]), "=r"(r[2]), "=r"(r[3]) : "r"(addr));
}
__device__ __forceinline__ void mma_bf16(float* d, const u32* a, u32 b0, u32 b1) {
    asm volatile("mma.sync.aligned.m16n8k16.row.col.f32.bf16.bf16.f32 "
                 "{%0,%1,%2,%3}, {%4,%5,%6,%7}, {%8,%9}, {%0,%1,%2,%3};"
                 : "+f"(d[0]), "+f"(d[1]), "+f"(d[2]), "+f"(d[3])
                 : "r"(a[0]), "r"(a[1]), "r"(a[2]), "r"(a[3]), "r"(b0), "r"(b1));
}
__device__ __forceinline__ u32 prmt16(u32 a, u32 b) {
    u32 r;
    asm("prmt.b32 %0, %1, %2, 0x7632;" : "=r"(r) : "r"(a), "r"(b));
    return r;
}
// truncation split: h = top16(f), l = top16(f - as_float(top16(f)))
__device__ __forceinline__ void split2(float f0, float f1, u32& h01, u32& l01) {
    u32 b0 = __float_as_uint(f0), b1 = __float_as_uint(f1);
    h01 = prmt16(b0, b1);
    float lo0 = f0 - __uint_as_float(b0 & 0xFFFF0000u);
    float lo1 = f1 - __uint_as_float(b1 & 0xFFFF0000u);
    l01 = prmt16(__float_as_uint(lo0), __float_as_uint(lo1));
}
__device__ __forceinline__ float eluf(float v) {
    return (v > 0.f) ? (v + 1.f) : expf(v);
}
#define CP_ASYNC16(dst, src) \
    asm volatile("cp.async.cg.shared.global [%0], [%1], 16;" :: "r"(dst), "l"(src))
#define CP_COMMIT() asm volatile("cp.async.commit_group;")
#define CP_WAIT0()  asm volatile("cp.async.wait_group 0;" ::: "memory")

// ---------------- K0: Wk, Wo*grms -> split bf16 ----------------
__global__ void __launch_bounds__(256) convw_kernel(
    const float* __restrict__ Wk, const float* __restrict__ Wo,
    const float* __restrict__ grms)
{
    int gid = blockIdx.x * 256 + threadIdx.x;   // < 131072
    int sel = gid >> 16, idx = gid & 65535;
    float v = sel ? (Wo[idx] * grms[idx & 255]) : Wk[idx];
    __nv_bfloat16 h = __float2bfloat16(v);
    g_wsh[sel][idx] = h;
    g_wsl[sel][idx] = __float2bfloat16(v - __bfloat162float(h));
}

// ---------------- K0b: beta = sigmoid(x @ Wb^T), warp per row ----------------
__global__ void __launch_bounds__(256)
beta_kernel(const float* __restrict__ x, const float* __restrict__ Wb)
{
    int warp = (blockIdx.x * 256 + threadIdx.x) >> 5;
    int lane = threadIdx.x & 31;
    int m = warp;
    float a0 = 0.f, a1 = 0.f, a2 = 0.f, a3 = 0.f;
#pragma unroll
    for (int cc = 0; cc < 8; cc++) {
        int c = cc * 32 + lane;
        float xv = x[(size_t)m * C_ + c];
        a0 += xv * Wb[c];
        a1 += xv * Wb[256 + c];
        a2 += xv * Wb[512 + c];
        a3 += xv * Wb[768 + c];
    }
#pragma unroll
    for (int o = 16; o; o >>= 1) {
        a0 += __shfl_down_sync(0xffffffffu, a0, o);
        a1 += __shfl_down_sync(0xffffffffu, a1, o);
        a2 += __shfl_down_sync(0xffffffffu, a2, o);
        a3 += __shfl_down_sync(0xffffffffu, a3, o);
    }
    if (lane == 0) {
        int bb = m >> 12, n = m & (N_ - 1);
        g_beta[(bb * H_ + 0) * N_ + n] = 1.f / (1.f + expf(-a0));
        g_beta[(bb * H_ + 1) * N_ + n] = 1.f / (1.f + expf(-a1));
        g_beta[(bb * H_ + 2) * N_ + n] = 1.f / (1.f + expf(-a2));
        g_beta[(bb * H_ + 3) * N_ + n] = 1.f / (1.f + expf(-a3));
    }
}

// ---------------- K1: W'[b] = (0.95*S[b,h]) @ Wq_h, split bf16 ----------------
__global__ void __launch_bounds__(256)
wprime_kernel(const float* __restrict__ S, const float* __restrict__ Wq)
{
    extern __shared__ float sm[];        // sSdT[4096] + sWq[64*256] = 80KB
    float* sSdT = sm;
    float* sWq = sm + 4096;
    int bh = blockIdx.x, b = bh >> 2, h = bh & 3, tid = threadIdx.x;
    for (int t = tid; t < 4096; t += 256) {
        int i = t >> 6, j = t & 63;
        sSdT[j * 64 + i] = S[(size_t)bh * 4096 + t] * 0.95f;
    }
    for (int t = tid; t < 64 * 256; t += 256)
        sWq[t] = Wq[(size_t)(h * 64 + (t >> 8)) * 256 + (t & 255)];
    __syncthreads();
    int i = tid & 63, stripe = tid >> 6;
#pragma unroll 1
    for (int cc = 0; cc < 64; cc++) {
        int c = stripe * 64 + cc;
        float acc = 0.f;
#pragma unroll
        for (int j = 0; j < 64; j++)
            acc += sSdT[j * 64 + i] * sWq[j * 256 + c];
        __nv_bfloat16 hh = __float2bfloat16(acc);
        size_t o = (size_t)b * 65536 + (size_t)(h * 64 + i) * 256 + c;
        g_wph[o] = hh;
        g_wpl[o] = __float2bfloat16(acc - __bfloat162float(hh));
    }
}

// ============ pipelined GEMM body pieces (K=32 chunks, double buffered) ============
// smem layout per stage s: A at s*32768 (16KB), B at s*32768+16384 (16KB)
// A/B smem rows: 128 bytes = [h cols 0..31 | l cols 0..31] with XOR-8 swizzle on 16B groups.
// MMA order within (ks,nh): pass-major over (ms,pair) -> same-acc reuse distance 4.

// ---------------- K2/K6: projection GEMM, 128x128 tiles, pipelined ----------------
// task 0: y = x @ W'[b]^T (grid 2 x 512) + per-row ss partials
// task 1: out = irm * (y @ Wog^T) (grid 2 x 512) -> fout
__global__ void __launch_bounds__(256, 2)
gemm_proj_kernel(int task, const float* __restrict__ Xfp, float* __restrict__ fout)
{
    extern __shared__ char smem[];
    __shared__ float sm_ss[128][2];
    const u32 sb = smem_u32(smem);
    const int tid = threadIdx.x, wid = tid >> 5, lane = tid & 31;
    const int m0 = blockIdx.y * 128;
    const int n0 = (int)blockIdx.x * 128;

    const float* Afp = (task == 0) ? Xfp : g_y;
    const __nv_bfloat16 *Bh, *Bl;
    if (task == 0) {
        int b = m0 >> 12;
        Bh = g_wph + (size_t)b * 65536;
        Bl = g_wpl + (size_t)b * 65536;
    } else {
        Bh = g_wsh[1]; Bl = g_wsl[1];
    }

    const int wm = wid & 3, wn = wid >> 2;
    const int rA = (lane & 7) + ((lane >> 3) & 1) * 8, cAx = (lane >> 4) & 1;
    const int rB = (lane & 7) + ((lane >> 4) & 1) * 8, cBx = (lane >> 3) & 1;

    float acc[2][8][4];
#pragma unroll
    for (int i = 0; i < 2; i++)
#pragma unroll
        for (int j = 0; j < 8; j++)
#pragma unroll
            for (int t = 0; t < 4; t++) acc[i][j][t] = 0.f;

    const int lr = tid >> 1, q = tid & 1;
    const size_t arow = (size_t)(m0 + lr) * C_ + q * 16;
    const size_t brow = (size_t)(n0 + lr) * C_;
    float fr[16];

#define LD_A(c) do { \
    const float4* _p = (const float4*)(Afp + arow + (c) * 32); \
    *(float4*)(fr)      = _p[0]; *(float4*)(fr + 4)  = _p[1]; \
    *(float4*)(fr + 8)  = _p[2]; *(float4*)(fr + 12) = _p[3]; \
} while (0)

#define LD_B(c, ob) do { \
    _Pragma("unroll") \
    for (int _i = 0; _i < 2; _i++) { \
        int _cg = q * 2 + _i; \
        u32 _row = (ob) + (u32)lr * 128; \
        CP_ASYNC16(sb + _row + (u32)((_cg ^ (lr & 7)) << 4), \
                   (const void*)(Bh + brow + (c) * 32 + _cg * 8)); \
        CP_ASYNC16(sb + _row + (u32)(((_cg + 4) ^ (lr & 7)) << 4), \
                   (const void*)(Bl + brow + (c) * 32 + _cg * 8)); \
    } \
    CP_COMMIT(); \
} while (0)

#define ST_A(c, oa) do { \
    u32 _hv[8], _lv[8]; \
    _Pragma("unroll") \
    for (int _t = 0; _t < 8; _t++) split2(fr[2 * _t], fr[2 * _t + 1], _hv[_t], _lv[_t]); \
    u32 _base = (oa) + (u32)lr * 128; \
    int _c0 = q * 2, _c1 = q * 2 + 1; \
    *(uint4*)(smem + _base + ((_c0 ^ (lr & 7)) << 4))       = make_uint4(_hv[0], _hv[1], _hv[2], _hv[3]); \
    *(uint4*)(smem + _base + ((_c1 ^ (lr & 7)) << 4))       = make_uint4(_hv[4], _hv[5], _hv[6], _hv[7]); \
    *(uint4*)(smem + _base + (((_c0 + 4) ^ (lr & 7)) << 4)) = make_uint4(_lv[0], _lv[1], _lv[2], _lv[3]); \
    *(uint4*)(smem + _base + (((_c1 + 4) ^ (lr & 7)) << 4)) = make_uint4(_lv[4], _lv[5], _lv[6], _lv[7]); \
} while (0)

#define MMA_CHUNK(s) do { \
    u32 _oa = (u32)(s) * 32768, _obm = _oa + 16384; \
    _Pragma("unroll") \
    for (int ks = 0; ks < 2; ks++) { \
        u32 ah[2][4], al[2][4]; \
        _Pragma("unroll") \
        for (int ms = 0; ms < 2; ms++) { \
            int r = wm * 32 + ms * 16 + rA; \
            u32 rowb = _oa + (u32)r * 128; \
            ldmx4(ah[ms], sb + rowb + (u32)((((2 * ks + cAx)) ^ (r & 7)) << 4)); \
            ldmx4(al[ms], sb + rowb + (u32)((((2 * ks + cAx) + 4) ^ (r & 7)) << 4)); \
        } \
        _Pragma("unroll") \
        for (int nh = 0; nh < 4; nh++) { \
            int n = wn * 64 + nh * 16 + rB; \
            u32 rowbB = _obm + (u32)n * 128; \
            u32 bhf[4], blf[4]; \
            ldmx4(bhf, sb + rowbB + (u32)((((2 * ks + cBx)) ^ (n & 7)) << 4)); \
            ldmx4(blf, sb + rowbB + (u32)((((2 * ks + cBx) + 4) ^ (n & 7)) << 4)); \
            /* pass 1: ah x bh */ \
            mma_bf16(acc[0][nh * 2],     ah[0], bhf[0], bhf[1]); \
            mma_bf16(acc[1][nh * 2],     ah[1], bhf[0], bhf[1]); \
            mma_bf16(acc[0][nh * 2 + 1], ah[0], bhf[2], bhf[3]); \
            mma_bf16(acc[1][nh * 2 + 1], ah[1], bhf[2], bhf[3]); \
            /* pass 2: al x bh */ \
            mma_bf16(acc[0][nh * 2],     al[0], bhf[0], bhf[1]); \
            mma_bf16(acc[1][nh * 2],     al[1], bhf[0], bhf[1]); \
            mma_bf16(acc[0][nh * 2 + 1], al[0], bhf[2], bhf[3]); \
            mma_bf16(acc[1][nh * 2 + 1], al[1], bhf[2], bhf[3]); \
            /* pass 3: ah x bl */ \
            mma_bf16(acc[0][nh * 2],     ah[0], blf[0], blf[1]); \
            mma_bf16(acc[1][nh * 2],     ah[1], blf[0], blf[1]); \
            mma_bf16(acc[0][nh * 2 + 1], ah[0], blf[2], blf[3]); \
            mma_bf16(acc[1][nh * 2 + 1], ah[1], blf[2], blf[3]); \
        } \
    } \
} while (0)

    // prologue: stage chunk 0 into buffer 0
    LD_A(0);
    LD_B(0, 16384u);
    ST_A(0, 0u);
    CP_WAIT0();
    __syncthreads();

#pragma unroll
    for (int c = 0; c < 8; c++) {
        if (c < 7) { LD_A(c + 1); LD_B(c + 1, (u32)(((c + 1) & 1) * 32768 + 16384)); }
        MMA_CHUNK(c & 1);
        if (c < 7) {
            ST_A(c + 1, (u32)(((c + 1) & 1) * 32768));
            CP_WAIT0();
            __syncthreads();
        }
    }

    // ---- epilogue ----
    const int qrow = lane >> 2, qcol = (lane & 3) * 2;
    if (task == 0) {
#pragma unroll
        for (int mm = 0; mm < 2; mm++) {
            size_t r_lo = (size_t)(m0 + wm * 32 + mm * 16 + qrow);
            size_t r_hi = r_lo + 8;
            float ssl = 0.f, ssh = 0.f;
#pragma unroll
            for (int nf = 0; nf < 8; nf++) {
                int cof = n0 + wn * 64 + nf * 8 + qcol;
                *(float2*)(g_y + r_lo * C_ + cof) = make_float2(acc[mm][nf][0], acc[mm][nf][1]);
                *(float2*)(g_y + r_hi * C_ + cof) = make_float2(acc[mm][nf][2], acc[mm][nf][3]);
                ssl += acc[mm][nf][0] * acc[mm][nf][0] + acc[mm][nf][1] * acc[mm][nf][1];
                ssh += acc[mm][nf][2] * acc[mm][nf][2] + acc[mm][nf][3] * acc[mm][nf][3];
            }
            ssl += __shfl_xor_sync(0xffffffffu, ssl, 1);
            ssl += __shfl_xor_sync(0xffffffffu, ssl, 2);
            ssh += __shfl_xor_sync(0xffffffffu, ssh, 1);
            ssh += __shfl_xor_sync(0xffffffffu, ssh, 2);
            if ((lane & 3) == 0) {
                sm_ss[wm * 32 + mm * 16 + qrow][wn]     = ssl;
                sm_ss[wm * 32 + mm * 16 + qrow + 8][wn] = ssh;
            }
        }
        __syncthreads();
        if (tid < 128)
            g_ssp[(size_t)(m0 + tid) * 2 + (n0 >> 7)] = sm_ss[tid][0] + sm_ss[tid][1];
    } else {
#pragma unroll
        for (int mm = 0; mm < 2; mm++) {
            size_t r_lo = (size_t)(m0 + wm * 32 + mm * 16 + qrow);
            size_t r_hi = r_lo + 8;
            float irm_lo = g_invrms[r_lo];
            float irm_hi = g_invrms[r_hi];
#pragma unroll
            for (int nf = 0; nf < 8; nf++) {
                int cof = n0 + wn * 64 + nf * 8 + qcol;
                *(float2*)(fout + r_lo * C_ + cof) =
                    make_float2(acc[mm][nf][0] * irm_lo, acc[mm][nf][1] * irm_lo);
                *(float2*)(fout + r_hi * C_ + cof) =
                    make_float2(acc[mm][nf][2] * irm_hi, acc[mm][nf][3] * irm_hi);
            }
        }
    }
#undef LD_A
#undef LD_B
#undef ST_A
#undef MMA_CHUNK
}

// ---------------- K4: k GEMM + fused elu/L2norm + mk/mbk reductions, pipelined ----------------
__global__ void __launch_bounds__(256, 2)
gemm_k_kernel(const float* __restrict__ Xfp)
{
    extern __shared__ char smem[];
    const u32 sb = smem_u32(smem);
    const int tid = threadIdx.x, wid = tid >> 5, lane = tid & 31;
    const int m0 = blockIdx.y * 128;
    const int n0 = (int)blockIdx.x * 128;
    const __nv_bfloat16* Bh = g_wsh[0];
    const __nv_bfloat16* Bl = g_wsl[0];

    const int wm = wid & 3, wn = wid >> 2;
    const int rA = (lane & 7) + ((lane >> 3) & 1) * 8, cAx = (lane >> 4) & 1;
    const int rB = (lane & 7) + ((lane >> 4) & 1) * 8, cBx = (lane >> 3) & 1;

    float acc[2][8][4];
#pragma unroll
    for (int i = 0; i < 2; i++)
#pragma unroll
        for (int j = 0; j < 8; j++)
#pragma unroll
            for (int t = 0; t < 4; t++) acc[i][j][t] = 0.f;

    const int lr = tid >> 1, q = tid & 1;
    const size_t arow = (size_t)(m0 + lr) * C_ + q * 16;
    const size_t brow = (size_t)(n0 + lr) * C_;
    float fr[16];

#define LD_A(c) do { \
    const float4* _p = (const float4*)(Xfp + arow + (c) * 32); \
    *(float4*)(fr)      = _p[0]; *(float4*)(fr + 4)  = _p[1]; \
    *(float4*)(fr + 8)  = _p[2]; *(float4*)(fr + 12) = _p[3]; \
} while (0)

#define LD_B(c, ob) do { \
    _Pragma("unroll") \
    for (int _i = 0; _i < 2; _i++) { \
        int _cg = q * 2 + _i; \
        u32 _row = (ob) + (u32)lr * 128; \
        CP_ASYNC16(sb + _row + (u32)((_cg ^ (lr & 7)) << 4), \
                   (const void*)(Bh + brow + (c) * 32 + _cg * 8)); \
        CP_ASYNC16(sb + _row + (u32)(((_cg + 4) ^ (lr & 7)) << 4), \
                   (const void*)(Bl + brow + (c) * 32 + _cg * 8)); \
    } \
    CP_COMMIT(); \
} while (0)

#define ST_A(c, oa) do { \
    u32 _hv[8], _lv[8]; \
    _Pragma("unroll") \
    for (int _t = 0; _t < 8; _t++) split2(fr[2 * _t], fr[2 * _t + 1], _hv[_t], _lv[_t]); \
    u32 _base = (oa) + (u32)lr * 128; \
    int _c0 = q * 2, _c1 = q * 2 + 1; \
    *(uint4*)(smem + _base + ((_c0 ^ (lr & 7)) << 4))       = make_uint4(_hv[0], _hv[1], _hv[2], _hv[3]); \
    *(uint4*)(smem + _base + ((_c1 ^ (lr & 7)) << 4))       = make_uint4(_hv[4], _hv[5], _hv[6], _hv[7]); \
    *(uint4*)(smem + _base + (((_c0 + 4) ^ (lr & 7)) << 4)) = make_uint4(_lv[0], _lv[1], _lv[2], _lv[3]); \
    *(uint4*)(smem + _base + (((_c1 + 4) ^ (lr & 7)) << 4)) = make_uint4(_lv[4], _lv[5], _lv[6], _lv[7]); \
} while (0)

#define MMA_CHUNK(s) do { \
    u32 _oa = (u32)(s) * 32768, _obm = _oa + 16384; \
    _Pragma("unroll") \
    for (int ks = 0; ks < 2; ks++) { \
        u32 ah[2][4], al[2][4]; \
        _Pragma("unroll") \
        for (int ms = 0; ms < 2; ms++) { \
            int r = wm * 32 + ms * 16 + rA; \
            u32 rowb = _oa + (u32)r * 128; \
            ldmx4(ah[ms], sb + rowb + (u32)((((2 * ks + cAx)) ^ (r & 7)) << 4)); \
            ldmx4(al[ms], sb + rowb + (u32)((((2 * ks + cAx) + 4) ^ (r & 7)) << 4)); \
        } \
        _Pragma("unroll") \
        for (int nh = 0; nh < 4; nh++) { \
            int n = wn * 64 + nh * 16 + rB; \
            u32 rowbB = _obm + (u32)n * 128; \
            u32 bhf[4], blf[4]; \
            ldmx4(bhf, sb + rowbB + (u32)((((2 * ks + cBx)) ^ (n & 7)) << 4)); \
            ldmx4(blf, sb + rowbB + (u32)((((2 * ks + cBx) + 4) ^ (n & 7)) << 4)); \
            mma_bf16(acc[0][nh * 2],     ah[0], bhf[0], bhf[1]); \
            mma_bf16(acc[1][nh * 2],     ah[1], bhf[0], bhf[1]); \
            mma_bf16(acc[0][nh * 2 + 1], ah[0], bhf[2], bhf[3]); \
            mma_bf16(acc[1][nh * 2 + 1], ah[1], bhf[2], bhf[3]); \
            mma_bf16(acc[0][nh * 2],     al[0], bhf[0], bhf[1]); \
            mma_bf16(acc[1][nh * 2],     al[1], bhf[0], bhf[1]); \
            mma_bf16(acc[0][nh * 2 + 1], al[0], bhf[2], bhf[3]); \
            mma_bf16(acc[1][nh * 2 + 1], al[1], bhf[2], bhf[3]); \
            mma_bf16(acc[0][nh * 2],     ah[0], blf[0], blf[1]); \
            mma_bf16(acc[1][nh * 2],     ah[1], blf[0], blf[1]); \
            mma_bf16(acc[0][nh * 2 + 1], ah[0], blf[2], blf[3]); \
            mma_bf16(acc[1][nh * 2 + 1], ah[1], blf[2], blf[3]); \
        } \
    } \
} while (0)

    LD_A(0);
    LD_B(0, 16384u);
    ST_A(0, 0u);
    CP_WAIT0();
    __syncthreads();

#pragma unroll
    for (int c = 0; c < 8; c++) {
        if (c < 7) { LD_A(c + 1); LD_B(c + 1, (u32)(((c + 1) & 1) * 32768 + 16384)); }
        MMA_CHUNK(c & 1);
        if (c < 7) {
            ST_A(c + 1, (u32)(((c + 1) & 1) * 32768));
            CP_WAIT0();
            __syncthreads();
        }
    }

    // ---- epilogue: elu+1, per-head L2 norm, reduce mk & beta-weighted mbk over rows ----
    const int qrow = lane >> 2, qcol = (lane & 3) * 2;
    const int head = (n0 >> 6) + wn;
    const int bhh = (m0 >> 12) * H_ + head;
    float mk0[8], mk1[8], mbk0[8], mbk1[8];
#pragma unroll
    for (int nf = 0; nf < 8; nf++) { mk0[nf] = mk1[nf] = mbk0[nf] = mbk1[nf] = 0.f; }

#pragma unroll
    for (int mm = 0; mm < 2; mm++) {
        float ssl = 0.f, ssh = 0.f;
#pragma unroll
        for (int nf = 0; nf < 8; nf++) {
            float e0 = eluf(acc[mm][nf][0]); acc[mm][nf][0] = e0; ssl += e0 * e0;
            float e1 = eluf(acc[mm][nf][1]); acc[mm][nf][1] = e1; ssl += e1 * e1;
            float e2 = eluf(acc[mm][nf][2]); acc[mm][nf][2] = e2; ssh += e2 * e2;
            float e3 = eluf(acc[mm][nf][3]); acc[mm][nf][3] = e3; ssh += e3 * e3;
        }
        ssl += __shfl_xor_sync(0xffffffffu, ssl, 1);
        ssl += __shfl_xor_sync(0xffffffffu, ssl, 2);
        ssh += __shfl_xor_sync(0xffffffffu, ssh, 1);
        ssh += __shfl_xor_sync(0xffffffffu, ssh, 2);
        float invl = 1.f / (sqrtf(ssl) + 1e-6f);
        float invh = 1.f / (sqrtf(ssh) + 1e-6f);
        int nrow = (m0 & (N_ - 1)) + wm * 32 + mm * 16 + qrow;
        float b_lo = g_beta[bhh * N_ + nrow];
        float b_hi = g_beta[bhh * N_ + nrow + 8];
#pragma unroll
        for (int nf = 0; nf < 8; nf++) {
            float v0 = acc[mm][nf][0] * invl, v1 = acc[mm][nf][1] * invl;
            float v2 = acc[mm][nf][2] * invh, v3 = acc[mm][nf][3] * invh;
            mk0[nf]  += v0 + v2;
            mk1[nf]  += v1 + v3;
            mbk0[nf] += b_lo * v0 + b_hi * v2;
            mbk1[nf] += b_lo * v1 + b_hi * v3;
        }
    }
#pragma unroll
    for (int o = 4; o <= 16; o <<= 1) {
#pragma unroll
        for (int nf = 0; nf < 8; nf++) {
            mk0[nf]  += __shfl_xor_sync(0xffffffffu, mk0[nf], o);
            mk1[nf]  += __shfl_xor_sync(0xffffffffu, mk1[nf], o);
            mbk0[nf] += __shfl_xor_sync(0xffffffffu, mbk0[nf], o);
            mbk1[nf] += __shfl_xor_sync(0xffffffffu, mbk1[nf], o);
        }
    }
    __syncthreads();
    float* red = (float*)smem;   // reuse staging smem: [0,512) mk, [512,1024) mbk
    if (lane < 4) {
#pragma unroll
        for (int nf = 0; nf < 8; nf++) {
            red[wid * 64 + nf * 8 + lane * 2]           = mk0[nf];
            red[wid * 64 + nf * 8 + lane * 2 + 1]       = mk1[nf];
            red[512 + wid * 64 + nf * 8 + lane * 2]     = mbk0[nf];
            red[512 + wid * 64 + nf * 8 + lane * 2 + 1] = mbk1[nf];
        }
    }
    __syncthreads();
    if (tid < 128) {
        int hh = tid >> 6, col = tid & 63;
        float s = red[(hh * 4 + 0) * 64 + col] + red[(hh * 4 + 1) * 64 + col]
                + red[(hh * 4 + 2) * 64 + col] + red[(hh * 4 + 3) * 64 + col];
        g_mkp[(size_t)blockIdx.y * 256 + n0 + hh * 64 + col] = s;
    } else {
        int t2 = tid - 128, hh = t2 >> 6, col = t2 & 63;
        float s = red[512 + (hh * 4 + 0) * 64 + col] + red[512 + (hh * 4 + 1) * 64 + col]
                + red[512 + (hh * 4 + 2) * 64 + col] + red[512 + (hh * 4 + 3) * 64 + col];
        g_mbkp[(size_t)blockIdx.y * 256 + n0 + hh * 64 + col] = s;
    }
#undef LD_A
#undef LD_B
#undef ST_A
#undef MMA_CHUNK
}

// ---------------- K3: xbar partials = sum_n beta*x over 64-row chunks ----------------
__global__ void __launch_bounds__(256)
xbar_kernel(const float* __restrict__ x)
{
    __shared__ float sbeta[64][4];
    int blk = blockIdx.x, m0 = blk * 64, tid = threadIdx.x;
    {
        int r = tid >> 2, h = tid & 3;
        int m = m0 + r, b = m >> 12, n = m & (N_ - 1);
        sbeta[r][h] = g_beta[(b * H_ + h) * N_ + n];
    }
    __syncthreads();
    float a0 = 0.f, a1 = 0.f, a2 = 0.f, a3 = 0.f;
    for (int r = 0; r < 64; r++) {
        float xv = x[(size_t)(m0 + r) * C_ + tid];
        a0 += xv * sbeta[r][0];
        a1 += xv * sbeta[r][1];
        a2 += xv * sbeta[r][2];
        a3 += xv * sbeta[r][3];
    }
    g_xbp[((size_t)blk * 4 + 0) * 256 + tid] = a0;
    g_xbp[((size_t)blk * 4 + 1) * 256 + tid] = a1;
    g_xbp[((size_t)blk * 4 + 2) * 256 + tid] = a2;
    g_xbp[((size_t)blk * 4 + 3) * 256 + tid] = a3;
}

// ---------------- K5a: invrms ----------------
__global__ void __launch_bounds__(256)
invrms_kernel()
{
    int m = blockIdx.x * 256 + threadIdx.x;
    float s = g_ssp[(size_t)m * 2] + g_ssp[(size_t)m * 2 + 1];
    g_invrms[m] = rsqrtf(s * (1.f / (float)C_) + 1e-6f);
}

// ---------------- K5b: finalize werr/wkey ----------------
__global__ void __launch_bounds__(256)
final_kernel(const float* __restrict__ S, const float* __restrict__ Wv)
{
    __shared__ float s_mk[64], s_mbk[64], s_xbar[256];
    int bh = blockIdx.x, b = bh >> 2, h = bh & 3, tid = threadIdx.x;
    {
        float a = 0.f;
        for (int t = 0; t < 64; t++)
            a += g_xbp[((size_t)(b * 64 + t) * 4 + h) * 256 + tid];
        s_xbar[tid] = a * (1.f / (float)N_);
    }
    if (tid < 64) {
        float s = 0.f;
        for (int t = 0; t < 32; t++)
            s += g_mkp[(size_t)(b * 32 + t) * 256 + h * 64 + tid];
        s_mk[tid] = s * (1.f / (float)N_);
    } else if (tid < 128) {
        int c = tid - 64;
        float s = 0.f;
        for (int t = 0; t < 32; t++)
            s += g_mbkp[(size_t)(b * 32 + t) * 256 + h * 64 + c];
        s_mbk[c] = s * (1.f / (float)N_);
    }
    __syncthreads();
    if (tid < 64) {
        int i = tid;
        const float* wv = Wv + (size_t)(h * 64 + i) * 256;
        float mbv = 0.f;
        for (int c = 0; c < 256; c++) mbv += wv[c] * s_xbar[c];
        const float* sd = S + (size_t)bh * 4096 + (size_t)i * 64;
        float sp = 0.f;
        for (int j = 0; j < 64; j++) sp += 0.95f * sd[j] * s_mbk[j];
        g_werr[bh * 64 + i] = mbv - sp;
        g_wkey[bh * 64 + i] = s_mk[i];
    }
}

// ---------------- K5c: S_new ----------------
__global__ void __launch_bounds__(256)
snew_kernel(const float* __restrict__ S, float* __restrict__ out_s)
{
    int idx = blockIdx.x * 256 + threadIdx.x;
    int bh = idx >> 12;
    int i = (idx >> 6) & 63;
    int j = idx & 63;
    float val = S[idx] * 0.95f + g_werr[bh * 64 + i] * g_wkey[bh * 64 + j];
    out_s[idx] = fminf(fmaxf(val, -10.f), 10.f);
}

// ---------------- launcher ----------------
extern "C" void kernel_launch(void* const* d_in, const int* in_sizes, int n_in,
                              void* d_out, int out_size)
{
    const float* x    = (const float*)d_in[0];
    const float* S    = (const float*)d_in[1];
    const float* Wq   = (const float*)d_in[2];
    const float* Wk   = (const float*)d_in[3];
    const float* Wv   = (const float*)d_in[4];
    const float* Wb   = (const float*)d_in[5];
    const float* Wo   = (const float*)d_in[6];
    const float* grms = (const float*)d_in[7];
    float* out = (float*)d_out;

    static int init = 0;
    static cudaStream_t s2;
    static cudaEvent_t eW, eB;
    if (!init) {
        cudaFuncSetAttribute(gemm_proj_kernel, cudaFuncAttributeMaxDynamicSharedMemorySize, 65536);
        cudaFuncSetAttribute(gemm_k_kernel, cudaFuncAttributeMaxDynamicSharedMemorySize, 65536);
        cudaFuncSetAttribute(wprime_kernel, cudaFuncAttributeMaxDynamicSharedMemorySize, 81920);
        cudaStreamCreateWithFlags(&s2, cudaStreamNonBlocking);
        cudaEventCreateWithFlags(&eW, cudaEventDisableTiming);
        cudaEventCreateWithFlags(&eB, cudaEventDisableTiming);
        init = 1;
    }

    // L1 (main): weight conversion (Wk, Wog)
    convw_kernel<<<512, 256>>>(Wk, Wo, grms);
    cudaEventRecord(eW, 0);

    // L2 (s2): beta — fully independent, starts immediately
    beta_kernel<<<8192, 256, 0, s2>>>(x, Wb);

    // L3 (main): W' = Sd@Wq
    wprime_kernel<<<64, 256, 81920>>>(S, Wq);

    // L4 (s2): k GEMM — needs beta (s2 order) + Wk (eW). Runs CONCURRENT with proj0.
    cudaStreamWaitEvent(s2, eW, 0);
    gemm_k_kernel<<<dim3(2, 512), 256, 65536, s2>>>(x);

    // L5 (main): y = x @ W'^T (+ ss partials)
    gemm_proj_kernel<<<dim3(2, 512), 256, 65536>>>(0, x, nullptr);

    // s2 tail: xbar, final, snew (all hidden under main-stream GEMMs)
    xbar_kernel<<<1024, 256, 0, s2>>>(x);
    final_kernel<<<64, 256, 0, s2>>>(S, Wv);
    if (out_size >= OUT_MAIN + OUT_S) {
        snew_kernel<<<OUT_S / 256, 256, 0, s2>>>(S, out + OUT_MAIN);
    }
    cudaEventRecord(eB, s2);

    // main: invrms + out-projection
    invrms_kernel<<<M_ / 256, 256>>>();
    gemm_proj_kernel<<<dim3(2, 512), 256, 65536>>>(1, x, out);

    // join
    cudaStreamWaitEvent(0, eB, 0);
}

// round 12
// speedup vs baseline: 1.9974x; 1.0443x over previous
#include <cuda_runtime.h>
#include <cuda_bf16.h>
#include <math.h>

// ---------------- constants ----------------
#define B_ 16
#define N_ 4096
#define C_ 256
#define H_ 4
#define D_ 64
#define M_ (B_ * N_)              // 65536
#define OUT_MAIN (M_ * C_)        // 16777216
#define OUT_S (B_ * H_ * D_ * D_) // 262144

typedef unsigned int u32;

// ---------------- device scratch ----------------
__device__ __nv_bfloat16 g_wph[B_ * C_ * C_], g_wpl[B_ * C_ * C_]; // W' = Sd@Wq per batch (split)
__device__ __nv_bfloat16 g_wsh[2][C_ * C_], g_wsl[2][C_ * C_];     // Wk, Wo*g (split)
__device__ float g_y[M_ * C_];
__device__ float g_beta[B_ * H_ * N_];
__device__ float g_ssp[M_ * 2];
__device__ float g_invrms[M_];
__device__ float g_mkp[512 * 256], g_mbkp[512 * 256];   // per-mtile k partials
__device__ float g_xbp[1024 * H_ * C_];                  // per-64row beta*x partials
__device__ float g_werr[64 * 64], g_wkey[64 * 64];

// ---------------- helpers ----------------
__device__ __forceinline__ u32 smem_u32(const void* p) {
    u32 a;
    asm("{ .reg .u64 t; cvta.to.shared.u64 t, %1; cvt.u32.u64 %0, t; }" : "=r"(a) : "l"(p));
    return a;
}
__device__ __forceinline__ void ldmx4(u32* r, u32 addr) {
    asm volatile("ldmatrix.sync.aligned.m8n8.x4.shared.b16 {%0,%1,%2,%3}, [%4];"
                 : "=r"(r[0]), "=r"(r[1]), "=r"(r[2]), "=r"(r[3]) : "r"(addr));
}
__device__ __forceinline__ void mma_bf16(float* d, const u32* a, u32 b0, u32 b1) {
    asm volatile("mma.sync.aligned.m16n8k16.row.col.f32.bf16.bf16.f32 "
                 "{%0,%1,%2,%3}, {%4,%5,%6,%7}, {%8,%9}, {%0,%1,%2,%3};"
                 : "+f"(d[0]), "+f"(d[1]), "+f"(d[2]), "+f"(d[3])
                 : "r"(a[0]), "r"(a[1]), "r"(a[2]), "r"(a[3]), "r"(b0), "r"(b1));
}
__device__ __forceinline__ u32 prmt16(u32 a, u32 b) {
    u32 r;
    asm("prmt.b32 %0, %1, %2, 0x7632;" : "=r"(r) : "r"(a), "r"(b));
    return r;
}
// truncation split: h = top16(f), l = top16(f - as_float(top16(f)))
__device__ __forceinline__ void split2(float f0, float f1, u32& h01, u32& l01) {
    u32 b0 = __float_as_uint(f0), b1 = __float_as_uint(f1);
    h01 = prmt16(b0, b1);
    float lo0 = f0 - __uint_as_float(b0 & 0xFFFF0000u);
    float lo1 = f1 - __uint_as_float(b1 & 0xFFFF0000u);
    l01 = prmt16(__float_as_uint(lo0), __float_as_uint(lo1));
}
// RN bf16 pair pack: low half = f0, high half = f1
__device__ __forceinline__ u32 bf16pair(float f0, float f1) {
    u32 r;
    asm("cvt.rn.bf16x2.f32 %0, %1, %2;" : "=r"(r) : "f"(f1), "f"(f0));
    return r;
}
__device__ __forceinline__ float eluf(float v) {
    return (v > 0.f) ? (v + 1.f) : expf(v);
}
#define CP_ASYNC16(dst, src) \
    asm volatile("cp.async.cg.shared.global [%0], [%1], 16;" :: "r"(dst), "l"(src))
#define CP_COMMIT() asm volatile("cp.async.commit_group;")
#define CP_WAIT0()  asm volatile("cp.async.wait_group 0;" ::: "memory")

// ---------------- K0: Wk, Wo*grms -> split bf16 ----------------
__global__ void __launch_bounds__(256) convw_kernel(
    const float* __restrict__ Wk, const float* __restrict__ Wo,
    const float* __restrict__ grms)
{
    int gid = blockIdx.x * 256 + threadIdx.x;   // < 131072
    int sel = gid >> 16, idx = gid & 65535;
    float v = sel ? (Wo[idx] * grms[idx & 255]) : Wk[idx];
    __nv_bfloat16 h = __float2bfloat16(v);
    g_wsh[sel][idx] = h;
    g_wsl[sel][idx] = __float2bfloat16(v - __bfloat162float(h));
}

// ---------------- K0b: beta = sigmoid(x @ Wb^T), warp per row ----------------
__global__ void __launch_bounds__(256)
beta_kernel(const float* __restrict__ x, const float* __restrict__ Wb)
{
    int warp = (blockIdx.x * 256 + threadIdx.x) >> 5;
    int lane = threadIdx.x & 31;
    int m = warp;
    float a0 = 0.f, a1 = 0.f, a2 = 0.f, a3 = 0.f;
#pragma unroll
    for (int cc = 0; cc < 8; cc++) {
        int c = cc * 32 + lane;
        float xv = x[(size_t)m * C_ + c];
        a0 += xv * Wb[c];
        a1 += xv * Wb[256 + c];
        a2 += xv * Wb[512 + c];
        a3 += xv * Wb[768 + c];
    }
#pragma unroll
    for (int o = 16; o; o >>= 1) {
        a0 += __shfl_down_sync(0xffffffffu, a0, o);
        a1 += __shfl_down_sync(0xffffffffu, a1, o);
        a2 += __shfl_down_sync(0xffffffffu, a2, o);
        a3 += __shfl_down_sync(0xffffffffu, a3, o);
    }
    if (lane == 0) {
        int bb = m >> 12, n = m & (N_ - 1);
        g_beta[(bb * H_ + 0) * N_ + n] = 1.f / (1.f + expf(-a0));
        g_beta[(bb * H_ + 1) * N_ + n] = 1.f / (1.f + expf(-a1));
        g_beta[(bb * H_ + 2) * N_ + n] = 1.f / (1.f + expf(-a2));
        g_beta[(bb * H_ + 3) * N_ + n] = 1.f / (1.f + expf(-a3));
    }
}

// ---------------- K1: W'[b] = (0.95*S[b,h]) @ Wq_h, split bf16 ----------------
__global__ void __launch_bounds__(256)
wprime_kernel(const float* __restrict__ S, const float* __restrict__ Wq)
{
    extern __shared__ float sm[];        // sSdT[4096] + sWq[64*256] = 80KB
    float* sSdT = sm;
    float* sWq = sm + 4096;
    int bh = blockIdx.x, b = bh >> 2, h = bh & 3, tid = threadIdx.x;
    for (int t = tid; t < 4096; t += 256) {
        int i = t >> 6, j = t & 63;
        sSdT[j * 64 + i] = S[(size_t)bh * 4096 + t] * 0.95f;
    }
    for (int t = tid; t < 64 * 256; t += 256)
        sWq[t] = Wq[(size_t)(h * 64 + (t >> 8)) * 256 + (t & 255)];
    __syncthreads();
    int i = tid & 63, stripe = tid >> 6;
#pragma unroll 1
    for (int cc = 0; cc < 64; cc++) {
        int c = stripe * 64 + cc;
        float acc = 0.f;
#pragma unroll
        for (int j = 0; j < 64; j++)
            acc += sSdT[j * 64 + i] * sWq[j * 256 + c];
        __nv_bfloat16 hh = __float2bfloat16(acc);
        size_t o = (size_t)b * 65536 + (size_t)(h * 64 + i) * 256 + c;
        g_wph[o] = hh;
        g_wpl[o] = __float2bfloat16(acc - __bfloat162float(hh));
    }
}

// ============ pipelined GEMM bodies (K=32 chunks, double buffered) ============
// smem per stage s: A at s*32768 (16KB), B at s*32768+16384 (16KB)
// rows: 128 bytes = [h cols 0..31 | l cols 0..31], XOR-8 swizzle on 16B groups.

// ---------------- K2/K6: projection GEMM (3-pass split), 128x128 tiles ----------------
__global__ void __launch_bounds__(256, 2)
gemm_proj_kernel(int task, const float* __restrict__ Xfp, float* __restrict__ fout)
{
    extern __shared__ char smem[];
    __shared__ float sm_ss[128][2];
    const u32 sb = smem_u32(smem);
    const int tid = threadIdx.x, wid = tid >> 5, lane = tid & 31;
    const int m0 = blockIdx.y * 128;
    const int n0 = (int)blockIdx.x * 128;

    const float* Afp = (task == 0) ? Xfp : g_y;
    const __nv_bfloat16 *Bh, *Bl;
    if (task == 0) {
        int b = m0 >> 12;
        Bh = g_wph + (size_t)b * 65536;
        Bl = g_wpl + (size_t)b * 65536;
    } else {
        Bh = g_wsh[1]; Bl = g_wsl[1];
    }

    const int wm = wid & 3, wn = wid >> 2;
    const int rA = (lane & 7) + ((lane >> 3) & 1) * 8, cAx = (lane >> 4) & 1;
    const int rB = (lane & 7) + ((lane >> 4) & 1) * 8, cBx = (lane >> 3) & 1;

    float acc[2][8][4];
#pragma unroll
    for (int i = 0; i < 2; i++)
#pragma unroll
        for (int j = 0; j < 8; j++)
#pragma unroll
            for (int t = 0; t < 4; t++) acc[i][j][t] = 0.f;

    const int lr = tid >> 1, q = tid & 1;
    const size_t arow = (size_t)(m0 + lr) * C_ + q * 16;
    const size_t brow = (size_t)(n0 + lr) * C_;
    float fr[16];

#define LD_A(c) do { \
    const float4* _p = (const float4*)(Afp + arow + (c) * 32); \
    *(float4*)(fr)      = _p[0]; *(float4*)(fr + 4)  = _p[1]; \
    *(float4*)(fr + 8)  = _p[2]; *(float4*)(fr + 12) = _p[3]; \
} while (0)

#define LD_B(c, ob) do { \
    _Pragma("unroll") \
    for (int _i = 0; _i < 2; _i++) { \
        int _cg = q * 2 + _i; \
        u32 _row = (ob) + (u32)lr * 128; \
        CP_ASYNC16(sb + _row + (u32)((_cg ^ (lr & 7)) << 4), \
                   (const void*)(Bh + brow + (c) * 32 + _cg * 8)); \
        CP_ASYNC16(sb + _row + (u32)(((_cg + 4) ^ (lr & 7)) << 4), \
                   (const void*)(Bl + brow + (c) * 32 + _cg * 8)); \
    } \
    CP_COMMIT(); \
} while (0)

#define ST_A(c, oa) do { \
    u32 _hv[8], _lv[8]; \
    _Pragma("unroll") \
    for (int _t = 0; _t < 8; _t++) split2(fr[2 * _t], fr[2 * _t + 1], _hv[_t], _lv[_t]); \
    u32 _base = (oa) + (u32)lr * 128; \
    int _c0 = q * 2, _c1 = q * 2 + 1; \
    *(uint4*)(smem + _base + ((_c0 ^ (lr & 7)) << 4))       = make_uint4(_hv[0], _hv[1], _hv[2], _hv[3]); \
    *(uint4*)(smem + _base + ((_c1 ^ (lr & 7)) << 4))       = make_uint4(_hv[4], _hv[5], _hv[6], _hv[7]); \
    *(uint4*)(smem + _base + (((_c0 + 4) ^ (lr & 7)) << 4)) = make_uint4(_lv[0], _lv[1], _lv[2], _lv[3]); \
    *(uint4*)(smem + _base + (((_c1 + 4) ^ (lr & 7)) << 4)) = make_uint4(_lv[4], _lv[5], _lv[6], _lv[7]); \
} while (0)

#define MMA_CHUNK(s) do { \
    u32 _oa = (u32)(s) * 32768, _obm = _oa + 16384; \
    _Pragma("unroll") \
    for (int ks = 0; ks < 2; ks++) { \
        u32 ah[2][4], al[2][4]; \
        _Pragma("unroll") \
        for (int ms = 0; ms < 2; ms++) { \
            int r = wm * 32 + ms * 16 + rA; \
            u32 rowb = _oa + (u32)r * 128; \
            ldmx4(ah[ms], sb + rowb + (u32)((((2 * ks + cAx)) ^ (r & 7)) << 4)); \
            ldmx4(al[ms], sb + rowb + (u32)((((2 * ks + cAx) + 4) ^ (r & 7)) << 4)); \
        } \
        _Pragma("unroll") \
        for (int nh = 0; nh < 4; nh++) { \
            int n = wn * 64 + nh * 16 + rB; \
            u32 rowbB = _obm + (u32)n * 128; \
            u32 bhf[4], blf[4]; \
            ldmx4(bhf, sb + rowbB + (u32)((((2 * ks + cBx)) ^ (n & 7)) << 4)); \
            ldmx4(blf, sb + rowbB + (u32)((((2 * ks + cBx) + 4) ^ (n & 7)) << 4)); \
            mma_bf16(acc[0][nh * 2],     ah[0], bhf[0], bhf[1]); \
            mma_bf16(acc[1][nh * 2],     ah[1], bhf[0], bhf[1]); \
            mma_bf16(acc[0][nh * 2 + 1], ah[0], bhf[2], bhf[3]); \
            mma_bf16(acc[1][nh * 2 + 1], ah[1], bhf[2], bhf[3]); \
            mma_bf16(acc[0][nh * 2],     al[0], bhf[0], bhf[1]); \
            mma_bf16(acc[1][nh * 2],     al[1], bhf[0], bhf[1]); \
            mma_bf16(acc[0][nh * 2 + 1], al[0], bhf[2], bhf[3]); \
            mma_bf16(acc[1][nh * 2 + 1], al[1], bhf[2], bhf[3]); \
            mma_bf16(acc[0][nh * 2],     ah[0], blf[0], blf[1]); \
            mma_bf16(acc[1][nh * 2],     ah[1], blf[0], blf[1]); \
            mma_bf16(acc[0][nh * 2 + 1], ah[0], blf[2], blf[3]); \
            mma_bf16(acc[1][nh * 2 + 1], ah[1], blf[2], blf[3]); \
        } \
    } \
} while (0)

    LD_A(0);
    LD_B(0, 16384u);
    ST_A(0, 0u);
    CP_WAIT0();
    __syncthreads();

#pragma unroll
    for (int c = 0; c < 8; c++) {
        if (c < 7) { LD_A(c + 1); LD_B(c + 1, (u32)(((c + 1) & 1) * 32768 + 16384)); }
        MMA_CHUNK(c & 1);
        if (c < 7) {
            ST_A(c + 1, (u32)(((c + 1) & 1) * 32768));
            CP_WAIT0();
            __syncthreads();
        }
    }

    // ---- epilogue ----
    const int qrow = lane >> 2, qcol = (lane & 3) * 2;
    if (task == 0) {
#pragma unroll
        for (int mm = 0; mm < 2; mm++) {
            size_t r_lo = (size_t)(m0 + wm * 32 + mm * 16 + qrow);
            size_t r_hi = r_lo + 8;
            float ssl = 0.f, ssh = 0.f;
#pragma unroll
            for (int nf = 0; nf < 8; nf++) {
                int cof = n0 + wn * 64 + nf * 8 + qcol;
                *(float2*)(g_y + r_lo * C_ + cof) = make_float2(acc[mm][nf][0], acc[mm][nf][1]);
                *(float2*)(g_y + r_hi * C_ + cof) = make_float2(acc[mm][nf][2], acc[mm][nf][3]);
                ssl += acc[mm][nf][0] * acc[mm][nf][0] + acc[mm][nf][1] * acc[mm][nf][1];
                ssh += acc[mm][nf][2] * acc[mm][nf][2] + acc[mm][nf][3] * acc[mm][nf][3];
            }
            ssl += __shfl_xor_sync(0xffffffffu, ssl, 1);
            ssl += __shfl_xor_sync(0xffffffffu, ssl, 2);
            ssh += __shfl_xor_sync(0xffffffffu, ssh, 1);
            ssh += __shfl_xor_sync(0xffffffffu, ssh, 2);
            if ((lane & 3) == 0) {
                sm_ss[wm * 32 + mm * 16 + qrow][wn]     = ssl;
                sm_ss[wm * 32 + mm * 16 + qrow + 8][wn] = ssh;
            }
        }
        __syncthreads();
        if (tid < 128)
            g_ssp[(size_t)(m0 + tid) * 2 + (n0 >> 7)] = sm_ss[tid][0] + sm_ss[tid][1];
    } else {
#pragma unroll
        for (int mm = 0; mm < 2; mm++) {
            size_t r_lo = (size_t)(m0 + wm * 32 + mm * 16 + qrow);
            size_t r_hi = r_lo + 8;
            float irm_lo = g_invrms[r_lo];
            float irm_hi = g_invrms[r_hi];
#pragma unroll
            for (int nf = 0; nf < 8; nf++) {
                int cof = n0 + wn * 64 + nf * 8 + qcol;
                *(float2*)(fout + r_lo * C_ + cof) =
                    make_float2(acc[mm][nf][0] * irm_lo, acc[mm][nf][1] * irm_lo);
                *(float2*)(fout + r_hi * C_ + cof) =
                    make_float2(acc[mm][nf][2] * irm_hi, acc[mm][nf][3] * irm_hi);
            }
        }
    }
#undef LD_A
#undef LD_B
#undef ST_A
#undef MMA_CHUNK
}

// ---------------- K4: k GEMM, SINGLE-PASS bf16 (k only feeds means) ----------------
__global__ void __launch_bounds__(256, 2)
gemm_k_kernel(const float* __restrict__ Xfp)
{
    extern __shared__ char smem[];
    const u32 sb = smem_u32(smem);
    const int tid = threadIdx.x, wid = tid >> 5, lane = tid & 31;
    const int m0 = blockIdx.y * 128;
    const int n0 = (int)blockIdx.x * 128;
    const __nv_bfloat16* Bh = g_wsh[0];

    const int wm = wid & 3, wn = wid >> 2;
    const int rA = (lane & 7) + ((lane >> 3) & 1) * 8, cAx = (lane >> 4) & 1;
    const int rB = (lane & 7) + ((lane >> 4) & 1) * 8, cBx = (lane >> 3) & 1;

    float acc[2][8][4];
#pragma unroll
    for (int i = 0; i < 2; i++)
#pragma unroll
        for (int j = 0; j < 8; j++)
#pragma unroll
            for (int t = 0; t < 4; t++) acc[i][j][t] = 0.f;

    const int lr = tid >> 1, q = tid & 1;
    const size_t arow = (size_t)(m0 + lr) * C_ + q * 16;
    const size_t brow = (size_t)(n0 + lr) * C_;
    float fr[16];

#define LD_A(c) do { \
    const float4* _p = (const float4*)(Xfp + arow + (c) * 32); \
    *(float4*)(fr)      = _p[0]; *(float4*)(fr + 4)  = _p[1]; \
    *(float4*)(fr + 8)  = _p[2]; *(float4*)(fr + 12) = _p[3]; \
} while (0)

#define LD_B(c, ob) do { \
    _Pragma("unroll") \
    for (int _i = 0; _i < 2; _i++) { \
        int _cg = q * 2 + _i; \
        u32 _row = (ob) + (u32)lr * 128; \
        CP_ASYNC16(sb + _row + (u32)((_cg ^ (lr & 7)) << 4), \
                   (const void*)(Bh + brow + (c) * 32 + _cg * 8)); \
    } \
    CP_COMMIT(); \
} while (0)

#define ST_A(c, oa) do { \
    u32 _hv[8]; \
    _Pragma("unroll") \
    for (int _t = 0; _t < 8; _t++) _hv[_t] = bf16pair(fr[2 * _t], fr[2 * _t + 1]); \
    u32 _base = (oa) + (u32)lr * 128; \
    int _c0 = q * 2, _c1 = q * 2 + 1; \
    *(uint4*)(smem + _base + ((_c0 ^ (lr & 7)) << 4)) = make_uint4(_hv[0], _hv[1], _hv[2], _hv[3]); \
    *(uint4*)(smem + _base + ((_c1 ^ (lr & 7)) << 4)) = make_uint4(_hv[4], _hv[5], _hv[6], _hv[7]); \
} while (0)

#define MMA_CHUNK(s) do { \
    u32 _oa = (u32)(s) * 32768, _obm = _oa + 16384; \
    _Pragma("unroll") \
    for (int ks = 0; ks < 2; ks++) { \
        u32 ah[2][4]; \
        _Pragma("unroll") \
        for (int ms = 0; ms < 2; ms++) { \
            int r = wm * 32 + ms * 16 + rA; \
            u32 rowb = _oa + (u32)r * 128; \
            ldmx4(ah[ms], sb + rowb + (u32)((((2 * ks + cAx)) ^ (r & 7)) << 4)); \
        } \
        _Pragma("unroll") \
        for (int nh = 0; nh < 4; nh++) { \
            int n = wn * 64 + nh * 16 + rB; \
            u32 rowbB = _obm + (u32)n * 128; \
            u32 bhf[4]; \
            ldmx4(bhf, sb + rowbB + (u32)((((2 * ks + cBx)) ^ (n & 7)) << 4)); \
            mma_bf16(acc[0][nh * 2],     ah[0], bhf[0], bhf[1]); \
            mma_bf16(acc[1][nh * 2],     ah[1], bhf[0], bhf[1]); \
            mma_bf16(acc[0][nh * 2 + 1], ah[0], bhf[2], bhf[3]); \
            mma_bf16(acc[1][nh * 2 + 1], ah[1], bhf[2], bhf[3]); \
        } \
    } \
} while (0)

    LD_A(0);
    LD_B(0, 16384u);
    ST_A(0, 0u);
    CP_WAIT0();
    __syncthreads();

#pragma unroll
    for (int c = 0; c < 8; c++) {
        if (c < 7) { LD_A(c + 1); LD_B(c + 1, (u32)(((c + 1) & 1) * 32768 + 16384)); }
        MMA_CHUNK(c & 1);
        if (c < 7) {
            ST_A(c + 1, (u32)(((c + 1) & 1) * 32768));
            CP_WAIT0();
            __syncthreads();
        }
    }

    // ---- epilogue: elu+1, per-head L2 norm, reduce mk & beta-weighted mbk ----
    const int qrow = lane >> 2, qcol = (lane & 3) * 2;
    const int head = (n0 >> 6) + wn;
    const int bhh = (m0 >> 12) * H_ + head;
    float mk0[8], mk1[8], mbk0[8], mbk1[8];
#pragma unroll
    for (int nf = 0; nf < 8; nf++) { mk0[nf] = mk1[nf] = mbk0[nf] = mbk1[nf] = 0.f; }

#pragma unroll
    for (int mm = 0; mm < 2; mm++) {
        float ssl = 0.f, ssh = 0.f;
#pragma unroll
        for (int nf = 0; nf < 8; nf++) {
            float e0 = eluf(acc[mm][nf][0]); acc[mm][nf][0] = e0; ssl += e0 * e0;
            float e1 = eluf(acc[mm][nf][1]); acc[mm][nf][1] = e1; ssl += e1 * e1;
            float e2 = eluf(acc[mm][nf][2]); acc[mm][nf][2] = e2; ssh += e2 * e2;
            float e3 = eluf(acc[mm][nf][3]); acc[mm][nf][3] = e3; ssh += e3 * e3;
        }
        ssl += __shfl_xor_sync(0xffffffffu, ssl, 1);
        ssl += __shfl_xor_sync(0xffffffffu, ssl, 2);
        ssh += __shfl_xor_sync(0xffffffffu, ssh, 1);
        ssh += __shfl_xor_sync(0xffffffffu, ssh, 2);
        float invl = 1.f / (sqrtf(ssl) + 1e-6f);
        float invh = 1.f / (sqrtf(ssh) + 1e-6f);
        int nrow = (m0 & (N_ - 1)) + wm * 32 + mm * 16 + qrow;
        float b_lo = g_beta[bhh * N_ + nrow];
        float b_hi = g_beta[bhh * N_ + nrow + 8];
#pragma unroll
        for (int nf = 0; nf < 8; nf++) {
            float v0 = acc[mm][nf][0] * invl, v1 = acc[mm][nf][1] * invl;
            float v2 = acc[mm][nf][2] * invh, v3 = acc[mm][nf][3] * invh;
            mk0[nf]  += v0 + v2;
            mk1[nf]  += v1 + v3;
            mbk0[nf] += b_lo * v0 + b_hi * v2;
            mbk1[nf] += b_lo * v1 + b_hi * v3;
        }
    }
#pragma unroll
    for (int o = 4; o <= 16; o <<= 1) {
#pragma unroll
        for (int nf = 0; nf < 8; nf++) {
            mk0[nf]  += __shfl_xor_sync(0xffffffffu, mk0[nf], o);
            mk1[nf]  += __shfl_xor_sync(0xffffffffu, mk1[nf], o);
            mbk0[nf] += __shfl_xor_sync(0xffffffffu, mbk0[nf], o);
            mbk1[nf] += __shfl_xor_sync(0xffffffffu, mbk1[nf], o);
        }
    }
    __syncthreads();
    float* red = (float*)smem;   // reuse staging smem: [0,512) mk, [512,1024) mbk
    if (lane < 4) {
#pragma unroll
        for (int nf = 0; nf < 8; nf++) {
            red[wid * 64 + nf * 8 + lane * 2]           = mk0[nf];
            red[wid * 64 + nf * 8 + lane * 2 + 1]       = mk1[nf];
            red[512 + wid * 64 + nf * 8 + lane * 2]     = mbk0[nf];
            red[512 + wid * 64 + nf * 8 + lane * 2 + 1] = mbk1[nf];
        }
    }
    __syncthreads();
    if (tid < 128) {
        int hh = tid >> 6, col = tid & 63;
        float s = red[(hh * 4 + 0) * 64 + col] + red[(hh * 4 + 1) * 64 + col]
                + red[(hh * 4 + 2) * 64 + col] + red[(hh * 4 + 3) * 64 + col];
        g_mkp[(size_t)blockIdx.y * 256 + n0 + hh * 64 + col] = s;
    } else {
        int t2 = tid - 128, hh = t2 >> 6, col = t2 & 63;
        float s = red[512 + (hh * 4 + 0) * 64 + col] + red[512 + (hh * 4 + 1) * 64 + col]
                + red[512 + (hh * 4 + 2) * 64 + col] + red[512 + (hh * 4 + 3) * 64 + col];
        g_mbkp[(size_t)blockIdx.y * 256 + n0 + hh * 64 + col] = s;
    }
#undef LD_A
#undef LD_B
#undef ST_A
#undef MMA_CHUNK
}

// ---------------- K3: xbar partials = sum_n beta*x over 64-row chunks ----------------
__global__ void __launch_bounds__(256)
xbar_kernel(const float* __restrict__ x)
{
    __shared__ float sbeta[64][4];
    int blk = blockIdx.x, m0 = blk * 64, tid = threadIdx.x;
    {
        int r = tid >> 2, h = tid & 3;
        int m = m0 + r, b = m >> 12, n = m & (N_ - 1);
        sbeta[r][h] = g_beta[(b * H_ + h) * N_ + n];
    }
    __syncthreads();
    float a0 = 0.f, a1 = 0.f, a2 = 0.f, a3 = 0.f;
    for (int r = 0; r < 64; r++) {
        float xv = x[(size_t)(m0 + r) * C_ + tid];
        a0 += xv * sbeta[r][0];
        a1 += xv * sbeta[r][1];
        a2 += xv * sbeta[r][2];
        a3 += xv * sbeta[r][3];
    }
    g_xbp[((size_t)blk * 4 + 0) * 256 + tid] = a0;
    g_xbp[((size_t)blk * 4 + 1) * 256 + tid] = a1;
    g_xbp[((size_t)blk * 4 + 2) * 256 + tid] = a2;
    g_xbp[((size_t)blk * 4 + 3) * 256 + tid] = a3;
}

// ---------------- K5a: invrms ----------------
__global__ void __launch_bounds__(256)
invrms_kernel()
{
    int m = blockIdx.x * 256 + threadIdx.x;
    float s = g_ssp[(size_t)m * 2] + g_ssp[(size_t)m * 2 + 1];
    g_invrms[m] = rsqrtf(s * (1.f / (float)C_) + 1e-6f);
}

// ---------------- K5b: finalize werr/wkey ----------------
__global__ void __launch_bounds__(256)
final_kernel(const float* __restrict__ S, const float* __restrict__ Wv)
{
    __shared__ float s_mk[64], s_mbk[64], s_xbar[256];
    int bh = blockIdx.x, b = bh >> 2, h = bh & 3, tid = threadIdx.x;
    {
        float a = 0.f;
        for (int t = 0; t < 64; t++)
            a += g_xbp[((size_t)(b * 64 + t) * 4 + h) * 256 + tid];
        s_xbar[tid] = a * (1.f / (float)N_);
    }
    if (tid < 64) {
        float s = 0.f;
        for (int t = 0; t < 32; t++)
            s += g_mkp[(size_t)(b * 32 + t) * 256 + h * 64 + tid];
        s_mk[tid] = s * (1.f / (float)N_);
    } else if (tid < 128) {
        int c = tid - 64;
        float s = 0.f;
        for (int t = 0; t < 32; t++)
            s += g_mbkp[(size_t)(b * 32 + t) * 256 + h * 64 + c];
        s_mbk[c] = s * (1.f / (float)N_);
    }
    __syncthreads();
    if (tid < 64) {
        int i = tid;
        const float* wv = Wv + (size_t)(h * 64 + i) * 256;
        float mbv = 0.f;
        for (int c = 0; c < 256; c++) mbv += wv[c] * s_xbar[c];
        const float* sd = S + (size_t)bh * 4096 + (size_t)i * 64;
        float sp = 0.f;
        for (int j = 0; j < 64; j++) sp += 0.95f * sd[j] * s_mbk[j];
        g_werr[bh * 64 + i] = mbv - sp;
        g_wkey[bh * 64 + i] = s_mk[i];
    }
}

// ---------------- K5c: S_new ----------------
__global__ void __launch_bounds__(256)
snew_kernel(const float* __restrict__ S, float* __restrict__ out_s)
{
    int idx = blockIdx.x * 256 + threadIdx.x;
    int bh = idx >> 12;
    int i = (idx >> 6) & 63;
    int j = idx & 63;
    float val = S[idx] * 0.95f + g_werr[bh * 64 + i] * g_wkey[bh * 64 + j];
    out_s[idx] = fminf(fmaxf(val, -10.f), 10.f);
}

// ---------------- launcher ----------------
extern "C" void kernel_launch(void* const* d_in, const int* in_sizes, int n_in,
                              void* d_out, int out_size)
{
    const float* x    = (const float*)d_in[0];
    const float* S    = (const float*)d_in[1];
    const float* Wq   = (const float*)d_in[2];
    const float* Wk   = (const float*)d_in[3];
    const float* Wv   = (const float*)d_in[4];
    const float* Wb   = (const float*)d_in[5];
    const float* Wo   = (const float*)d_in[6];
    const float* grms = (const float*)d_in[7];
    float* out = (float*)d_out;

    static int init = 0;
    static cudaStream_t s2;
    static cudaEvent_t eW, eB;
    if (!init) {
        cudaFuncSetAttribute(gemm_proj_kernel, cudaFuncAttributeMaxDynamicSharedMemorySize, 65536);
        cudaFuncSetAttribute(gemm_k_kernel, cudaFuncAttributeMaxDynamicSharedMemorySize, 65536);
        cudaFuncSetAttribute(wprime_kernel, cudaFuncAttributeMaxDynamicSharedMemorySize, 81920);
        cudaStreamCreateWithFlags(&s2, cudaStreamNonBlocking);
        cudaEventCreateWithFlags(&eW, cudaEventDisableTiming);
        cudaEventCreateWithFlags(&eB, cudaEventDisableTiming);
        init = 1;
    }

    // L1 (main): weight conversion (Wk, Wog)
    convw_kernel<<<512, 256>>>(Wk, Wo, grms);
    cudaEventRecord(eW, 0);

    // L2 (s2): beta — fully independent, starts immediately
    beta_kernel<<<8192, 256, 0, s2>>>(x, Wb);

    // L3 (main): W' = Sd@Wq
    wprime_kernel<<<64, 256, 81920>>>(S, Wq);

    // L4 (s2): k GEMM (single-pass bf16) — needs beta (s2 order) + Wk (eW)
    cudaStreamWaitEvent(s2, eW, 0);
    gemm_k_kernel<<<dim3(2, 512), 256, 65536, s2>>>(x);

    // L5 (main): y = x @ W'^T (+ ss partials)
    gemm_proj_kernel<<<dim3(2, 512), 256, 65536>>>(0, x, nullptr);

    // s2 tail: xbar, final, snew (hidden under main-stream GEMMs)
    xbar_kernel<<<1024, 256, 0, s2>>>(x);
    final_kernel<<<64, 256, 0, s2>>>(S, Wv);
    if (out_size >= OUT_MAIN + OUT_S) {
        snew_kernel<<<OUT_S / 256, 256, 0, s2>>>(S, out + OUT_MAIN);
    }
    cudaEventRecord(eB, s2);

    // main: invrms + out-projection
    invrms_kernel<<<M_ / 256, 256>>>();
    gemm_proj_kernel<<<dim3(2, 512), 256, 65536>>>(1, x, out);

    // join
    cudaStreamWaitEvent(0, eB, 0);
}

// round 13
// speedup vs baseline: 2.2312x; 1.1170x over previous
#include <cuda_runtime.h>
#include <cuda_bf16.h>
#include <cuda_fp16.h>
#include <math.h>

// ---------------- constants ----------------
#define B_ 16
#define N_ 4096
#define C_ 256
#define H_ 4
#define D_ 64
#define M_ (B_ * N_)              // 65536
#define OUT_MAIN (M_ * C_)        // 16777216
#define OUT_S (B_ * H_ * D_ * D_) // 262144

typedef unsigned int u32;
typedef unsigned short u16;

// ---------------- device scratch ----------------
__device__ u16 g_wph[B_ * C_ * C_];            // W' = Sd@Wq per batch (fp16 rn)
__device__ u16 g_wk[C_ * C_];                  // Wk (bf16 rn, for gemm_k)
__device__ u16 g_wog[C_ * C_];                 // Wo*grms (fp16 rn)
__device__ float g_y[M_ * C_];
__device__ float g_beta[B_ * H_ * N_];
__device__ float g_ssp[M_ * 2];
__device__ float g_invrms[M_];
__device__ float g_mkp[512 * 256], g_mbkp[512 * 256];   // per-mtile k partials
__device__ float g_xbp[1024 * H_ * C_];                  // per-64row beta*x partials
__device__ float g_werr[64 * 64], g_wkey[64 * 64];

// ---------------- helpers ----------------
__device__ __forceinline__ u32 smem_u32(const void* p) {
    u32 a;
    asm("{ .reg .u64 t; cvta.to.shared.u64 t, %1; cvt.u32.u64 %0, t; }" : "=r"(a) : "l"(p));
    return a;
}
__device__ __forceinline__ void ldmx4(u32* r, u32 addr) {
    asm volatile("ldmatrix.sync.aligned.m8n8.x4.shared.b16 {%0,%1,%2,%3}, [%4];"
                 : "=r"(r[0]), "=r"(r[1]), "=r"(r[2]), "=r"(r[3]) : "r"(addr));
}
__device__ __forceinline__ void mma_bf16(float* d, const u32* a, u32 b0, u32 b1) {
    asm volatile("mma.sync.aligned.m16n8k16.row.col.f32.bf16.bf16.f32 "
                 "{%0,%1,%2,%3}, {%4,%5,%6,%7}, {%8,%9}, {%0,%1,%2,%3};"
                 : "+f"(d[0]), "+f"(d[1]), "+f"(d[2]), "+f"(d[3])
                 : "r"(a[0]), "r"(a[1]), "r"(a[2]), "r"(a[3]), "r"(b0), "r"(b1));
}
__device__ __forceinline__ void mma_f16(float* d, const u32* a, u32 b0, u32 b1) {
    asm volatile("mma.sync.aligned.m16n8k16.row.col.f32.f16.f16.f32 "
                 "{%0,%1,%2,%3}, {%4,%5,%6,%7}, {%8,%9}, {%0,%1,%2,%3};"
                 : "+f"(d[0]), "+f"(d[1]), "+f"(d[2]), "+f"(d[3])
                 : "r"(a[0]), "r"(a[1]), "r"(a[2]), "r"(a[3]), "r"(b0), "r"(b1));
}
// fp16 RN pair: low = f0, high = f1
__device__ __forceinline__ u32 f16pair(float f0, float f1) {
    u32 r;
    asm("cvt.rn.f16x2.f32 %0, %1, %2;" : "=r"(r) : "f"(f1), "f"(f0));
    return r;
}
// fp16 split: h = rn16(f), l = rn16(f - h)  (a = h + l to ~2^-24)
__device__ __forceinline__ void split2h(float f0, float f1, u32& h01, u32& l01) {
    h01 = f16pair(f0, f1);
    __half2 hp = *reinterpret_cast<__half2*>(&h01);
    float2 bk = __half22float2(hp);
    l01 = f16pair(f0 - bk.x, f1 - bk.y);
}
// RN bf16 pair pack: low half = f0, high half = f1
__device__ __forceinline__ u32 bf16pair(float f0, float f1) {
    u32 r;
    asm("cvt.rn.bf16x2.f32 %0, %1, %2;" : "=r"(r) : "f"(f1), "f"(f0));
    return r;
}
__device__ __forceinline__ float eluf(float v) {
    return (v > 0.f) ? (v + 1.f) : expf(v);
}
#define CP_ASYNC16(dst, src) \
    asm volatile("cp.async.cg.shared.global [%0], [%1], 16;" :: "r"(dst), "l"(src))
#define CP_COMMIT() asm volatile("cp.async.commit_group;")
#define CP_WAIT0()  asm volatile("cp.async.wait_group 0;" ::: "memory")

// ---------------- K0: Wk -> bf16, Wo*grms -> fp16 ----------------
__global__ void __launch_bounds__(256) convw_kernel(
    const float* __restrict__ Wk, const float* __restrict__ Wo,
    const float* __restrict__ grms)
{
    int gid = blockIdx.x * 256 + threadIdx.x;   // < 131072
    int sel = gid >> 16, idx = gid & 65535;
    if (sel) {
        float v = Wo[idx] * grms[idx & 255];
        g_wog[idx] = __half_as_ushort(__float2half_rn(v));
    } else {
        g_wk[idx] = __bfloat16_as_ushort(__float2bfloat16(Wk[idx]));
    }
}

// ---------------- K0b: beta = sigmoid(x @ Wb^T), warp per row ----------------
__global__ void __launch_bounds__(256)
beta_kernel(const float* __restrict__ x, const float* __restrict__ Wb)
{
    int warp = (blockIdx.x * 256 + threadIdx.x) >> 5;
    int lane = threadIdx.x & 31;
    int m = warp;
    float a0 = 0.f, a1 = 0.f, a2 = 0.f, a3 = 0.f;
#pragma unroll
    for (int cc = 0; cc < 8; cc++) {
        int c = cc * 32 + lane;
        float xv = x[(size_t)m * C_ + c];
        a0 += xv * Wb[c];
        a1 += xv * Wb[256 + c];
        a2 += xv * Wb[512 + c];
        a3 += xv * Wb[768 + c];
    }
#pragma unroll
    for (int o = 16; o; o >>= 1) {
        a0 += __shfl_down_sync(0xffffffffu, a0, o);
        a1 += __shfl_down_sync(0xffffffffu, a1, o);
        a2 += __shfl_down_sync(0xffffffffu, a2, o);
        a3 += __shfl_down_sync(0xffffffffu, a3, o);
    }
    if (lane == 0) {
        int bb = m >> 12, n = m & (N_ - 1);
        g_beta[(bb * H_ + 0) * N_ + n] = 1.f / (1.f + expf(-a0));
        g_beta[(bb * H_ + 1) * N_ + n] = 1.f / (1.f + expf(-a1));
        g_beta[(bb * H_ + 2) * N_ + n] = 1.f / (1.f + expf(-a2));
        g_beta[(bb * H_ + 3) * N_ + n] = 1.f / (1.f + expf(-a3));
    }
}

// ---------------- K1: W'[b] = (0.95*S[b,h]) @ Wq_h -> fp16 rn ----------------
__global__ void __launch_bounds__(256)
wprime_kernel(const float* __restrict__ S, const float* __restrict__ Wq)
{
    extern __shared__ float sm[];        // sSdT[4096] + sWq[64*256] = 80KB
    float* sSdT = sm;
    float* sWq = sm + 4096;
    int bh = blockIdx.x, b = bh >> 2, h = bh & 3, tid = threadIdx.x;
    for (int t = tid; t < 4096; t += 256) {
        int i = t >> 6, j = t & 63;
        sSdT[j * 64 + i] = S[(size_t)bh * 4096 + t] * 0.95f;
    }
    for (int t = tid; t < 64 * 256; t += 256)
        sWq[t] = Wq[(size_t)(h * 64 + (t >> 8)) * 256 + (t & 255)];
    __syncthreads();
    int i = tid & 63, stripe = tid >> 6;
#pragma unroll 1
    for (int cc = 0; cc < 64; cc++) {
        int c = stripe * 64 + cc;
        float acc = 0.f;
#pragma unroll
        for (int j = 0; j < 64; j++)
            acc += sSdT[j * 64 + i] * sWq[j * 256 + c];
        size_t o = (size_t)b * 65536 + (size_t)(h * 64 + i) * 256 + c;
        g_wph[o] = __half_as_ushort(__float2half_rn(acc));
    }
}

// ============ pipelined GEMM bodies (K=32 chunks, double buffered) ============
// smem per stage s: A at s*32768 (16KB, fp16 h+l halves), B at s*32768+16384 (h half only used)
// A rows: 128 bytes = [h cols 0..31 | l cols 0..31], XOR-8 swizzle on 16B groups.

// ---------------- K2/K6: projection GEMM, 2-pass fp16 (A split, B rn), 128x128 ----------------
__global__ void __launch_bounds__(256, 2)
gemm_proj_kernel(int task, const float* __restrict__ Xfp, float* __restrict__ fout)
{
    extern __shared__ char smem[];
    __shared__ float sm_ss[128][2];
    const u32 sb = smem_u32(smem);
    const int tid = threadIdx.x, wid = tid >> 5, lane = tid & 31;
    const int m0 = blockIdx.y * 128;
    const int n0 = (int)blockIdx.x * 128;

    const float* Afp = (task == 0) ? Xfp : g_y;
    const u16* Bp = (task == 0) ? (g_wph + (size_t)(m0 >> 12) * 65536) : g_wog;

    const int wm = wid & 3, wn = wid >> 2;
    const int rA = (lane & 7) + ((lane >> 3) & 1) * 8, cAx = (lane >> 4) & 1;
    const int rB = (lane & 7) + ((lane >> 4) & 1) * 8, cBx = (lane >> 3) & 1;

    float acc[2][8][4];
#pragma unroll
    for (int i = 0; i < 2; i++)
#pragma unroll
        for (int j = 0; j < 8; j++)
#pragma unroll
            for (int t = 0; t < 4; t++) acc[i][j][t] = 0.f;

    const int lr = tid >> 1, q = tid & 1;
    const size_t arow = (size_t)(m0 + lr) * C_ + q * 16;
    const size_t brow = (size_t)(n0 + lr) * C_;
    float fr[16];

#define LD_A(c) do { \
    const float4* _p = (const float4*)(Afp + arow + (c) * 32); \
    *(float4*)(fr)      = _p[0]; *(float4*)(fr + 4)  = _p[1]; \
    *(float4*)(fr + 8)  = _p[2]; *(float4*)(fr + 12) = _p[3]; \
} while (0)

#define LD_B(c, ob) do { \
    _Pragma("unroll") \
    for (int _i = 0; _i < 2; _i++) { \
        int _cg = q * 2 + _i; \
        u32 _row = (ob) + (u32)lr * 128; \
        CP_ASYNC16(sb + _row + (u32)((_cg ^ (lr & 7)) << 4), \
                   (const void*)(Bp + brow + (c) * 32 + _cg * 8)); \
    } \
    CP_COMMIT(); \
} while (0)

#define ST_A(c, oa) do { \
    u32 _hv[8], _lv[8]; \
    _Pragma("unroll") \
    for (int _t = 0; _t < 8; _t++) split2h(fr[2 * _t], fr[2 * _t + 1], _hv[_t], _lv[_t]); \
    u32 _base = (oa) + (u32)lr * 128; \
    int _c0 = q * 2, _c1 = q * 2 + 1; \
    *(uint4*)(smem + _base + ((_c0 ^ (lr & 7)) << 4))       = make_uint4(_hv[0], _hv[1], _hv[2], _hv[3]); \
    *(uint4*)(smem + _base + ((_c1 ^ (lr & 7)) << 4))       = make_uint4(_hv[4], _hv[5], _hv[6], _hv[7]); \
    *(uint4*)(smem + _base + (((_c0 + 4) ^ (lr & 7)) << 4)) = make_uint4(_lv[0], _lv[1], _lv[2], _lv[3]); \
    *(uint4*)(smem + _base + (((_c1 + 4) ^ (lr & 7)) << 4)) = make_uint4(_lv[4], _lv[5], _lv[6], _lv[7]); \
} while (0)

#define MMA_CHUNK(s) do { \
    u32 _oa = (u32)(s) * 32768, _obm = _oa + 16384; \
    _Pragma("unroll") \
    for (int ks = 0; ks < 2; ks++) { \
        u32 ah[2][4], al[2][4]; \
        _Pragma("unroll") \
        for (int ms = 0; ms < 2; ms++) { \
            int r = wm * 32 + ms * 16 + rA; \
            u32 rowb = _oa + (u32)r * 128; \
            ldmx4(ah[ms], sb + rowb + (u32)((((2 * ks + cAx)) ^ (r & 7)) << 4)); \
            ldmx4(al[ms], sb + rowb + (u32)((((2 * ks + cAx) + 4) ^ (r & 7)) << 4)); \
        } \
        _Pragma("unroll") \
        for (int nh = 0; nh < 4; nh++) { \
            int n = wn * 64 + nh * 16 + rB; \
            u32 rowbB = _obm + (u32)n * 128; \
            u32 bhf[4]; \
            ldmx4(bhf, sb + rowbB + (u32)((((2 * ks + cBx)) ^ (n & 7)) << 4)); \
            mma_f16(acc[0][nh * 2],     ah[0], bhf[0], bhf[1]); \
            mma_f16(acc[1][nh * 2],     ah[1], bhf[0], bhf[1]); \
            mma_f16(acc[0][nh * 2 + 1], ah[0], bhf[2], bhf[3]); \
            mma_f16(acc[1][nh * 2 + 1], ah[1], bhf[2], bhf[3]); \
            mma_f16(acc[0][nh * 2],     al[0], bhf[0], bhf[1]); \
            mma_f16(acc[1][nh * 2],     al[1], bhf[0], bhf[1]); \
            mma_f16(acc[0][nh * 2 + 1], al[0], bhf[2], bhf[3]); \
            mma_f16(acc[1][nh * 2 + 1], al[1], bhf[2], bhf[3]); \
        } \
    } \
} while (0)

    LD_A(0);
    LD_B(0, 16384u);
    ST_A(0, 0u);
    CP_WAIT0();
    __syncthreads();

#pragma unroll
    for (int c = 0; c < 8; c++) {
        if (c < 7) { LD_A(c + 1); LD_B(c + 1, (u32)(((c + 1) & 1) * 32768 + 16384)); }
        MMA_CHUNK(c & 1);
        if (c < 7) {
            ST_A(c + 1, (u32)(((c + 1) & 1) * 32768));
            CP_WAIT0();
            __syncthreads();
        }
    }

    // ---- epilogue ----
    const int qrow = lane >> 2, qcol = (lane & 3) * 2;
    if (task == 0) {
#pragma unroll
        for (int mm = 0; mm < 2; mm++) {
            size_t r_lo = (size_t)(m0 + wm * 32 + mm * 16 + qrow);
            size_t r_hi = r_lo + 8;
            float ssl = 0.f, ssh = 0.f;
#pragma unroll
            for (int nf = 0; nf < 8; nf++) {
                int cof = n0 + wn * 64 + nf * 8 + qcol;
                *(float2*)(g_y + r_lo * C_ + cof) = make_float2(acc[mm][nf][0], acc[mm][nf][1]);
                *(float2*)(g_y + r_hi * C_ + cof) = make_float2(acc[mm][nf][2], acc[mm][nf][3]);
                ssl += acc[mm][nf][0] * acc[mm][nf][0] + acc[mm][nf][1] * acc[mm][nf][1];
                ssh += acc[mm][nf][2] * acc[mm][nf][2] + acc[mm][nf][3] * acc[mm][nf][3];
            }
            ssl += __shfl_xor_sync(0xffffffffu, ssl, 1);
            ssl += __shfl_xor_sync(0xffffffffu, ssl, 2);
            ssh += __shfl_xor_sync(0xffffffffu, ssh, 1);
            ssh += __shfl_xor_sync(0xffffffffu, ssh, 2);
            if ((lane & 3) == 0) {
                sm_ss[wm * 32 + mm * 16 + qrow][wn]     = ssl;
                sm_ss[wm * 32 + mm * 16 + qrow + 8][wn] = ssh;
            }
        }
        __syncthreads();
        if (tid < 128)
            g_ssp[(size_t)(m0 + tid) * 2 + (n0 >> 7)] = sm_ss[tid][0] + sm_ss[tid][1];
    } else {
#pragma unroll
        for (int mm = 0; mm < 2; mm++) {
            size_t r_lo = (size_t)(m0 + wm * 32 + mm * 16 + qrow);
            size_t r_hi = r_lo + 8;
            float irm_lo = g_invrms[r_lo];
            float irm_hi = g_invrms[r_hi];
#pragma unroll
            for (int nf = 0; nf < 8; nf++) {
                int cof = n0 + wn * 64 + nf * 8 + qcol;
                *(float2*)(fout + r_lo * C_ + cof) =
                    make_float2(acc[mm][nf][0] * irm_lo, acc[mm][nf][1] * irm_lo);
                *(float2*)(fout + r_hi * C_ + cof) =
                    make_float2(acc[mm][nf][2] * irm_hi, acc[mm][nf][3] * irm_hi);
            }
        }
    }
#undef LD_A
#undef LD_B
#undef ST_A
#undef MMA_CHUNK
}

// ---------------- K4: k GEMM, single-pass bf16 (k only feeds means) ----------------
__global__ void __launch_bounds__(256, 2)
gemm_k_kernel(const float* __restrict__ Xfp)
{
    extern __shared__ char smem[];
    const u32 sb = smem_u32(smem);
    const int tid = threadIdx.x, wid = tid >> 5, lane = tid & 31;
    const int m0 = blockIdx.y * 128;
    const int n0 = (int)blockIdx.x * 128;
    const u16* Bp = g_wk;

    const int wm = wid & 3, wn = wid >> 2;
    const int rA = (lane & 7) + ((lane >> 3) & 1) * 8, cAx = (lane >> 4) & 1;
    const int rB = (lane & 7) + ((lane >> 4) & 1) * 8, cBx = (lane >> 3) & 1;

    float acc[2][8][4];
#pragma unroll
    for (int i = 0; i < 2; i++)
#pragma unroll
        for (int j = 0; j < 8; j++)
#pragma unroll
            for (int t = 0; t < 4; t++) acc[i][j][t] = 0.f;

    const int lr = tid >> 1, q = tid & 1;
    const size_t arow = (size_t)(m0 + lr) * C_ + q * 16;
    const size_t brow = (size_t)(n0 + lr) * C_;
    float fr[16];

#define LD_A(c) do { \
    const float4* _p = (const float4*)(Xfp + arow + (c) * 32); \
    *(float4*)(fr)      = _p[0]; *(float4*)(fr + 4)  = _p[1]; \
    *(float4*)(fr + 8)  = _p[2]; *(float4*)(fr + 12) = _p[3]; \
} while (0)

#define LD_B(c, ob) do { \
    _Pragma("unroll") \
    for (int _i = 0; _i < 2; _i++) { \
        int _cg = q * 2 + _i; \
        u32 _row = (ob) + (u32)lr * 128; \
        CP_ASYNC16(sb + _row + (u32)((_cg ^ (lr & 7)) << 4), \
                   (const void*)(Bp + brow + (c) * 32 + _cg * 8)); \
    } \
    CP_COMMIT(); \
} while (0)

#define ST_A(c, oa) do { \
    u32 _hv[8]; \
    _Pragma("unroll") \
    for (int _t = 0; _t < 8; _t++) _hv[_t] = bf16pair(fr[2 * _t], fr[2 * _t + 1]); \
    u32 _base = (oa) + (u32)lr * 128; \
    int _c0 = q * 2, _c1 = q * 2 + 1; \
    *(uint4*)(smem + _base + ((_c0 ^ (lr & 7)) << 4)) = make_uint4(_hv[0], _hv[1], _hv[2], _hv[3]); \
    *(uint4*)(smem + _base + ((_c1 ^ (lr & 7)) << 4)) = make_uint4(_hv[4], _hv[5], _hv[6], _hv[7]); \
} while (0)

#define MMA_CHUNK(s) do { \
    u32 _oa = (u32)(s) * 32768, _obm = _oa + 16384; \
    _Pragma("unroll") \
    for (int ks = 0; ks < 2; ks++) { \
        u32 ah[2][4]; \
        _Pragma("unroll") \
        for (int ms = 0; ms < 2; ms++) { \
            int r = wm * 32 + ms * 16 + rA; \
            u32 rowb = _oa + (u32)r * 128; \
            ldmx4(ah[ms], sb + rowb + (u32)((((2 * ks + cAx)) ^ (r & 7)) << 4)); \
        } \
        _Pragma("unroll") \
        for (int nh = 0; nh < 4; nh++) { \
            int n = wn * 64 + nh * 16 + rB; \
            u32 rowbB = _obm + (u32)n * 128; \
            u32 bhf[4]; \
            ldmx4(bhf, sb + rowbB + (u32)((((2 * ks + cBx)) ^ (n & 7)) << 4)); \
            mma_bf16(acc[0][nh * 2],     ah[0], bhf[0], bhf[1]); \
            mma_bf16(acc[1][nh * 2],     ah[1], bhf[0], bhf[1]); \
            mma_bf16(acc[0][nh * 2 + 1], ah[0], bhf[2], bhf[3]); \
            mma_bf16(acc[1][nh * 2 + 1], ah[1], bhf[2], bhf[3]); \
        } \
    } \
} while (0)

    LD_A(0);
    LD_B(0, 16384u);
    ST_A(0, 0u);
    CP_WAIT0();
    __syncthreads();

#pragma unroll
    for (int c = 0; c < 8; c++) {
        if (c < 7) { LD_A(c + 1); LD_B(c + 1, (u32)(((c + 1) & 1) * 32768 + 16384)); }
        MMA_CHUNK(c & 1);
        if (c < 7) {
            ST_A(c + 1, (u32)(((c + 1) & 1) * 32768));
            CP_WAIT0();
            __syncthreads();
        }
    }

    // ---- epilogue: elu+1, per-head L2 norm, reduce mk & beta-weighted mbk ----
    const int qrow = lane >> 2, qcol = (lane & 3) * 2;
    const int head = (n0 >> 6) + wn;
    const int bhh = (m0 >> 12) * H_ + head;
    float mk0[8], mk1[8], mbk0[8], mbk1[8];
#pragma unroll
    for (int nf = 0; nf < 8; nf++) { mk0[nf] = mk1[nf] = mbk0[nf] = mbk1[nf] = 0.f; }

#pragma unroll
    for (int mm = 0; mm < 2; mm++) {
        float ssl = 0.f, ssh = 0.f;
#pragma unroll
        for (int nf = 0; nf < 8; nf++) {
            float e0 = eluf(acc[mm][nf][0]); acc[mm][nf][0] = e0; ssl += e0 * e0;
            float e1 = eluf(acc[mm][nf][1]); acc[mm][nf][1] = e1; ssl += e1 * e1;
            float e2 = eluf(acc[mm][nf][2]); acc[mm][nf][2] = e2; ssh += e2 * e2;
            float e3 = eluf(acc[mm][nf][3]); acc[mm][nf][3] = e3; ssh += e3 * e3;
        }
        ssl += __shfl_xor_sync(0xffffffffu, ssl, 1);
        ssl += __shfl_xor_sync(0xffffffffu, ssl, 2);
        ssh += __shfl_xor_sync(0xffffffffu, ssh, 1);
        ssh += __shfl_xor_sync(0xffffffffu, ssh, 2);
        float invl = 1.f / (sqrtf(ssl) + 1e-6f);
        float invh = 1.f / (sqrtf(ssh) + 1e-6f);
        int nrow = (m0 & (N_ - 1)) + wm * 32 + mm * 16 + qrow;
        float b_lo = g_beta[bhh * N_ + nrow];
        float b_hi = g_beta[bhh * N_ + nrow + 8];
#pragma unroll
        for (int nf = 0; nf < 8; nf++) {
            float v0 = acc[mm][nf][0] * invl, v1 = acc[mm][nf][1] * invl;
            float v2 = acc[mm][nf][2] * invh, v3 = acc[mm][nf][3] * invh;
            mk0[nf]  += v0 + v2;
            mk1[nf]  += v1 + v3;
            mbk0[nf] += b_lo * v0 + b_hi * v2;
            mbk1[nf] += b_lo * v1 + b_hi * v3;
        }
    }
#pragma unroll
    for (int o = 4; o <= 16; o <<= 1) {
#pragma unroll
        for (int nf = 0; nf < 8; nf++) {
            mk0[nf]  += __shfl_xor_sync(0xffffffffu, mk0[nf], o);
            mk1[nf]  += __shfl_xor_sync(0xffffffffu, mk1[nf], o);
            mbk0[nf] += __shfl_xor_sync(0xffffffffu, mbk0[nf], o);
            mbk1[nf] += __shfl_xor_sync(0xffffffffu, mbk1[nf], o);
        }
    }
    __syncthreads();
    float* red = (float*)smem;   // reuse staging smem: [0,512) mk, [512,1024) mbk
    if (lane < 4) {
#pragma unroll
        for (int nf = 0; nf < 8; nf++) {
            red[wid * 64 + nf * 8 + lane * 2]           = mk0[nf];
            red[wid * 64 + nf * 8 + lane * 2 + 1]       = mk1[nf];
            red[512 + wid * 64 + nf * 8 + lane * 2]     = mbk0[nf];
            red[512 + wid * 64 + nf * 8 + lane * 2 + 1] = mbk1[nf];
        }
    }
    __syncthreads();
    if (tid < 128) {
        int hh = tid >> 6, col = tid & 63;
        float s = red[(hh * 4 + 0) * 64 + col] + red[(hh * 4 + 1) * 64 + col]
                + red[(hh * 4 + 2) * 64 + col] + red[(hh * 4 + 3) * 64 + col];
        g_mkp[(size_t)blockIdx.y * 256 + n0 + hh * 64 + col] = s;
    } else {
        int t2 = tid - 128, hh = t2 >> 6, col = t2 & 63;
        float s = red[512 + (hh * 4 + 0) * 64 + col] + red[512 + (hh * 4 + 1) * 64 + col]
                + red[512 + (hh * 4 + 2) * 64 + col] + red[512 + (hh * 4 + 3) * 64 + col];
        g_mbkp[(size_t)blockIdx.y * 256 + n0 + hh * 64 + col] = s;
    }
#undef LD_A
#undef LD_B
#undef ST_A
#undef MMA_CHUNK
}

// ---------------- K3: xbar partials = sum_n beta*x over 64-row chunks ----------------
__global__ void __launch_bounds__(256)
xbar_kernel(const float* __restrict__ x)
{
    __shared__ float sbeta[64][4];
    int blk = blockIdx.x, m0 = blk * 64, tid = threadIdx.x;
    {
        int r = tid >> 2, h = tid & 3;
        int m = m0 + r, b = m >> 12, n = m & (N_ - 1);
        sbeta[r][h] = g_beta[(b * H_ + h) * N_ + n];
    }
    __syncthreads();
    float a0 = 0.f, a1 = 0.f, a2 = 0.f, a3 = 0.f;
    for (int r = 0; r < 64; r++) {
        float xv = x[(size_t)(m0 + r) * C_ + tid];
        a0 += xv * sbeta[r][0];
        a1 += xv * sbeta[r][1];
        a2 += xv * sbeta[r][2];
        a3 += xv * sbeta[r][3];
    }
    g_xbp[((size_t)blk * 4 + 0) * 256 + tid] = a0;
    g_xbp[((size_t)blk * 4 + 1) * 256 + tid] = a1;
    g_xbp[((size_t)blk * 4 + 2) * 256 + tid] = a2;
    g_xbp[((size_t)blk * 4 + 3) * 256 + tid] = a3;
}

// ---------------- K5a: invrms ----------------
__global__ void __launch_bounds__(256)
invrms_kernel()
{
    int m = blockIdx.x * 256 + threadIdx.x;
    float s = g_ssp[(size_t)m * 2] + g_ssp[(size_t)m * 2 + 1];
    g_invrms[m] = rsqrtf(s * (1.f / (float)C_) + 1e-6f);
}

// ---------------- K5b: finalize werr/wkey ----------------
__global__ void __launch_bounds__(256)
final_kernel(const float* __restrict__ S, const float* __restrict__ Wv)
{
    __shared__ float s_mk[64], s_mbk[64], s_xbar[256];
    int bh = blockIdx.x, b = bh >> 2, h = bh & 3, tid = threadIdx.x;
    {
        float a = 0.f;
        for (int t = 0; t < 64; t++)
            a += g_xbp[((size_t)(b * 64 + t) * 4 + h) * 256 + tid];
        s_xbar[tid] = a * (1.f / (float)N_);
    }
    if (tid < 64) {
        float s = 0.f;
        for (int t = 0; t < 32; t++)
            s += g_mkp[(size_t)(b * 32 + t) * 256 + h * 64 + tid];
        s_mk[tid] = s * (1.f / (float)N_);
    } else if (tid < 128) {
        int c = tid - 64;
        float s = 0.f;
        for (int t = 0; t < 32; t++)
            s += g_mbkp[(size_t)(b * 32 + t) * 256 + h * 64 + c];
        s_mbk[c] = s * (1.f / (float)N_);
    }
    __syncthreads();
    if (tid < 64) {
        int i = tid;
        const float* wv = Wv + (size_t)(h * 64 + i) * 256;
        float mbv = 0.f;
        for (int c = 0; c < 256; c++) mbv += wv[c] * s_xbar[c];
        const float* sd = S + (size_t)bh * 4096 + (size_t)i * 64;
        float sp = 0.f;
        for (int j = 0; j < 64; j++) sp += 0.95f * sd[j] * s_mbk[j];
        g_werr[bh * 64 + i] = mbv - sp;
        g_wkey[bh * 64 + i] = s_mk[i];
    }
}

// ---------------- K5c: S_new ----------------
__global__ void __launch_bounds__(256)
snew_kernel(const float* __restrict__ S, float* __restrict__ out_s)
{
    int idx = blockIdx.x * 256 + threadIdx.x;
    int bh = idx >> 12;
    int i = (idx >> 6) & 63;
    int j = idx & 63;
    float val = S[idx] * 0.95f + g_werr[bh * 64 + i] * g_wkey[bh * 64 + j];
    out_s[idx] = fminf(fmaxf(val, -10.f), 10.f);
}

// ---------------- launcher ----------------
extern "C" void kernel_launch(void* const* d_in, const int* in_sizes, int n_in,
                              void* d_out, int out_size)
{
    const float* x    = (const float*)d_in[0];
    const float* S    = (const float*)d_in[1];
    const float* Wq   = (const float*)d_in[2];
    const float* Wk   = (const float*)d_in[3];
    const float* Wv   = (const float*)d_in[4];
    const float* Wb   = (const float*)d_in[5];
    const float* Wo   = (const float*)d_in[6];
    const float* grms = (const float*)d_in[7];
    float* out = (float*)d_out;

    static int init = 0;
    static cudaStream_t s2;
    static cudaEvent_t eW, eB;
    if (!init) {
        cudaFuncSetAttribute(gemm_proj_kernel, cudaFuncAttributeMaxDynamicSharedMemorySize, 65536);
        cudaFuncSetAttribute(gemm_k_kernel, cudaFuncAttributeMaxDynamicSharedMemorySize, 65536);
        cudaFuncSetAttribute(wprime_kernel, cudaFuncAttributeMaxDynamicSharedMemorySize, 81920);
        cudaStreamCreateWithFlags(&s2, cudaStreamNonBlocking);
        cudaEventCreateWithFlags(&eW, cudaEventDisableTiming);
        cudaEventCreateWithFlags(&eB, cudaEventDisableTiming);
        init = 1;
    }

    // L1 (main): weight conversion (Wk bf16, Wog fp16)
    convw_kernel<<<512, 256>>>(Wk, Wo, grms);
    cudaEventRecord(eW, 0);

    // L2 (s2): beta — fully independent
    beta_kernel<<<8192, 256, 0, s2>>>(x, Wb);

    // L3 (main): W' = Sd@Wq (fp16 rn)
    wprime_kernel<<<64, 256, 81920>>>(S, Wq);

    // L4 (s2): k GEMM (single-pass bf16) — needs beta (s2 order) + Wk (eW)
    cudaStreamWaitEvent(s2, eW, 0);
    gemm_k_kernel<<<dim3(2, 512), 256, 65536, s2>>>(x);

    // L5 (main): y = x @ W'^T, 2-pass fp16 (+ ss partials)
    gemm_proj_kernel<<<dim3(2, 512), 256, 65536>>>(0, x, nullptr);

    // s2 tail: xbar, final, snew (hidden under main-stream GEMMs)
    xbar_kernel<<<1024, 256, 0, s2>>>(x);
    final_kernel<<<64, 256, 0, s2>>>(S, Wv);
    if (out_size >= OUT_MAIN + OUT_S) {
        snew_kernel<<<OUT_S / 256, 256, 0, s2>>>(S, out + OUT_MAIN);
    }
    cudaEventRecord(eB, s2);

    // main: invrms + out-projection (2-pass fp16)
    invrms_kernel<<<M_ / 256, 256>>>();
    gemm_proj_kernel<<<dim3(2, 512), 256, 65536>>>(1, x, out);

    // join
    cudaStreamWaitEvent(0, eB, 0);
}

// round 14
// speedup vs baseline: 2.6146x; 1.1719x over previous
#include <cuda_runtime.h>
#include <cuda_bf16.h>
#include <cuda_fp16.h>
#include <math.h>

// ---------------- constants ----------------
#define B_ 16
#define N_ 4096
#define C_ 256
#define H_ 4
#define D_ 64
#define M_ (B_ * N_)              // 65536
#define OUT_MAIN (M_ * C_)        // 16777216
#define OUT_S (B_ * H_ * D_ * D_) // 262144

typedef unsigned int u32;
typedef unsigned short u16;

// ---------------- device scratch ----------------
__device__ u16 g_wph[B_ * C_ * C_];            // W' = Sd@Wq per batch (fp16 rn)
__device__ u16 g_wk[C_ * C_];                  // Wk (bf16 rn, for gemm_k)
__device__ u16 g_wog[C_ * C_];                 // Wo*grms (fp16 rn)
__device__ float g_y[M_ * C_];
__device__ float g_beta[B_ * H_ * N_];
__device__ float g_ssp[M_ * 2];
__device__ float g_invrms[M_];
__device__ float g_mkp[512 * 256], g_mbkp[512 * 256];   // per-mtile k partials
__device__ float g_xbp[1024 * H_ * C_];                  // per-64row beta*x partials
__device__ float g_werr[64 * 64], g_wkey[64 * 64];

// ---------------- helpers ----------------
__device__ __forceinline__ u32 smem_u32(const void* p) {
    u32 a;
    asm("{ .reg .u64 t; cvta.to.shared.u64 t, %1; cvt.u32.u64 %0, t; }" : "=r"(a) : "l"(p));
    return a;
}
__device__ __forceinline__ void ldmx4(u32* r, u32 addr) {
    asm volatile("ldmatrix.sync.aligned.m8n8.x4.shared.b16 {%0,%1,%2,%3}, [%4];"
                 : "=r"(r[0]), "=r"(r[1]), "=r"(r[2]), "=r"(r[3]) : "r"(addr));
}
__device__ __forceinline__ void mma_bf16(float* d, const u32* a, u32 b0, u32 b1) {
    asm volatile("mma.sync.aligned.m16n8k16.row.col.f32.bf16.bf16.f32 "
                 "{%0,%1,%2,%3}, {%4,%5,%6,%7}, {%8,%9}, {%0,%1,%2,%3};"
                 : "+f"(d[0]), "+f"(d[1]), "+f"(d[2]), "+f"(d[3])
                 : "r"(a[0]), "r"(a[1]), "r"(a[2]), "r"(a[3]), "r"(b0), "r"(b1));
}
__device__ __forceinline__ void mma_f16(float* d, const u32* a, u32 b0, u32 b1) {
    asm volatile("mma.sync.aligned.m16n8k16.row.col.f32.f16.f16.f32 "
                 "{%0,%1,%2,%3}, {%4,%5,%6,%7}, {%8,%9}, {%0,%1,%2,%3};"
                 : "+f"(d[0]), "+f"(d[1]), "+f"(d[2]), "+f"(d[3])
                 : "r"(a[0]), "r"(a[1]), "r"(a[2]), "r"(a[3]), "r"(b0), "r"(b1));
}
// fp16 RN pair: low = f0, high = f1
__device__ __forceinline__ u32 f16pair(float f0, float f1) {
    u32 r;
    asm("cvt.rn.f16x2.f32 %0, %1, %2;" : "=r"(r) : "f"(f1), "f"(f0));
    return r;
}
// fp16 split: h = rn16(f), l = rn16(f - h)  (a = h + l to ~2^-24)
__device__ __forceinline__ void split2h(float f0, float f1, u32& h01, u32& l01) {
    h01 = f16pair(f0, f1);
    __half2 hp = *reinterpret_cast<__half2*>(&h01);
    float2 bk = __half22float2(hp);
    l01 = f16pair(f0 - bk.x, f1 - bk.y);
}
// RN bf16 pair pack: low half = f0, high half = f1
__device__ __forceinline__ u32 bf16pair(float f0, float f1) {
    u32 r;
    asm("cvt.rn.bf16x2.f32 %0, %1, %2;" : "=r"(r) : "f"(f1), "f"(f0));
    return r;
}
__device__ __forceinline__ float eluf(float v) {
    return (v > 0.f) ? (v + 1.f) : expf(v);
}
#define CP_ASYNC16(dst, src) \
    asm volatile("cp.async.cg.shared.global [%0], [%1], 16;" :: "r"(dst), "l"(src))
#define CP_COMMIT() asm volatile("cp.async.commit_group;")
#define CP_WAIT0()  asm volatile("cp.async.wait_group 0;" ::: "memory")

// ---------------- K0: Wk -> bf16, Wo*grms -> fp16 ----------------
__global__ void __launch_bounds__(256) convw_kernel(
    const float* __restrict__ Wk, const float* __restrict__ Wo,
    const float* __restrict__ grms)
{
    int gid = blockIdx.x * 256 + threadIdx.x;   // < 131072
    int sel = gid >> 16, idx = gid & 65535;
    if (sel) {
        float v = Wo[idx] * grms[idx & 255];
        g_wog[idx] = __half_as_ushort(__float2half_rn(v));
    } else {
        g_wk[idx] = __bfloat16_as_ushort(__float2bfloat16(Wk[idx]));
    }
}

// ---------------- K0b: beta = sigmoid(x @ Wb^T), warp per row ----------------
__global__ void __launch_bounds__(256)
beta_kernel(const float* __restrict__ x, const float* __restrict__ Wb)
{
    int warp = (blockIdx.x * 256 + threadIdx.x) >> 5;
    int lane = threadIdx.x & 31;
    int m = warp;
    float a0 = 0.f, a1 = 0.f, a2 = 0.f, a3 = 0.f;
#pragma unroll
    for (int cc = 0; cc < 8; cc++) {
        int c = cc * 32 + lane;
        float xv = x[(size_t)m * C_ + c];
        a0 += xv * Wb[c];
        a1 += xv * Wb[256 + c];
        a2 += xv * Wb[512 + c];
        a3 += xv * Wb[768 + c];
    }
#pragma unroll
    for (int o = 16; o; o >>= 1) {
        a0 += __shfl_down_sync(0xffffffffu, a0, o);
        a1 += __shfl_down_sync(0xffffffffu, a1, o);
        a2 += __shfl_down_sync(0xffffffffu, a2, o);
        a3 += __shfl_down_sync(0xffffffffu, a3, o);
    }
    if (lane == 0) {
        int bb = m >> 12, n = m & (N_ - 1);
        g_beta[(bb * H_ + 0) * N_ + n] = 1.f / (1.f + expf(-a0));
        g_beta[(bb * H_ + 1) * N_ + n] = 1.f / (1.f + expf(-a1));
        g_beta[(bb * H_ + 2) * N_ + n] = 1.f / (1.f + expf(-a2));
        g_beta[(bb * H_ + 3) * N_ + n] = 1.f / (1.f + expf(-a3));
    }
}

// ---------------- K1: W'[b] = (0.95*S[b,h]) @ Wq_h -> fp16 rn ----------------
__global__ void __launch_bounds__(256)
wprime_kernel(const float* __restrict__ S, const float* __restrict__ Wq)
{
    extern __shared__ float sm[];        // sSdT[4096] + sWq[64*256] = 80KB
    float* sSdT = sm;
    float* sWq = sm + 4096;
    int bh = blockIdx.x, b = bh >> 2, h = bh & 3, tid = threadIdx.x;
    for (int t = tid; t < 4096; t += 256) {
        int i = t >> 6, j = t & 63;
        sSdT[j * 64 + i] = S[(size_t)bh * 4096 + t] * 0.95f;
    }
    for (int t = tid; t < 64 * 256; t += 256)
        sWq[t] = Wq[(size_t)(h * 64 + (t >> 8)) * 256 + (t & 255)];
    __syncthreads();
    int i = tid & 63, stripe = tid >> 6;
#pragma unroll 1
    for (int cc = 0; cc < 64; cc++) {
        int c = stripe * 64 + cc;
        float acc = 0.f;
#pragma unroll
        for (int j = 0; j < 64; j++)
            acc += sSdT[j * 64 + i] * sWq[j * 256 + c];
        size_t o = (size_t)b * 65536 + (size_t)(h * 64 + i) * 256 + c;
        g_wph[o] = __half_as_ushort(__float2half_rn(acc));
    }
}

// ============ pipelined GEMM bodies (K=32 chunks, double buffered) ============

// ---------------- K2/K6: projection GEMM, 2-pass fp16 (A split, B rn), 128x128 ----------------
// grid (2, 256) per M-half; mbase selects the half.
__global__ void __launch_bounds__(256, 2)
gemm_proj_kernel(int task, int mbase, const float* __restrict__ Xfp, float* __restrict__ fout)
{
    extern __shared__ char smem[];
    __shared__ float sm_ss[128][2];
    const u32 sb = smem_u32(smem);
    const int tid = threadIdx.x, wid = tid >> 5, lane = tid & 31;
    const int m0 = mbase + blockIdx.y * 128;
    const int n0 = (int)blockIdx.x * 128;

    const float* Afp = (task == 0) ? Xfp : g_y;
    const u16* Bp = (task == 0) ? (g_wph + (size_t)(m0 >> 12) * 65536) : g_wog;

    const int wm = wid & 3, wn = wid >> 2;
    const int rA = (lane & 7) + ((lane >> 3) & 1) * 8, cAx = (lane >> 4) & 1;
    const int rB = (lane & 7) + ((lane >> 4) & 1) * 8, cBx = (lane >> 3) & 1;

    float acc[2][8][4];
#pragma unroll
    for (int i = 0; i < 2; i++)
#pragma unroll
        for (int j = 0; j < 8; j++)
#pragma unroll
            for (int t = 0; t < 4; t++) acc[i][j][t] = 0.f;

    const int lr = tid >> 1, q = tid & 1;
    const size_t arow = (size_t)(m0 + lr) * C_ + q * 16;
    const size_t brow = (size_t)(n0 + lr) * C_;
    float fr[16];

#define LD_A(c) do { \
    const float4* _p = (const float4*)(Afp + arow + (c) * 32); \
    *(float4*)(fr)      = _p[0]; *(float4*)(fr + 4)  = _p[1]; \
    *(float4*)(fr + 8)  = _p[2]; *(float4*)(fr + 12) = _p[3]; \
} while (0)

#define LD_B(c, ob) do { \
    _Pragma("unroll") \
    for (int _i = 0; _i < 2; _i++) { \
        int _cg = q * 2 + _i; \
        u32 _row = (ob) + (u32)lr * 128; \
        CP_ASYNC16(sb + _row + (u32)((_cg ^ (lr & 7)) << 4), \
                   (const void*)(Bp + brow + (c) * 32 + _cg * 8)); \
    } \
    CP_COMMIT(); \
} while (0)

#define ST_A(c, oa) do { \
    u32 _hv[8], _lv[8]; \
    _Pragma("unroll") \
    for (int _t = 0; _t < 8; _t++) split2h(fr[2 * _t], fr[2 * _t + 1], _hv[_t], _lv[_t]); \
    u32 _base = (oa) + (u32)lr * 128; \
    int _c0 = q * 2, _c1 = q * 2 + 1; \
    *(uint4*)(smem + _base + ((_c0 ^ (lr & 7)) << 4))       = make_uint4(_hv[0], _hv[1], _hv[2], _hv[3]); \
    *(uint4*)(smem + _base + ((_c1 ^ (lr & 7)) << 4))       = make_uint4(_hv[4], _hv[5], _hv[6], _hv[7]); \
    *(uint4*)(smem + _base + (((_c0 + 4) ^ (lr & 7)) << 4)) = make_uint4(_lv[0], _lv[1], _lv[2], _lv[3]); \
    *(uint4*)(smem + _base + (((_c1 + 4) ^ (lr & 7)) << 4)) = make_uint4(_lv[4], _lv[5], _lv[6], _lv[7]); \
} while (0)

#define MMA_CHUNK(s) do { \
    u32 _oa = (u32)(s) * 32768, _obm = _oa + 16384; \
    _Pragma("unroll") \
    for (int ks = 0; ks < 2; ks++) { \
        u32 ah[2][4], al[2][4]; \
        _Pragma("unroll") \
        for (int ms = 0; ms < 2; ms++) { \
            int r = wm * 32 + ms * 16 + rA; \
            u32 rowb = _oa + (u32)r * 128; \
            ldmx4(ah[ms], sb + rowb + (u32)((((2 * ks + cAx)) ^ (r & 7)) << 4)); \
            ldmx4(al[ms], sb + rowb + (u32)((((2 * ks + cAx) + 4) ^ (r & 7)) << 4)); \
        } \
        _Pragma("unroll") \
        for (int nh = 0; nh < 4; nh++) { \
            int n = wn * 64 + nh * 16 + rB; \
            u32 rowbB = _obm + (u32)n * 128; \
            u32 bhf[4]; \
            ldmx4(bhf, sb + rowbB + (u32)((((2 * ks + cBx)) ^ (n & 7)) << 4)); \
            mma_f16(acc[0][nh * 2],     ah[0], bhf[0], bhf[1]); \
            mma_f16(acc[1][nh * 2],     ah[1], bhf[0], bhf[1]); \
            mma_f16(acc[0][nh * 2 + 1], ah[0], bhf[2], bhf[3]); \
            mma_f16(acc[1][nh * 2 + 1], ah[1], bhf[2], bhf[3]); \
            mma_f16(acc[0][nh * 2],     al[0], bhf[0], bhf[1]); \
            mma_f16(acc[1][nh * 2],     al[1], bhf[0], bhf[1]); \
            mma_f16(acc[0][nh * 2 + 1], al[0], bhf[2], bhf[3]); \
            mma_f16(acc[1][nh * 2 + 1], al[1], bhf[2], bhf[3]); \
        } \
    } \
} while (0)

    LD_A(0);
    LD_B(0, 16384u);
    ST_A(0, 0u);
    CP_WAIT0();
    __syncthreads();

#pragma unroll
    for (int c = 0; c < 8; c++) {
        if (c < 7) { LD_A(c + 1); LD_B(c + 1, (u32)(((c + 1) & 1) * 32768 + 16384)); }
        MMA_CHUNK(c & 1);
        if (c < 7) {
            ST_A(c + 1, (u32)(((c + 1) & 1) * 32768));
            CP_WAIT0();
            __syncthreads();
        }
    }

    // ---- epilogue ----
    const int qrow = lane >> 2, qcol = (lane & 3) * 2;
    if (task == 0) {
#pragma unroll
        for (int mm = 0; mm < 2; mm++) {
            size_t r_lo = (size_t)(m0 + wm * 32 + mm * 16 + qrow);
            size_t r_hi = r_lo + 8;
            float ssl = 0.f, ssh = 0.f;
#pragma unroll
            for (int nf = 0; nf < 8; nf++) {
                int cof = n0 + wn * 64 + nf * 8 + qcol;
                *(float2*)(g_y + r_lo * C_ + cof) = make_float2(acc[mm][nf][0], acc[mm][nf][1]);
                *(float2*)(g_y + r_hi * C_ + cof) = make_float2(acc[mm][nf][2], acc[mm][nf][3]);
                ssl += acc[mm][nf][0] * acc[mm][nf][0] + acc[mm][nf][1] * acc[mm][nf][1];
                ssh += acc[mm][nf][2] * acc[mm][nf][2] + acc[mm][nf][3] * acc[mm][nf][3];
            }
            ssl += __shfl_xor_sync(0xffffffffu, ssl, 1);
            ssl += __shfl_xor_sync(0xffffffffu, ssl, 2);
            ssh += __shfl_xor_sync(0xffffffffu, ssh, 1);
            ssh += __shfl_xor_sync(0xffffffffu, ssh, 2);
            if ((lane & 3) == 0) {
                sm_ss[wm * 32 + mm * 16 + qrow][wn]     = ssl;
                sm_ss[wm * 32 + mm * 16 + qrow + 8][wn] = ssh;
            }
        }
        __syncthreads();
        if (tid < 128)
            g_ssp[(size_t)(m0 + tid) * 2 + (n0 >> 7)] = sm_ss[tid][0] + sm_ss[tid][1];
    } else {
#pragma unroll
        for (int mm = 0; mm < 2; mm++) {
            size_t r_lo = (size_t)(m0 + wm * 32 + mm * 16 + qrow);
            size_t r_hi = r_lo + 8;
            float irm_lo = g_invrms[r_lo];
            float irm_hi = g_invrms[r_hi];
#pragma unroll
            for (int nf = 0; nf < 8; nf++) {
                int cof = n0 + wn * 64 + nf * 8 + qcol;
                *(float2*)(fout + r_lo * C_ + cof) =
                    make_float2(acc[mm][nf][0] * irm_lo, acc[mm][nf][1] * irm_lo);
                *(float2*)(fout + r_hi * C_ + cof) =
                    make_float2(acc[mm][nf][2] * irm_hi, acc[mm][nf][3] * irm_hi);
            }
        }
    }
#undef LD_A
#undef LD_B
#undef ST_A
#undef MMA_CHUNK
}

// ---------------- K4: k GEMM, single-pass bf16 (k only feeds means) ----------------
__global__ void __launch_bounds__(256, 2)
gemm_k_kernel(const float* __restrict__ Xfp)
{
    extern __shared__ char smem[];
    const u32 sb = smem_u32(smem);
    const int tid = threadIdx.x, wid = tid >> 5, lane = tid & 31;
    const int m0 = blockIdx.y * 128;
    const int n0 = (int)blockIdx.x * 128;
    const u16* Bp = g_wk;

    const int wm = wid & 3, wn = wid >> 2;
    const int rA = (lane & 7) + ((lane >> 3) & 1) * 8, cAx = (lane >> 4) & 1;
    const int rB = (lane & 7) + ((lane >> 4) & 1) * 8, cBx = (lane >> 3) & 1;

    float acc[2][8][4];
#pragma unroll
    for (int i = 0; i < 2; i++)
#pragma unroll
        for (int j = 0; j < 8; j++)
#pragma unroll
            for (int t = 0; t < 4; t++) acc[i][j][t] = 0.f;

    const int lr = tid >> 1, q = tid & 1;
    const size_t arow = (size_t)(m0 + lr) * C_ + q * 16;
    const size_t brow = (size_t)(n0 + lr) * C_;
    float fr[16];

#define LD_A(c) do { \
    const float4* _p = (const float4*)(Xfp + arow + (c) * 32); \
    *(float4*)(fr)      = _p[0]; *(float4*)(fr + 4)  = _p[1]; \
    *(float4*)(fr + 8)  = _p[2]; *(float4*)(fr + 12) = _p[3]; \
} while (0)

#define LD_B(c, ob) do { \
    _Pragma("unroll") \
    for (int _i = 0; _i < 2; _i++) { \
        int _cg = q * 2 + _i; \
        u32 _row = (ob) + (u32)lr * 128; \
        CP_ASYNC16(sb + _row + (u32)((_cg ^ (lr & 7)) << 4), \
                   (const void*)(Bp + brow + (c) * 32 + _cg * 8)); \
    } \
    CP_COMMIT(); \
} while (0)

#define ST_A(c, oa) do { \
    u32 _hv[8]; \
    _Pragma("unroll") \
    for (int _t = 0; _t < 8; _t++) _hv[_t] = bf16pair(fr[2 * _t], fr[2 * _t + 1]); \
    u32 _base = (oa) + (u32)lr * 128; \
    int _c0 = q * 2, _c1 = q * 2 + 1; \
    *(uint4*)(smem + _base + ((_c0 ^ (lr & 7)) << 4)) = make_uint4(_hv[0], _hv[1], _hv[2], _hv[3]); \
    *(uint4*)(smem + _base + ((_c1 ^ (lr & 7)) << 4)) = make_uint4(_hv[4], _hv[5], _hv[6], _hv[7]); \
} while (0)

#define MMA_CHUNK(s) do { \
    u32 _oa = (u32)(s) * 32768, _obm = _oa + 16384; \
    _Pragma("unroll") \
    for (int ks = 0; ks < 2; ks++) { \
        u32 ah[2][4]; \
        _Pragma("unroll") \
        for (int ms = 0; ms < 2; ms++) { \
            int r = wm * 32 + ms * 16 + rA; \
            u32 rowb = _oa + (u32)r * 128; \
            ldmx4(ah[ms], sb + rowb + (u32)((((2 * ks + cAx)) ^ (r & 7)) << 4)); \
        } \
        _Pragma("unroll") \
        for (int nh = 0; nh < 4; nh++) { \
            int n = wn * 64 + nh * 16 + rB; \
            u32 rowbB = _obm + (u32)n * 128; \
            u32 bhf[4]; \
            ldmx4(bhf, sb + rowbB + (u32)((((2 * ks + cBx)) ^ (n & 7)) << 4)); \
            mma_bf16(acc[0][nh * 2],     ah[0], bhf[0], bhf[1]); \
            mma_bf16(acc[1][nh * 2],     ah[1], bhf[0], bhf[1]); \
            mma_bf16(acc[0][nh * 2 + 1], ah[0], bhf[2], bhf[3]); \
            mma_bf16(acc[1][nh * 2 + 1], ah[1], bhf[2], bhf[3]); \
        } \
    } \
} while (0)

    LD_A(0);
    LD_B(0, 16384u);
    ST_A(0, 0u);
    CP_WAIT0();
    __syncthreads();

#pragma unroll
    for (int c = 0; c < 8; c++) {
        if (c < 7) { LD_A(c + 1); LD_B(c + 1, (u32)(((c + 1) & 1) * 32768 + 16384)); }
        MMA_CHUNK(c & 1);
        if (c < 7) {
            ST_A(c + 1, (u32)(((c + 1) & 1) * 32768));
            CP_WAIT0();
            __syncthreads();
        }
    }

    // ---- epilogue: elu+1, per-head L2 norm, reduce mk & beta-weighted mbk ----
    const int qrow = lane >> 2, qcol = (lane & 3) * 2;
    const int head = (n0 >> 6) + wn;
    const int bhh = (m0 >> 12) * H_ + head;
    float mk0[8], mk1[8], mbk0[8], mbk1[8];
#pragma unroll
    for (int nf = 0; nf < 8; nf++) { mk0[nf] = mk1[nf] = mbk0[nf] = mbk1[nf] = 0.f; }

#pragma unroll
    for (int mm = 0; mm < 2; mm++) {
        float ssl = 0.f, ssh = 0.f;
#pragma unroll
        for (int nf = 0; nf < 8; nf++) {
            float e0 = eluf(acc[mm][nf][0]); acc[mm][nf][0] = e0; ssl += e0 * e0;
            float e1 = eluf(acc[mm][nf][1]); acc[mm][nf][1] = e1; ssl += e1 * e1;
            float e2 = eluf(acc[mm][nf][2]); acc[mm][nf][2] = e2; ssh += e2 * e2;
            float e3 = eluf(acc[mm][nf][3]); acc[mm][nf][3] = e3; ssh += e3 * e3;
        }
        ssl += __shfl_xor_sync(0xffffffffu, ssl, 1);
        ssl += __shfl_xor_sync(0xffffffffu, ssl, 2);
        ssh += __shfl_xor_sync(0xffffffffu, ssh, 1);
        ssh += __shfl_xor_sync(0xffffffffu, ssh, 2);
        float invl = 1.f / (sqrtf(ssl) + 1e-6f);
        float invh = 1.f / (sqrtf(ssh) + 1e-6f);
        int nrow = (m0 & (N_ - 1)) + wm * 32 + mm * 16 + qrow;
        float b_lo = g_beta[bhh * N_ + nrow];
        float b_hi = g_beta[bhh * N_ + nrow + 8];
#pragma unroll
        for (int nf = 0; nf < 8; nf++) {
            float v0 = acc[mm][nf][0] * invl, v1 = acc[mm][nf][1] * invl;
            float v2 = acc[mm][nf][2] * invh, v3 = acc[mm][nf][3] * invh;
            mk0[nf]  += v0 + v2;
            mk1[nf]  += v1 + v3;
            mbk0[nf] += b_lo * v0 + b_hi * v2;
            mbk1[nf] += b_lo * v1 + b_hi * v3;
        }
    }
#pragma unroll
    for (int o = 4; o <= 16; o <<= 1) {
#pragma unroll
        for (int nf = 0; nf < 8; nf++) {
            mk0[nf]  += __shfl_xor_sync(0xffffffffu, mk0[nf], o);
            mk1[nf]  += __shfl_xor_sync(0xffffffffu, mk1[nf], o);
            mbk0[nf] += __shfl_xor_sync(0xffffffffu, mbk0[nf], o);
            mbk1[nf] += __shfl_xor_sync(0xffffffffu, mbk1[nf], o);
        }
    }
    __syncthreads();
    float* red = (float*)smem;   // reuse staging smem: [0,512) mk, [512,1024) mbk
    if (lane < 4) {
#pragma unroll
        for (int nf = 0; nf < 8; nf++) {
            red[wid * 64 + nf * 8 + lane * 2]           = mk0[nf];
            red[wid * 64 + nf * 8 + lane * 2 + 1]       = mk1[nf];
            red[512 + wid * 64 + nf * 8 + lane * 2]     = mbk0[nf];
            red[512 + wid * 64 + nf * 8 + lane * 2 + 1] = mbk1[nf];
        }
    }
    __syncthreads();
    if (tid < 128) {
        int hh = tid >> 6, col = tid & 63;
        float s = red[(hh * 4 + 0) * 64 + col] + red[(hh * 4 + 1) * 64 + col]
                + red[(hh * 4 + 2) * 64 + col] + red[(hh * 4 + 3) * 64 + col];
        g_mkp[(size_t)blockIdx.y * 256 + n0 + hh * 64 + col] = s;
    } else {
        int t2 = tid - 128, hh = t2 >> 6, col = t2 & 63;
        float s = red[512 + (hh * 4 + 0) * 64 + col] + red[512 + (hh * 4 + 1) * 64 + col]
                + red[512 + (hh * 4 + 2) * 64 + col] + red[512 + (hh * 4 + 3) * 64 + col];
        g_mbkp[(size_t)blockIdx.y * 256 + n0 + hh * 64 + col] = s;
    }
#undef LD_A
#undef LD_B
#undef ST_A
#undef MMA_CHUNK
}

// ---------------- K3: xbar partials = sum_n beta*x over 64-row chunks ----------------
__global__ void __launch_bounds__(256)
xbar_kernel(const float* __restrict__ x)
{
    __shared__ float sbeta[64][4];
    int blk = blockIdx.x, m0 = blk * 64, tid = threadIdx.x;
    {
        int r = tid >> 2, h = tid & 3;
        int m = m0 + r, b = m >> 12, n = m & (N_ - 1);
        sbeta[r][h] = g_beta[(b * H_ + h) * N_ + n];
    }
    __syncthreads();
    float a0 = 0.f, a1 = 0.f, a2 = 0.f, a3 = 0.f;
    for (int r = 0; r < 64; r++) {
        float xv = x[(size_t)(m0 + r) * C_ + tid];
        a0 += xv * sbeta[r][0];
        a1 += xv * sbeta[r][1];
        a2 += xv * sbeta[r][2];
        a3 += xv * sbeta[r][3];
    }
    g_xbp[((size_t)blk * 4 + 0) * 256 + tid] = a0;
    g_xbp[((size_t)blk * 4 + 1) * 256 + tid] = a1;
    g_xbp[((size_t)blk * 4 + 2) * 256 + tid] = a2;
    g_xbp[((size_t)blk * 4 + 3) * 256 + tid] = a3;
}

// ---------------- K5a: invrms (per M-half) ----------------
__global__ void __launch_bounds__(256)
invrms_kernel(int mbase)
{
    int m = mbase + blockIdx.x * 256 + threadIdx.x;
    float s = g_ssp[(size_t)m * 2] + g_ssp[(size_t)m * 2 + 1];
    g_invrms[m] = rsqrtf(s * (1.f / (float)C_) + 1e-6f);
}

// ---------------- K5b: finalize werr/wkey ----------------
__global__ void __launch_bounds__(256)
final_kernel(const float* __restrict__ S, const float* __restrict__ Wv)
{
    __shared__ float s_mk[64], s_mbk[64], s_xbar[256];
    int bh = blockIdx.x, b = bh >> 2, h = bh & 3, tid = threadIdx.x;
    {
        float a = 0.f;
        for (int t = 0; t < 64; t++)
            a += g_xbp[((size_t)(b * 64 + t) * 4 + h) * 256 + tid];
        s_xbar[tid] = a * (1.f / (float)N_);
    }
    if (tid < 64) {
        float s = 0.f;
        for (int t = 0; t < 32; t++)
            s += g_mkp[(size_t)(b * 32 + t) * 256 + h * 64 + tid];
        s_mk[tid] = s * (1.f / (float)N_);
    } else if (tid < 128) {
        int c = tid - 64;
        float s = 0.f;
        for (int t = 0; t < 32; t++)
            s += g_mbkp[(size_t)(b * 32 + t) * 256 + h * 64 + c];
        s_mbk[c] = s * (1.f / (float)N_);
    }
    __syncthreads();
    if (tid < 64) {
        int i = tid;
        const float* wv = Wv + (size_t)(h * 64 + i) * 256;
        float mbv = 0.f;
        for (int c = 0; c < 256; c++) mbv += wv[c] * s_xbar[c];
        const float* sd = S + (size_t)bh * 4096 + (size_t)i * 64;
        float sp = 0.f;
        for (int j = 0; j < 64; j++) sp += 0.95f * sd[j] * s_mbk[j];
        g_werr[bh * 64 + i] = mbv - sp;
        g_wkey[bh * 64 + i] = s_mk[i];
    }
}

// ---------------- K5c: S_new ----------------
__global__ void __launch_bounds__(256)
snew_kernel(const float* __restrict__ S, float* __restrict__ out_s)
{
    int idx = blockIdx.x * 256 + threadIdx.x;
    int bh = idx >> 12;
    int i = (idx >> 6) & 63;
    int j = idx & 63;
    float val = S[idx] * 0.95f + g_werr[bh * 64 + i] * g_wkey[bh * 64 + j];
    out_s[idx] = fminf(fmaxf(val, -10.f), 10.f);
}

// ---------------- launcher ----------------
extern "C" void kernel_launch(void* const* d_in, const int* in_sizes, int n_in,
                              void* d_out, int out_size)
{
    const float* x    = (const float*)d_in[0];
    const float* S    = (const float*)d_in[1];
    const float* Wq   = (const float*)d_in[2];
    const float* Wk   = (const float*)d_in[3];
    const float* Wv   = (const float*)d_in[4];
    const float* Wb   = (const float*)d_in[5];
    const float* Wo   = (const float*)d_in[6];
    const float* grms = (const float*)d_in[7];
    float* out = (float*)d_out;

    static int init = 0;
    static cudaStream_t s2, s3;
    static cudaEvent_t eW, eB, e0, eQ0;
    if (!init) {
        cudaFuncSetAttribute(gemm_proj_kernel, cudaFuncAttributeMaxDynamicSharedMemorySize, 65536);
        cudaFuncSetAttribute(gemm_k_kernel, cudaFuncAttributeMaxDynamicSharedMemorySize, 65536);
        cudaFuncSetAttribute(wprime_kernel, cudaFuncAttributeMaxDynamicSharedMemorySize, 81920);
        cudaStreamCreateWithFlags(&s2, cudaStreamNonBlocking);
        cudaStreamCreateWithFlags(&s3, cudaStreamNonBlocking);
        cudaEventCreateWithFlags(&eW, cudaEventDisableTiming);
        cudaEventCreateWithFlags(&eB, cudaEventDisableTiming);
        cudaEventCreateWithFlags(&e0, cudaEventDisableTiming);
        cudaEventCreateWithFlags(&eQ0, cudaEventDisableTiming);
        init = 1;
    }

    const int HALF = M_ / 2;   // 32768

    // main: weight conversion (Wk bf16, Wog fp16)
    convw_kernel<<<512, 256>>>(Wk, Wo, grms);
    cudaEventRecord(eW, 0);

    // s2: beta (independent) -> k GEMM -> delta-rule tail
    beta_kernel<<<8192, 256, 0, s2>>>(x, Wb);

    // main: W' = Sd@Wq (fp16 rn)
    wprime_kernel<<<64, 256, 81920>>>(S, Wq);

    cudaStreamWaitEvent(s2, eW, 0);
    gemm_k_kernel<<<dim3(2, 512), 256, 65536, s2>>>(x);

    // main: proj0 half 0, then half 1
    gemm_proj_kernel<<<dim3(2, 256), 256, 65536>>>(0, 0, x, nullptr);
    cudaEventRecord(e0, 0);
    gemm_proj_kernel<<<dim3(2, 256), 256, 65536>>>(0, HALF, x, nullptr);

    // s2 tail (hidden under main GEMMs)
    xbar_kernel<<<1024, 256, 0, s2>>>(x);
    final_kernel<<<64, 256, 0, s2>>>(S, Wv);
    if (out_size >= OUT_MAIN + OUT_S) {
        snew_kernel<<<OUT_S / 256, 256, 0, s2>>>(S, out + OUT_MAIN);
    }
    cudaEventRecord(eB, s2);

    // s3: proj1 half 0 (runs concurrent with proj0 half 1)
    cudaStreamWaitEvent(s3, e0, 0);
    invrms_kernel<<<HALF / 256, 256, 0, s3>>>(0);
    gemm_proj_kernel<<<dim3(2, 256), 256, 65536, s3>>>(1, 0, x, out);
    cudaEventRecord(eQ0, s3);

    // main: proj1 half 1
    invrms_kernel<<<HALF / 256, 256>>>(HALF);
    gemm_proj_kernel<<<dim3(2, 256), 256, 65536>>>(1, HALF, x, out);

    // join
    cudaStreamWaitEvent(0, eQ0, 0);
    cudaStreamWaitEvent(0, eB, 0);
}